// round 6
// baseline (speedup 1.0000x reference)
#include <cuda_runtime.h>
#include <cuda_bf16.h>

typedef unsigned long long ull;

#define NNODES 50000
#define NEDGES 1600000
#define NGRAPH 4
#define HID    64
#define NLAYERS 5
#define NTILES (NEDGES / 128)   // 12500

// ---------------- device scratch ----------------
__device__ float g_h[NNODES * HID];
__device__ float g_agg[NNODES * HID];
__device__ float g_pooled[NGRAPH * HID];
__device__ int   g_cnt[NGRAPH];
// per-layer prepped bf16 hi/lo weights [n][k] stride-144: B1(4x9216) + B2(2x9216) = 55296 B
__device__ __align__(16) unsigned char g_wB[NLAYERS * 55296];

// ---------------- SMEM layout (bytes) ----------------
#define OFF_A    0u        // A hi 128x72 bf16 (18432) + A lo (18432)
#define OFF_B1   36864u    // c0H, c0L, c1H, c1L each 9216
#define OFF_B2H  73728u
#define OFF_B2L  82944u
#define OFF_T    92160u    // W1 tail rows 128..132 fp32 [5][64] (1280)
#define OFF_BB1  93440u
#define OFF_BB2  93696u
#define OFF_G    93952u
#define OFF_BE   94208u
#define OFF_SDST 94464u    // 2 x 128 ints (1024)
#define OFF_SEA  95488u    // 2 x 640 fp32 (5120)
#define EDGE_SMEM 100608

// ---------------- generic helpers ----------------
__device__ __forceinline__ float silu_f(float x) {
    float t;
    asm("tanh.approx.f32 %0, %1;" : "=f"(t) : "f"(x * 0.5f));
    return x * 0.5f * t + x * 0.5f;
}
__device__ __forceinline__ ull fma2(ull a, ull b, ull c) {
    ull d;
    asm("fma.rn.f32x2 %0, %1, %2, %3;" : "=l"(d) : "l"(a), "l"(b), "l"(c));
    return d;
}
__device__ __forceinline__ ull pack2(float lo, float hi) {
    ull r;
    asm("mov.b64 %0, {%1, %2};" : "=l"(r) : "f"(lo), "f"(hi));
    return r;
}
__device__ __forceinline__ ull dup2(float x) {
    ull r;
    asm("mov.b64 %0, {%1, %1};" : "=l"(r) : "f"(x));
    return r;
}
__device__ __forceinline__ void unpack2(ull v, float& lo, float& hi) {
    asm("mov.b64 {%0, %1}, %2;" : "=f"(lo), "=f"(hi) : "l"(v));
}
__device__ __forceinline__ void red_add4(float* p, float a, float b, float c, float d) {
    asm volatile("red.global.add.v4.f32 [%0], {%1, %2, %3, %4};"
                 :: "l"(p), "f"(a), "f"(b), "f"(c), "f"(d) : "memory");
}
__device__ __forceinline__ unsigned smem_u32(const void* p) {
    unsigned a;
    asm("{ .reg .u64 t; cvta.to.shared.u64 t, %1; cvt.u32.u64 %0, t; }" : "=r"(a) : "l"(p));
    return a;
}

// ---------------- mma.sync helpers ----------------
__device__ __forceinline__ void ldsm4(unsigned* r, unsigned addr) {
    asm volatile("ldmatrix.sync.aligned.m8n8.x4.shared.b16 {%0,%1,%2,%3}, [%4];"
                 : "=r"(r[0]), "=r"(r[1]), "=r"(r[2]), "=r"(r[3]) : "r"(addr));
}
__device__ __forceinline__ void mma16816(float* c, const unsigned* a, unsigned b0, unsigned b1) {
    asm volatile("mma.sync.aligned.m16n8k16.row.col.f32.bf16.bf16.f32 "
                 "{%0,%1,%2,%3}, {%4,%5,%6,%7}, {%8,%9}, {%0,%1,%2,%3};"
                 : "+f"(c[0]), "+f"(c[1]), "+f"(c[2]), "+f"(c[3])
                 : "r"(a[0]), "r"(a[1]), "r"(a[2]), "r"(a[3]), "r"(b0), "r"(b1));
}

// fused GEMM1 chunk: (AH + AL) x BH, then AH x BL  (B frags shared, no reg cache)
__device__ __forceinline__ void mma_chunk(float (&acc)[2][8][4],
        unsigned AHb, unsigned ALb, unsigned bH, unsigned bL)
{
#pragma unroll
    for (int kt = 0; kt < 4; ++kt) {
        unsigned ah0[4], ah1[4], al0[4], al1[4];
        ldsm4(ah0, AHb + kt * 32u);
        ldsm4(ah1, AHb + 2304u + kt * 32u);
        ldsm4(al0, ALb + kt * 32u);
        ldsm4(al1, ALb + 2304u + kt * 32u);
#pragma unroll
        for (int q = 0; q < 4; ++q) {
            unsigned b[4];
            ldsm4(b, bH + q * 2304u + kt * 32u);
            mma16816(acc[0][2 * q],     ah0, b[0], b[1]);
            mma16816(acc[0][2 * q + 1], ah0, b[2], b[3]);
            mma16816(acc[1][2 * q],     ah1, b[0], b[1]);
            mma16816(acc[1][2 * q + 1], ah1, b[2], b[3]);
            mma16816(acc[0][2 * q],     al0, b[0], b[1]);
            mma16816(acc[0][2 * q + 1], al0, b[2], b[3]);
            mma16816(acc[1][2 * q],     al1, b[0], b[1]);
            mma16816(acc[1][2 * q + 1], al1, b[2], b[3]);
        }
    }
#pragma unroll
    for (int kt = 0; kt < 4; ++kt) {
        unsigned ah0[4], ah1[4];
        ldsm4(ah0, AHb + kt * 32u);
        ldsm4(ah1, AHb + 2304u + kt * 32u);
#pragma unroll
        for (int q = 0; q < 4; ++q) {
            unsigned b[4];
            ldsm4(b, bL + q * 2304u + kt * 32u);
            mma16816(acc[0][2 * q],     ah0, b[0], b[1]);
            mma16816(acc[0][2 * q + 1], ah0, b[2], b[3]);
            mma16816(acc[1][2 * q],     ah1, b[0], b[1]);
            mma16816(acc[1][2 * q + 1], ah1, b[2], b[3]);
        }
    }
}

// ---------------- zero kernels ----------------
__global__ void zero_agg_kernel() {
    int i = blockIdx.x * blockDim.x + threadIdx.x;
    for (; i < NNODES * HID; i += gridDim.x * blockDim.x) g_agg[i] = 0.f;
}
__global__ void zero_pool_kernel() {
    int t = threadIdx.x;
    if (t < NGRAPH * HID) g_pooled[t] = 0.f;
    if (t < NGRAPH) g_cnt[t] = 0;
}

// ---------------- weight prep ----------------
__global__ void prep_weights(const float* __restrict__ eW1, const float* __restrict__ eW2) {
    int idx = blockIdx.x * blockDim.x + threadIdx.x;
    if (idx >= NLAYERS * 12288) return;
    int l = idx / 12288, r = idx % 12288;
    unsigned char* base = g_wB + l * 55296;
    float w;
    unsigned offH;
    if (r < 8192) {
        int c = r >> 12, rr = r & 4095, n = rr >> 6, kk = rr & 63;
        w = eW1[l * 133 * 64 + (c * 64 + kk) * 64 + n];
        offH = (unsigned)(c * 18432 + n * 144 + kk * 2);
    } else {
        int rr = r - 8192, n = rr >> 6, kk = rr & 63;
        w = eW2[l * 4096 + kk * 64 + n];
        offH = (unsigned)(36864 + n * 144 + kk * 2);
    }
    __nv_bfloat16 hi = __float2bfloat16(w);
    __nv_bfloat16 lo = __float2bfloat16(w - __bfloat162float(hi));
    *(__nv_bfloat16*)(base + offH) = hi;
    *(__nv_bfloat16*)(base + offH + 9216) = lo;
}

// ---------------- encoder ----------------
__global__ void __launch_bounds__(128) encoder_kernel(
    const float* __restrict__ x, const int* __restrict__ batch,
    const float* __restrict__ caseP, const float* __restrict__ bcP,
    const float* __restrict__ W1, const float* __restrict__ b1,
    const float* __restrict__ W2, const float* __restrict__ b2,
    const float* __restrict__ gam, const float* __restrict__ bet)
{
    __shared__ float sW1[16 * 64];
    __shared__ float sW2[64 * 64];
    __shared__ float sb1[64], sb2[64], sg[64], sbe[64];
    __shared__ float sy[4][64];
    int tid = threadIdx.x;
    for (int i = tid; i < 16 * 64; i += 128) sW1[i] = W1[i];
    for (int i = tid; i < 64 * 64; i += 128) sW2[i] = W2[i];
    if (tid < 64) { sb1[tid] = b1[tid]; sb2[tid] = b2[tid]; sg[tid] = gam[tid]; sbe[tid] = bet[tid]; }
    __syncthreads();

    int lane = tid & 31, warp = tid >> 5;
    int j0 = lane, j1 = lane + 32;
    for (int n = blockIdx.x * 4 + warp; n < NNODES; n += gridDim.x * 4) {
        float in[16];
        const float* xr = x + n * 8;
#pragma unroll
        for (int k = 0; k < 8; ++k) in[k] = xr[k];
        int b = batch[n];
#pragma unroll
        for (int k = 0; k < 4; ++k) in[8 + k]  = caseP[b * 4 + k];
#pragma unroll
        for (int k = 0; k < 4; ++k) in[12 + k] = bcP[b * 4 + k];

        float a0 = sb1[j0], a1 = sb1[j1];
#pragma unroll
        for (int k = 0; k < 16; ++k) {
            a0 = fmaf(in[k], sW1[k * 64 + j0], a0);
            a1 = fmaf(in[k], sW1[k * 64 + j1], a1);
        }
        a0 = silu_f(a0); a1 = silu_f(a1);
        sy[warp][j0] = a0; sy[warp][j1] = a1;
        __syncwarp();
        float z0 = sb2[j0], z1 = sb2[j1];
#pragma unroll 4
        for (int k = 0; k < 64; ++k) {
            float v = sy[warp][k];
            z0 = fmaf(v, sW2[k * 64 + j0], z0);
            z1 = fmaf(v, sW2[k * 64 + j1], z1);
        }
        float s = z0 + z1, ss = z0 * z0 + z1 * z1;
#pragma unroll
        for (int o = 16; o > 0; o >>= 1) {
            s  += __shfl_xor_sync(0xffffffffu, s, o);
            ss += __shfl_xor_sync(0xffffffffu, ss, o);
        }
        float m = s * (1.f / 64.f);
        float rs = rsqrtf(ss * (1.f / 64.f) - m * m + 1e-5f);
        g_h[n * HID + j0] = (z0 - m) * rs * sg[j0] + sbe[j0];
        g_h[n * HID + j1] = (z1 - m) * rs * sg[j1] + sbe[j1];
        __syncwarp();
    }
}

// ---------------- edge MLP v6: pipelined gathers ----------------
__global__ void __launch_bounds__(128, 2) edge6_kernel(
    const int* __restrict__ ei, const float* __restrict__ ea, int layer,
    const float* __restrict__ W1full, const float* __restrict__ b1,
    const float* __restrict__ b2,
    const float* __restrict__ gam, const float* __restrict__ bet)
{
    extern __shared__ unsigned char sm[];
    const unsigned sbase = smem_u32(sm);
    const int tid = threadIdx.x;
    const int lane = tid & 31, warp = tid >> 5;
    const int gID = lane >> 2, tig = lane & 3;
    const int lt = lane >> 3, lr = lane & 7;

    // --- one-time loads ---
    {
        const uint4* srcw = (const uint4*)(g_wB + layer * 55296);
        uint4* dstw = (uint4*)(sm + OFF_B1);
#pragma unroll 4
        for (int i = tid; i < 3456; i += 128) dstw[i] = srcw[i];
    }
    for (int i = tid; i < 320; i += 128) ((float*)(sm + OFF_T))[i] = W1full[128 * 64 + i];
    if (tid < 64) {
        ((float*)(sm + OFF_BB1))[tid] = b1[tid];
        ((float*)(sm + OFF_BB2))[tid] = b2[tid];
        ((float*)(sm + OFF_G))[tid]   = gam[tid];
        ((float*)(sm + OFF_BE))[tid]  = bet[tid];
    }

    const unsigned aLane = (unsigned)((lr + ((lt & 1) << 3)) * 144 + ((lt >> 1) << 4));
    const unsigned bLane = (unsigned)(((lt >> 1) * 8 + lr) * 144 + ((lt & 1) << 4));
    const unsigned AHb = sbase + OFF_A + (unsigned)(warp * 32 * 144) + aLane;
    const unsigned ALb = AHb + 18432u;
    const float* bb1 = (const float*)(sm + OFF_BB1);

    // --- prologue: prefetch first tile ---
    float4 R[16];
    int idx1;
    {
        const int e0p = blockIdx.x * 128;
        int idx0 = ei[NEDGES + e0p + tid];
        ((int*)(sm + OFF_SDST))[tid] = idx0;
        float* s0 = (float*)(sm + OFF_SEA);
        for (int i = tid; i < 640; i += 128) s0[i] = ea[(ull)e0p * 5 + i];
        idx1 = ei[e0p + tid];
        const float4* hp = (const float4*)(g_h + (ull)idx0 * 64);
#pragma unroll
        for (int i = 0; i < 16; ++i) R[i] = hp[i];
    }
    __syncthreads();

    int it = 0;
    for (int t = blockIdx.x; t < NTILES; t += gridDim.x, ++it) {
        const int pb = it & 1;
        const int* sdst = (const int*)(sm + OFF_SDST) + pb * 128;
        const float* sea = (const float*)(sm + OFF_SEA) + pb * 640;

        // -- step1: convert R (chunk0 rows) -> A hi/lo --
        {
            unsigned char* hrow = sm + OFF_A + tid * 144;
#pragma unroll
            for (int i = 0; i < 16; ++i) {
                float4 v = R[i];
                __nv_bfloat162 h01 = __float22bfloat162_rn(make_float2(v.x, v.y));
                __nv_bfloat162 h23 = __float22bfloat162_rn(make_float2(v.z, v.w));
                float2 f01 = __bfloat1622float2(h01);
                float2 f23 = __bfloat1622float2(h23);
                __nv_bfloat162 l01 = __float22bfloat162_rn(make_float2(v.x - f01.x, v.y - f01.y));
                __nv_bfloat162 l23 = __float22bfloat162_rn(make_float2(v.z - f23.x, v.w - f23.y));
                *(ull*)(hrow + i * 8)         = ((ull)*(unsigned*)&h23 << 32) | *(unsigned*)&h01;
                *(ull*)(hrow + 18432 + i * 8) = ((ull)*(unsigned*)&l23 << 32) | *(unsigned*)&l01;
            }
        }
        __syncthreads();

        // -- step3: issue chunk1 gather (consumed after MMA c0) + next-tile idx0 --
        {
            const float4* hp = (const float4*)(g_h + (ull)idx1 * 64);
#pragma unroll
            for (int i = 0; i < 16; ++i) R[i] = hp[i];
        }
        const int tn = t + gridDim.x;
        const int tcl = (tn < NTILES) ? tn : t;
        const int e0n = tcl * 128;
        int idx0n = ei[NEDGES + e0n + tid];

        // -- acc init + step4: MMA chunk0 --
        float acc[2][8][4];
#pragma unroll
        for (int nt = 0; nt < 8; ++nt) {
            float2 bv = *(const float2*)(bb1 + nt * 8 + 2 * tig);
#pragma unroll
            for (int mt = 0; mt < 2; ++mt) {
                acc[mt][nt][0] = bv.x; acc[mt][nt][1] = bv.y;
                acc[mt][nt][2] = bv.x; acc[mt][nt][3] = bv.y;
            }
        }
        mma_chunk(acc, AHb, ALb, sbase + OFF_B1 + bLane, sbase + OFF_B1 + 9216u + bLane);
        __syncthreads();

        // -- step6: convert R (chunk1 rows) -> A hi/lo --
        {
            unsigned char* hrow = sm + OFF_A + tid * 144;
#pragma unroll
            for (int i = 0; i < 16; ++i) {
                float4 v = R[i];
                __nv_bfloat162 h01 = __float22bfloat162_rn(make_float2(v.x, v.y));
                __nv_bfloat162 h23 = __float22bfloat162_rn(make_float2(v.z, v.w));
                float2 f01 = __bfloat1622float2(h01);
                float2 f23 = __bfloat1622float2(h23);
                __nv_bfloat162 l01 = __float22bfloat162_rn(make_float2(v.x - f01.x, v.y - f01.y));
                __nv_bfloat162 l23 = __float22bfloat162_rn(make_float2(v.z - f23.x, v.w - f23.y));
                *(ull*)(hrow + i * 8)         = ((ull)*(unsigned*)&h23 << 32) | *(unsigned*)&h01;
                *(ull*)(hrow + 18432 + i * 8) = ((ull)*(unsigned*)&l23 << 32) | *(unsigned*)&l01;
            }
        }

        // -- step7: prefetch next tile (hidden under MMA c1 + GEMM2) --
        {
            const float4* hp = (const float4*)(g_h + (ull)idx0n * 64);
#pragma unroll
            for (int i = 0; i < 16; ++i) R[i] = hp[i];
        }
        ((int*)(sm + OFF_SDST))[(pb ^ 1) * 128 + tid] = idx0n;
        {
            float* sn = (float*)(sm + OFF_SEA) + (pb ^ 1) * 640;
            for (int i = tid; i < 640; i += 128) sn[i] = ea[(ull)e0n * 5 + i];
        }
        idx1 = ei[e0n + tid];
        __syncthreads();

        // -- step9: MMA chunk1 --
        mma_chunk(acc, AHb, ALb, sbase + OFF_B1 + 18432u + bLane, sbase + OFF_B1 + 27648u + bLane);

        // ===== epilogue1 (registers): fp32 edge_attr tail + silu + split =====
        float eav[2][2][5];
#pragma unroll
        for (int mt = 0; mt < 2; ++mt)
#pragma unroll
            for (int h = 0; h < 2; ++h) {
                const float* er = sea + (warp * 32 + mt * 16 + h * 8 + gID) * 5;
#pragma unroll
                for (int j = 0; j < 5; ++j) eav[mt][h][j] = er[j];
            }
        unsigned uh[2][2][8], ulo[2][2][8];
#pragma unroll
        for (int nt = 0; nt < 8; ++nt) {
            float2 w[5];
#pragma unroll
            for (int j = 0; j < 5; ++j)
                w[j] = *(const float2*)(sm + OFF_T + (unsigned)((j * 64 + nt * 8 + tig * 2) * 4));
#pragma unroll
            for (int mt = 0; mt < 2; ++mt)
#pragma unroll
                for (int h = 0; h < 2; ++h) {
                    float y0 = acc[mt][nt][2 * h], y1 = acc[mt][nt][2 * h + 1];
#pragma unroll
                    for (int j = 0; j < 5; ++j) {
                        y0 = fmaf(eav[mt][h][j], w[j].x, y0);
                        y1 = fmaf(eav[mt][h][j], w[j].y, y1);
                    }
                    y0 = silu_f(y0); y1 = silu_f(y1);
                    __nv_bfloat162 hb = __float22bfloat162_rn(make_float2(y0, y1));
                    float2 f = __bfloat1622float2(hb);
                    __nv_bfloat162 lb = __float22bfloat162_rn(make_float2(y0 - f.x, y1 - f.y));
                    uh[mt][h][nt]  = *(unsigned*)&hb;
                    ulo[mt][h][nt] = *(unsigned*)&lb;
                }
        }

        // ===== GEMM2 fused: (Yh + Yl) x B2H, then Yh x B2L =====
        float acc2[2][8][4];
#pragma unroll
        for (int nt = 0; nt < 8; ++nt) {
            float2 bv = *(const float2*)(sm + OFF_BB2 + (unsigned)((nt * 8 + tig * 2) * 4));
#pragma unroll
            for (int mt = 0; mt < 2; ++mt) {
                acc2[mt][nt][0] = bv.x; acc2[mt][nt][1] = bv.y;
                acc2[mt][nt][2] = bv.x; acc2[mt][nt][3] = bv.y;
            }
        }
        const unsigned b2H = sbase + OFF_B2H + bLane;
        const unsigned b2L = sbase + OFF_B2L + bLane;
#pragma unroll
        for (int kt = 0; kt < 4; ++kt) {
            unsigned ah0[4] = {uh[0][0][2 * kt], uh[0][1][2 * kt], uh[0][0][2 * kt + 1], uh[0][1][2 * kt + 1]};
            unsigned ah1[4] = {uh[1][0][2 * kt], uh[1][1][2 * kt], uh[1][0][2 * kt + 1], uh[1][1][2 * kt + 1]};
            unsigned al0[4] = {ulo[0][0][2 * kt], ulo[0][1][2 * kt], ulo[0][0][2 * kt + 1], ulo[0][1][2 * kt + 1]};
            unsigned al1[4] = {ulo[1][0][2 * kt], ulo[1][1][2 * kt], ulo[1][0][2 * kt + 1], ulo[1][1][2 * kt + 1]};
#pragma unroll
            for (int q = 0; q < 4; ++q) {
                unsigned b[4];
                ldsm4(b, b2H + q * 2304u + kt * 32u);
                mma16816(acc2[0][2 * q],     ah0, b[0], b[1]);
                mma16816(acc2[0][2 * q + 1], ah0, b[2], b[3]);
                mma16816(acc2[1][2 * q],     ah1, b[0], b[1]);
                mma16816(acc2[1][2 * q + 1], ah1, b[2], b[3]);
                mma16816(acc2[0][2 * q],     al0, b[0], b[1]);
                mma16816(acc2[0][2 * q + 1], al0, b[2], b[3]);
                mma16816(acc2[1][2 * q],     al1, b[0], b[1]);
                mma16816(acc2[1][2 * q + 1], al1, b[2], b[3]);
            }
        }
#pragma unroll
        for (int kt = 0; kt < 4; ++kt) {
            unsigned ah0[4] = {uh[0][0][2 * kt], uh[0][1][2 * kt], uh[0][0][2 * kt + 1], uh[0][1][2 * kt + 1]};
            unsigned ah1[4] = {uh[1][0][2 * kt], uh[1][1][2 * kt], uh[1][0][2 * kt + 1], uh[1][1][2 * kt + 1]};
#pragma unroll
            for (int q = 0; q < 4; ++q) {
                unsigned b[4];
                ldsm4(b, b2L + q * 2304u + kt * 32u);
                mma16816(acc2[0][2 * q],     ah0, b[0], b[1]);
                mma16816(acc2[0][2 * q + 1], ah0, b[2], b[3]);
                mma16816(acc2[1][2 * q],     ah1, b[0], b[1]);
                mma16816(acc2[1][2 * q + 1], ah1, b[2], b[3]);
            }
        }

        // ===== epilogue2: LayerNorm (shuffles) + scatter (red.v4) =====
        float mArr[2][2], rsArr[2][2];
#pragma unroll
        for (int mt = 0; mt < 2; ++mt)
#pragma unroll
            for (int h = 0; h < 2; ++h) {
                float s = 0.f, ssum = 0.f;
#pragma unroll
                for (int nt = 0; nt < 8; ++nt) {
                    float v0 = acc2[mt][nt][2 * h], v1 = acc2[mt][nt][2 * h + 1];
                    s += v0 + v1; ssum += v0 * v0 + v1 * v1;
                }
                s    += __shfl_xor_sync(0xffffffffu, s, 1);
                ssum += __shfl_xor_sync(0xffffffffu, ssum, 1);
                s    += __shfl_xor_sync(0xffffffffu, s, 2);
                ssum += __shfl_xor_sync(0xffffffffu, ssum, 2);
                float m = s * (1.f / 64.f);
                mArr[mt][h]  = m;
                rsArr[mt][h] = rsqrtf(ssum * (1.f / 64.f) - m * m + 1e-5f);
            }
        const int cq = (tig & 1) * 2 + (tig >> 1);
        float4 gq[4], beq[4];
#pragma unroll
        for (int j = 0; j < 4; ++j) {
            gq[j]  = ((const float4*)(sm + OFF_G))[4 * j + cq];
            beq[j] = ((const float4*)(sm + OFF_BE))[4 * j + cq];
        }
        const unsigned colb = (unsigned)((tig & 1) * 8 + (tig >> 1) * 4);
#pragma unroll
        for (int mt = 0; mt < 2; ++mt)
#pragma unroll
            for (int h = 0; h < 2; ++h) {
                int row = warp * 32 + mt * 16 + h * 8 + gID;
                float* ag = g_agg + (ull)sdst[row] * 64 + colb;
                float m = mArr[mt][h], rs = rsArr[mt][h];
#pragma unroll
                for (int j = 0; j < 4; ++j) {
                    ull p0 = pack2(acc2[mt][2 * j][2 * h],     acc2[mt][2 * j][2 * h + 1]);
                    ull p1 = pack2(acc2[mt][2 * j + 1][2 * h], acc2[mt][2 * j + 1][2 * h + 1]);
                    ull sel = (tig & 1) ? p0 : p1;
                    ull rv = __shfl_xor_sync(0xffffffffu, sel, 1);
                    float q0, q1, q2, q3;
                    if (tig & 1) { unpack2(rv, q0, q1); unpack2(p1, q2, q3); }
                    else         { unpack2(p0, q0, q1); unpack2(rv, q2, q3); }
                    float o0 = (q0 - m) * rs * gq[j].x + beq[j].x;
                    float o1 = (q1 - m) * rs * gq[j].y + beq[j].y;
                    float o2 = (q2 - m) * rs * gq[j].z + beq[j].z;
                    float o3 = (q3 - m) * rs * gq[j].w + beq[j].w;
                    red_add4(ag + 16 * j, o0, o1, o2, o3);
                }
            }
        __syncthreads();
    }
}

// ---------------- node MLP (fp32 register-tiled) ----------------
#define FMA16(AA, AB, W0, W1, W2, W3, ACC)                               \
    do {                                                                 \
        ACC[0][0]=fma2(AA.x,W0,ACC[0][0]); ACC[0][1]=fma2(AA.x,W1,ACC[0][1]); \
        ACC[0][2]=fma2(AA.x,W2,ACC[0][2]); ACC[0][3]=fma2(AA.x,W3,ACC[0][3]); \
        ACC[1][0]=fma2(AA.y,W0,ACC[1][0]); ACC[1][1]=fma2(AA.y,W1,ACC[1][1]); \
        ACC[1][2]=fma2(AA.y,W2,ACC[1][2]); ACC[1][3]=fma2(AA.y,W3,ACC[1][3]); \
        ACC[2][0]=fma2(AB.x,W0,ACC[2][0]); ACC[2][1]=fma2(AB.x,W1,ACC[2][1]); \
        ACC[2][2]=fma2(AB.x,W2,ACC[2][2]); ACC[2][3]=fma2(AB.x,W3,ACC[2][3]); \
        ACC[3][0]=fma2(AB.y,W0,ACC[3][0]); ACC[3][1]=fma2(AB.y,W1,ACC[3][1]); \
        ACC[3][2]=fma2(AB.y,W2,ACC[3][2]); ACC[3][3]=fma2(AB.y,W3,ACC[3][3]); \
    } while (0)

__global__ void __launch_bounds__(256, 2) node2_kernel(
    const float* __restrict__ W1, const float* __restrict__ b1,
    const float* __restrict__ W2, const float* __restrict__ b2,
    const float* __restrict__ gam, const float* __restrict__ bet)
{
    extern __shared__ float smem[];
    float* sW1 = smem;
    float* sW2 = sW1 + 8192;
    float* sg  = sW2 + 4096;
    float* sbe = sg + 64;
    float* buf = sbe + 64;

    const int tid = threadIdx.x;
    for (int i = tid; i < 8192; i += 256) sW1[i] = W1[i];
    for (int i = tid; i < 4096; i += 256) sW2[i] = W2[i];
    if (tid < 64) { sg[tid] = gam[tid]; sbe[tid] = bet[tid]; }

    const int n0 = blockIdx.x * 128;
    const int tn = tid & 15, tm = tid >> 4;
    const int eg_ = tid & 127;
    const int kq  = (tid >> 7) * 4;

    ull acc[4][4];
    {
        float4 bv = *(const float4*)(b1 + tn * 4);
#pragma unroll
        for (int ep = 0; ep < 4; ++ep) {
            acc[ep][0] = dup2(bv.x); acc[ep][1] = dup2(bv.y);
            acc[ep][2] = dup2(bv.z); acc[ep][3] = dup2(bv.w);
        }
    }

    int ngi = n0 + eg_;
    if (ngi >= NNODES) ngi = 0;

#pragma unroll
    for (int ch = 0; ch < 2; ++ch) {
        const float* srcp = (ch == 0) ? g_h : g_agg;
        const float4* hp = (const float4*)(srcp + (ull)ngi * 64);
        __syncthreads();
#pragma unroll
        for (int r = 0; r < 8; ++r) {
            int k = r * 8 + kq;
            float4 v = hp[2 * r + (kq >> 2)];
            buf[(k + 0) * 128 + eg_] = v.x;
            buf[(k + 1) * 128 + eg_] = v.y;
            buf[(k + 2) * 128 + eg_] = v.z;
            buf[(k + 3) * 128 + eg_] = v.w;
        }
        __syncthreads();
        const float* wbase = sW1 + ch * 64 * 64;
#pragma unroll 2
        for (int k = 0; k < 64; ++k) {
            const ulonglong2* ar = (const ulonglong2*)(buf + k * 128 + tm * 8);
            ulonglong2 aA = ar[0], aB = ar[1];
            float4 wv = *(const float4*)(wbase + k * 64 + tn * 4);
            ull w0 = dup2(wv.x), w1 = dup2(wv.y), w2 = dup2(wv.z), w3 = dup2(wv.w);
            FMA16(aA, aB, w0, w1, w2, w3, acc);
        }
    }
    __syncthreads();

#pragma unroll
    for (int ep = 0; ep < 4; ++ep)
#pragma unroll
        for (int j = 0; j < 4; ++j) {
            float x0, x1;
            unpack2(acc[ep][j], x0, x1);
            *(ull*)(buf + (tn * 4 + j) * 132 + tm * 8 + 2 * ep) = pack2(silu_f(x0), silu_f(x1));
        }
    __syncthreads();

    ull acc2[4][4];
    {
        float4 bv = *(const float4*)(b2 + tn * 4);
#pragma unroll
        for (int ep = 0; ep < 4; ++ep) {
            acc2[ep][0] = dup2(bv.x); acc2[ep][1] = dup2(bv.y);
            acc2[ep][2] = dup2(bv.z); acc2[ep][3] = dup2(bv.w);
        }
    }
#pragma unroll 2
    for (int k = 0; k < 64; ++k) {
        const ulonglong2* ar = (const ulonglong2*)(buf + k * 132 + tm * 8);
        ulonglong2 aA = ar[0], aB = ar[1];
        float4 wv = *(const float4*)(sW2 + k * 64 + tn * 4);
        ull w0 = dup2(wv.x), w1 = dup2(wv.y), w2 = dup2(wv.z), w3 = dup2(wv.w);
        FMA16(aA, aB, w0, w1, w2, w3, acc2);
    }
    __syncthreads();

#pragma unroll
    for (int ep = 0; ep < 4; ++ep)
#pragma unroll
        for (int j = 0; j < 4; ++j) {
            float x0, x1;
            unpack2(acc2[ep][j], x0, x1);
            int e = tm * 8 + 2 * ep;
            buf[e * 66 + tn * 4 + j]       = x0;
            buf[(e + 1) * 66 + tn * 4 + j] = x1;
        }
    __syncthreads();

    if (tid < 128 && n0 + tid < NNODES) {
        const float* z = buf + tid * 66;
        float s = 0.f, ss = 0.f;
#pragma unroll 8
        for (int c = 0; c < 64; ++c) { float v = z[c]; s += v; ss += v * v; }
        float m  = s * (1.f / 64.f);
        float rs = rsqrtf(ss * (1.f / 64.f) - m * m + 1e-5f);
        float4* hp = (float4*)(g_h + (ull)(n0 + tid) * 64);
#pragma unroll
        for (int q = 0; q < 16; ++q) {
            float4 hv = hp[q];
            hv.x += (z[4 * q + 0] - m) * rs * sg[4 * q + 0] + sbe[4 * q + 0];
            hv.y += (z[4 * q + 1] - m) * rs * sg[4 * q + 1] + sbe[4 * q + 1];
            hv.z += (z[4 * q + 2] - m) * rs * sg[4 * q + 2] + sbe[4 * q + 2];
            hv.w += (z[4 * q + 3] - m) * rs * sg[4 * q + 3] + sbe[4 * q + 3];
            hp[q] = hv;
        }
    }
}

// ---------------- local decoder ----------------
__global__ void __launch_bounds__(128) dec_local_kernel(
    const float* __restrict__ W1, const float* __restrict__ b1,
    const float* __restrict__ W2, const float* __restrict__ b2,
    float* __restrict__ out)
{
    __shared__ float sW1[64 * 64];
    __shared__ float sW2[64 * 6];
    __shared__ float sb1[64];
    __shared__ float sb2[8];
    __shared__ float sy[4][64];
    int tid = threadIdx.x;
    for (int i = tid; i < 64 * 64; i += 128) sW1[i] = W1[i];
    for (int i = tid; i < 64 * 6; i += 128) sW2[i] = W2[i];
    if (tid < 64) sb1[tid] = b1[tid];
    if (tid < 6)  sb2[tid] = b2[tid];
    __syncthreads();

    int lane = tid & 31, warp = tid >> 5;
    int j0 = lane, j1 = lane + 32;
    for (int n = blockIdx.x * 4 + warp; n < NNODES; n += gridDim.x * 4) {
        const float4* Hr = reinterpret_cast<const float4*>(g_h + n * HID);
        float a0 = sb1[j0], a1 = sb1[j1];
#pragma unroll 4
        for (int c = 0; c < 16; ++c) {
            float4 v = Hr[c];
            const float* w = sW1 + 4 * c * 64;
            a0 = fmaf(v.x, w[j0], a0);           a1 = fmaf(v.x, w[j1], a1);
            a0 = fmaf(v.y, w[64 + j0], a0);      a1 = fmaf(v.y, w[64 + j1], a1);
            a0 = fmaf(v.z, w[128 + j0], a0);     a1 = fmaf(v.z, w[128 + j1], a1);
            a0 = fmaf(v.w, w[192 + j0], a0);     a1 = fmaf(v.w, w[192 + j1], a1);
        }
        a0 = silu_f(a0); a1 = silu_f(a1);
        sy[warp][j0] = a0; sy[warp][j1] = a1;
        __syncwarp();
        if (lane < 6) {
            float o = sb2[lane];
#pragma unroll 8
            for (int k = 0; k < 64; ++k) o = fmaf(sy[warp][k], sW2[k * 6 + lane], o);
            out[n * 6 + lane] = o;
        }
        __syncwarp();
    }
}

// ---------------- pooling ----------------
__global__ void __launch_bounds__(256) pool_kernel(const int* __restrict__ batch)
{
    __shared__ float sacc[NGRAPH * HID];
    __shared__ int   scnt[NGRAPH];
    int tid = threadIdx.x;
    sacc[tid] = 0.f;
    if (tid < NGRAPH) scnt[tid] = 0;
    __syncthreads();
    int j = tid & 63;
    int r = tid >> 6;
    int base = blockIdx.x * 512;
    int end = min(base + 512, NNODES);
    for (int n = base + r; n < end; n += 4) {
        int b = batch[n];
        atomicAdd(&sacc[b * HID + j], g_h[n * HID + j]);
        if (j == 0) atomicAdd(&scnt[b], 1);
    }
    __syncthreads();
    atomicAdd(&g_pooled[tid], sacc[tid]);
    if (tid < NGRAPH) atomicAdd(&g_cnt[tid], scnt[tid]);
}

// ---------------- global decoder ----------------
__global__ void dec_global_kernel(
    const float* __restrict__ W1, const float* __restrict__ b1,
    const float* __restrict__ W2, const float* __restrict__ b2,
    float* __restrict__ out)
{
    __shared__ float sy[NGRAPH][32];
    int g = threadIdx.x >> 5;
    int lane = threadIdx.x & 31;
    float inv = 1.f / fmaxf((float)g_cnt[g], 1.f);
    float a = b1[lane];
#pragma unroll 8
    for (int k = 0; k < 64; ++k)
        a = fmaf(g_pooled[g * HID + k] * inv, W1[k * 32 + lane], a);
    a = silu_f(a);
    sy[g][lane] = a;
    __syncwarp();
    if (lane < 4) {
        float o = b2[lane];
#pragma unroll 8
        for (int k = 0; k < 32; ++k) o = fmaf(sy[g][k], W2[k * 4 + lane], o);
        out[g * 4 + lane] = o;
    }
}

// ---------------- launch ----------------
extern "C" void kernel_launch(void* const* d_in, const int* in_sizes, int n_in,
                              void* d_out, int out_size)
{
    (void)in_sizes; (void)n_in; (void)out_size;
    const float* x      = (const float*)d_in[0];
    const int*   ei     = (const int*)  d_in[1];
    const float* ea     = (const float*)d_in[2];
    const int*   batch  = (const int*)  d_in[3];
    const float* caseP  = (const float*)d_in[4];
    const float* bcP    = (const float*)d_in[5];
    const float* encW1  = (const float*)d_in[6];
    const float* encb1  = (const float*)d_in[7];
    const float* encW2  = (const float*)d_in[8];
    const float* encb2  = (const float*)d_in[9];
    const float* encg   = (const float*)d_in[10];
    const float* encbe  = (const float*)d_in[11];
    const float* eW1    = (const float*)d_in[12];
    const float* eb1    = (const float*)d_in[13];
    const float* eW2    = (const float*)d_in[14];
    const float* eb2    = (const float*)d_in[15];
    const float* egm    = (const float*)d_in[16];
    const float* ebe    = (const float*)d_in[17];
    const float* nW1    = (const float*)d_in[18];
    const float* nb1    = (const float*)d_in[19];
    const float* nW2    = (const float*)d_in[20];
    const float* nb2    = (const float*)d_in[21];
    const float* ngm    = (const float*)d_in[22];
    const float* nbe    = (const float*)d_in[23];
    const float* dlW1   = (const float*)d_in[24];
    const float* dlb1   = (const float*)d_in[25];
    const float* dlW2   = (const float*)d_in[26];
    const float* dlb2   = (const float*)d_in[27];
    const float* dgW1   = (const float*)d_in[28];
    const float* dgb1   = (const float*)d_in[29];
    const float* dgW2   = (const float*)d_in[30];
    const float* dgb2   = (const float*)d_in[31];
    float* out = (float*)d_out;

    const int NODE_SMEM = (8192 + 4096 + 128 + 8448) * 4;
    cudaFuncSetAttribute(edge6_kernel, cudaFuncAttributeMaxDynamicSharedMemorySize, EDGE_SMEM);
    cudaFuncSetAttribute(node2_kernel, cudaFuncAttributeMaxDynamicSharedMemorySize, NODE_SMEM);

    prep_weights<<<(NLAYERS * 12288 + 255) / 256, 256>>>(eW1, eW2);
    encoder_kernel<<<200, 128>>>(x, batch, caseP, bcP,
                                 encW1, encb1, encW2, encb2, encg, encbe);

    const int NODE_GRID = (NNODES + 127) / 128;

    for (int l = 0; l < NLAYERS; ++l) {
        zero_agg_kernel<<<512, 256>>>();
        edge6_kernel<<<296, 128, EDGE_SMEM>>>(
            ei, ea, l,
            eW1 + l * 133 * 64, eb1 + l * 64, eb2 + l * 64,
            egm + l * 64, ebe + l * 64);
        node2_kernel<<<NODE_GRID, 256, NODE_SMEM>>>(
            nW1 + l * 128 * 64, nb1 + l * 64,
            nW2 + l * 64 * 64,  nb2 + l * 64,
            ngm + l * 64,       nbe + l * 64);
    }

    zero_pool_kernel<<<1, 256>>>();
    dec_local_kernel<<<200, 128>>>(dlW1, dlb1, dlW2, dlb2, out);
    pool_kernel<<<(NNODES + 511) / 512, 256>>>(batch);
    dec_global_kernel<<<1, 128>>>(dgW1, dgb1, dgW2, dgb2, out + NNODES * 6);
}

// round 7
// speedup vs baseline: 1.0348x; 1.0348x over previous
#include <cuda_runtime.h>
#include <cuda_bf16.h>

typedef unsigned long long ull;

#define NNODES 50000
#define NEDGES 1600000
#define NGRAPH 4
#define HID    64
#define NLAYERS 5
#define NTILES (NEDGES / 128)   // 12500

// ---------------- device scratch ----------------
__device__ float g_h[NNODES * HID];
__device__ __align__(16) __nv_bfloat16 g_hs[NNODES * 128];  // per node: 64 hi, 64 lo
__device__ float g_agg[NNODES * HID];
__device__ float g_pooled[NGRAPH * HID];
__device__ int   g_cnt[NGRAPH];
// per-layer prepped bf16 hi/lo weights [n][k] stride-144: B1(4x9216) + B2(2x9216) = 55296 B
__device__ __align__(16) unsigned char g_wB[NLAYERS * 55296];

// ---------------- SMEM layout (bytes) ----------------
#define OFF_A    0u        // A hi 128x72 bf16 (18432) + A lo (18432)
#define OFF_B1   36864u    // c0H, c0L, c1H, c1L each 9216
#define OFF_B2H  73728u
#define OFF_B2L  82944u
#define OFF_T    92160u    // W1 tail rows 128..132 fp32 [5][64] (1280)
#define OFF_BB1  93440u
#define OFF_BB2  93696u
#define OFF_G    93952u
#define OFF_BE   94208u
#define OFF_SDST 94464u    // 128 ints
#define OFF_SEA  94976u    // 128x5 fp32 (2560)
#define EDGE_SMEM 97536

// ---------------- generic helpers ----------------
__device__ __forceinline__ float silu_f(float x) {
    float t;
    asm("tanh.approx.f32 %0, %1;" : "=f"(t) : "f"(x * 0.5f));
    return x * 0.5f * t + x * 0.5f;
}
__device__ __forceinline__ ull fma2(ull a, ull b, ull c) {
    ull d;
    asm("fma.rn.f32x2 %0, %1, %2, %3;" : "=l"(d) : "l"(a), "l"(b), "l"(c));
    return d;
}
__device__ __forceinline__ ull pack2(float lo, float hi) {
    ull r;
    asm("mov.b64 %0, {%1, %2};" : "=l"(r) : "f"(lo), "f"(hi));
    return r;
}
__device__ __forceinline__ ull dup2(float x) {
    ull r;
    asm("mov.b64 %0, {%1, %1};" : "=l"(r) : "f"(x));
    return r;
}
__device__ __forceinline__ void unpack2(ull v, float& lo, float& hi) {
    asm("mov.b64 {%0, %1}, %2;" : "=f"(lo), "=f"(hi) : "l"(v));
}
__device__ __forceinline__ void red_add4(float* p, float a, float b, float c, float d) {
    asm volatile("red.global.add.v4.f32 [%0], {%1, %2, %3, %4};"
                 :: "l"(p), "f"(a), "f"(b), "f"(c), "f"(d) : "memory");
}
__device__ __forceinline__ unsigned smem_u32(const void* p) {
    unsigned a;
    asm("{ .reg .u64 t; cvta.to.shared.u64 t, %1; cvt.u32.u64 %0, t; }" : "=r"(a) : "l"(p));
    return a;
}

// ---------------- mma.sync helpers ----------------
__device__ __forceinline__ void ldsm4(unsigned* r, unsigned addr) {
    asm volatile("ldmatrix.sync.aligned.m8n8.x4.shared.b16 {%0,%1,%2,%3}, [%4];"
                 : "=r"(r[0]), "=r"(r[1]), "=r"(r[2]), "=r"(r[3]) : "r"(addr));
}
__device__ __forceinline__ void mma16816(float* c, const unsigned* a, unsigned b0, unsigned b1) {
    asm volatile("mma.sync.aligned.m16n8k16.row.col.f32.bf16.bf16.f32 "
                 "{%0,%1,%2,%3}, {%4,%5,%6,%7}, {%8,%9}, {%0,%1,%2,%3};"
                 : "+f"(c[0]), "+f"(c[1]), "+f"(c[2]), "+f"(c[3])
                 : "r"(a[0]), "r"(a[1]), "r"(a[2]), "r"(a[3]), "r"(b0), "r"(b1));
}

// ---------------- zero kernels ----------------
__global__ void zero_agg_kernel() {
    int i = blockIdx.x * blockDim.x + threadIdx.x;
    for (; i < NNODES * HID; i += gridDim.x * blockDim.x) g_agg[i] = 0.f;
}
__global__ void zero_pool_kernel() {
    int t = threadIdx.x;
    if (t < NGRAPH * HID) g_pooled[t] = 0.f;
    if (t < NGRAPH) g_cnt[t] = 0;
}

// ---------------- weight prep ----------------
__global__ void prep_weights(const float* __restrict__ eW1, const float* __restrict__ eW2) {
    int idx = blockIdx.x * blockDim.x + threadIdx.x;
    if (idx >= NLAYERS * 12288) return;
    int l = idx / 12288, r = idx % 12288;
    unsigned char* base = g_wB + l * 55296;
    float w;
    unsigned offH;
    if (r < 8192) {
        int c = r >> 12, rr = r & 4095, n = rr >> 6, kk = rr & 63;
        w = eW1[l * 133 * 64 + (c * 64 + kk) * 64 + n];
        offH = (unsigned)(c * 18432 + n * 144 + kk * 2);
    } else {
        int rr = r - 8192, n = rr >> 6, kk = rr & 63;
        w = eW2[l * 4096 + kk * 64 + n];
        offH = (unsigned)(36864 + n * 144 + kk * 2);
    }
    __nv_bfloat16 hi = __float2bfloat16(w);
    __nv_bfloat16 lo = __float2bfloat16(w - __bfloat162float(hi));
    *(__nv_bfloat16*)(base + offH) = hi;
    *(__nv_bfloat16*)(base + offH + 9216) = lo;
}

// ---------------- encoder (also writes split-bf16 g_hs) ----------------
__global__ void __launch_bounds__(128) encoder_kernel(
    const float* __restrict__ x, const int* __restrict__ batch,
    const float* __restrict__ caseP, const float* __restrict__ bcP,
    const float* __restrict__ W1, const float* __restrict__ b1,
    const float* __restrict__ W2, const float* __restrict__ b2,
    const float* __restrict__ gam, const float* __restrict__ bet)
{
    __shared__ float sW1[16 * 64];
    __shared__ float sW2[64 * 64];
    __shared__ float sb1[64], sb2[64], sg[64], sbe[64];
    __shared__ float sy[4][64];
    int tid = threadIdx.x;
    for (int i = tid; i < 16 * 64; i += 128) sW1[i] = W1[i];
    for (int i = tid; i < 64 * 64; i += 128) sW2[i] = W2[i];
    if (tid < 64) { sb1[tid] = b1[tid]; sb2[tid] = b2[tid]; sg[tid] = gam[tid]; sbe[tid] = bet[tid]; }
    __syncthreads();

    int lane = tid & 31, warp = tid >> 5;
    int j0 = lane, j1 = lane + 32;
    for (int n = blockIdx.x * 4 + warp; n < NNODES; n += gridDim.x * 4) {
        float in[16];
        const float* xr = x + n * 8;
#pragma unroll
        for (int k = 0; k < 8; ++k) in[k] = xr[k];
        int b = batch[n];
#pragma unroll
        for (int k = 0; k < 4; ++k) in[8 + k]  = caseP[b * 4 + k];
#pragma unroll
        for (int k = 0; k < 4; ++k) in[12 + k] = bcP[b * 4 + k];

        float a0 = sb1[j0], a1 = sb1[j1];
#pragma unroll
        for (int k = 0; k < 16; ++k) {
            a0 = fmaf(in[k], sW1[k * 64 + j0], a0);
            a1 = fmaf(in[k], sW1[k * 64 + j1], a1);
        }
        a0 = silu_f(a0); a1 = silu_f(a1);
        sy[warp][j0] = a0; sy[warp][j1] = a1;
        __syncwarp();
        float z0 = sb2[j0], z1 = sb2[j1];
#pragma unroll 4
        for (int k = 0; k < 64; ++k) {
            float v = sy[warp][k];
            z0 = fmaf(v, sW2[k * 64 + j0], z0);
            z1 = fmaf(v, sW2[k * 64 + j1], z1);
        }
        float s = z0 + z1, ss = z0 * z0 + z1 * z1;
#pragma unroll
        for (int o = 16; o > 0; o >>= 1) {
            s  += __shfl_xor_sync(0xffffffffu, s, o);
            ss += __shfl_xor_sync(0xffffffffu, ss, o);
        }
        float m = s * (1.f / 64.f);
        float rs = rsqrtf(ss * (1.f / 64.f) - m * m + 1e-5f);
        float v0 = (z0 - m) * rs * sg[j0] + sbe[j0];
        float v1 = (z1 - m) * rs * sg[j1] + sbe[j1];
        g_h[n * HID + j0] = v0;
        g_h[n * HID + j1] = v1;
        __nv_bfloat16 h0 = __float2bfloat16(v0);
        __nv_bfloat16 h1 = __float2bfloat16(v1);
        g_hs[n * 128 + j0] = h0;
        g_hs[n * 128 + j1] = h1;
        g_hs[n * 128 + 64 + j0] = __float2bfloat16(v0 - __bfloat162float(h0));
        g_hs[n * 128 + 64 + j1] = __float2bfloat16(v1 - __bfloat162float(h1));
        __syncwarp();
    }
}

// ---------------- edge MLP v7: R5 structure + precomputed split gather ----------------
__global__ void __launch_bounds__(128, 2) edge7_kernel(
    const int* __restrict__ ei, const float* __restrict__ ea, int layer,
    const float* __restrict__ W1full, const float* __restrict__ b1,
    const float* __restrict__ b2,
    const float* __restrict__ gam, const float* __restrict__ bet)
{
    extern __shared__ unsigned char sm[];
    const unsigned sbase = smem_u32(sm);
    const int tid = threadIdx.x;
    const int lane = tid & 31, warp = tid >> 5;
    const int gID = lane >> 2, tig = lane & 3;
    const int lt = lane >> 3, lr = lane & 7;

    // --- one-time loads ---
    {
        const uint4* srcw = (const uint4*)(g_wB + layer * 55296);
        uint4* dstw = (uint4*)(sm + OFF_B1);
#pragma unroll 4
        for (int i = tid; i < 3456; i += 128) dstw[i] = srcw[i];
    }
    for (int i = tid; i < 320; i += 128) ((float*)(sm + OFF_T))[i] = W1full[128 * 64 + i];
    if (tid < 64) {
        ((float*)(sm + OFF_BB1))[tid] = b1[tid];
        ((float*)(sm + OFF_BB2))[tid] = b2[tid];
        ((float*)(sm + OFF_G))[tid]   = gam[tid];
        ((float*)(sm + OFF_BE))[tid]  = bet[tid];
    }
    __syncthreads();

    // ldmatrix lane addressing
    const unsigned aLane = (unsigned)((lr + ((lt & 1) << 3)) * 144 + ((lt >> 1) << 4));
    const unsigned bLane = (unsigned)(((lt >> 1) * 8 + lr) * 144 + ((lt & 1) << 4));
    const unsigned AHb = sbase + OFF_A + (unsigned)(warp * 32 * 144) + aLane;
    const unsigned ALb = AHb + 18432u;
    const float* bb1 = (const float*)(sm + OFF_BB1);
    int* sdst = (int*)(sm + OFF_SDST);
    float* sea = (float*)(sm + OFF_SEA);

    for (int t = blockIdx.x; t < NTILES; t += gridDim.x) {
        __syncthreads();   // protect sdst/sea/A against previous tile's readers
        const int e0 = t * 128;
        sdst[tid] = ei[NEDGES + e0 + tid];
        for (int i = tid; i < 640; i += 128) sea[i] = ea[(ull)e0 * 5 + i];

        // acc init with b1 (C-frag layout: cols 8nt+2tig)
        float acc[2][8][4];
#pragma unroll
        for (int nt = 0; nt < 8; ++nt) {
            float2 bv = *(const float2*)(bb1 + nt * 8 + 2 * tig);
#pragma unroll
            for (int mt = 0; mt < 2; ++mt) {
                acc[mt][nt][0] = bv.x; acc[mt][nt][1] = bv.y;
                acc[mt][nt][2] = bv.x; acc[mt][nt][3] = bv.y;
            }
        }

        // ===== GEMM1: chunk0 = h[dst], chunk1 = h[src] =====
#pragma unroll 1
        for (int c = 0; c < 2; ++c) {
            const int node = ei[(c == 0 ? NEDGES : 0) + e0 + tid];
            const uint4* hp = (const uint4*)(g_hs + (ull)node * 128);
            unsigned char* hrow = sm + OFF_A + tid * 144;
#pragma unroll
            for (int i = 0; i < 8; ++i) *(uint4*)(hrow + i * 16) = hp[i];
#pragma unroll
            for (int i = 0; i < 8; ++i) *(uint4*)(hrow + 18432 + i * 16) = hp[8 + i];
            __syncthreads();

            const unsigned bH = sbase + OFF_B1 + (unsigned)c * 18432u + bLane;
            const unsigned bL = bH + 9216u;

            // hold BH fragments in registers (reused by pass0 and pass1)
            unsigned BHf[4][4][4];
#pragma unroll
            for (int kt = 0; kt < 4; ++kt)
#pragma unroll
                for (int q = 0; q < 4; ++q)
                    ldsm4(BHf[kt][q], bH + q * 2304u + kt * 32u);

            // pass0: AH x BH
#pragma unroll
            for (int kt = 0; kt < 4; ++kt) {
                unsigned a0[4], a1[4];
                ldsm4(a0, AHb + kt * 32u);
                ldsm4(a1, AHb + 2304u + kt * 32u);
#pragma unroll
                for (int q = 0; q < 4; ++q) {
                    mma16816(acc[0][2 * q],     a0, BHf[kt][q][0], BHf[kt][q][1]);
                    mma16816(acc[0][2 * q + 1], a0, BHf[kt][q][2], BHf[kt][q][3]);
                    mma16816(acc[1][2 * q],     a1, BHf[kt][q][0], BHf[kt][q][1]);
                    mma16816(acc[1][2 * q + 1], a1, BHf[kt][q][2], BHf[kt][q][3]);
                }
            }
            // pass1: AL x BH (BH reused from regs)
#pragma unroll
            for (int kt = 0; kt < 4; ++kt) {
                unsigned a0[4], a1[4];
                ldsm4(a0, ALb + kt * 32u);
                ldsm4(a1, ALb + 2304u + kt * 32u);
#pragma unroll
                for (int q = 0; q < 4; ++q) {
                    mma16816(acc[0][2 * q],     a0, BHf[kt][q][0], BHf[kt][q][1]);
                    mma16816(acc[0][2 * q + 1], a0, BHf[kt][q][2], BHf[kt][q][3]);
                    mma16816(acc[1][2 * q],     a1, BHf[kt][q][0], BHf[kt][q][1]);
                    mma16816(acc[1][2 * q + 1], a1, BHf[kt][q][2], BHf[kt][q][3]);
                }
            }
            // pass2: AH x BL (BL transient)
#pragma unroll
            for (int kt = 0; kt < 4; ++kt) {
                unsigned a0[4], a1[4];
                ldsm4(a0, AHb + kt * 32u);
                ldsm4(a1, AHb + 2304u + kt * 32u);
#pragma unroll
                for (int q = 0; q < 4; ++q) {
                    unsigned bl[4];
                    ldsm4(bl, bL + q * 2304u + kt * 32u);
                    mma16816(acc[0][2 * q],     a0, bl[0], bl[1]);
                    mma16816(acc[0][2 * q + 1], a0, bl[2], bl[3]);
                    mma16816(acc[1][2 * q],     a1, bl[0], bl[1]);
                    mma16816(acc[1][2 * q + 1], a1, bl[2], bl[3]);
                }
            }
            if (c == 0) __syncthreads();   // before chunk1 gather overwrites A
        }

        // ===== epilogue1 (registers): fp32 edge_attr tail + silu + split =====
        float eav[2][2][5];
#pragma unroll
        for (int mt = 0; mt < 2; ++mt)
#pragma unroll
            for (int h = 0; h < 2; ++h) {
                const float* er = sea + (warp * 32 + mt * 16 + h * 8 + gID) * 5;
#pragma unroll
                for (int j = 0; j < 5; ++j) eav[mt][h][j] = er[j];
            }
        unsigned uh[2][2][8], ulo[2][2][8];
#pragma unroll
        for (int nt = 0; nt < 8; ++nt) {
            float2 w[5];
#pragma unroll
            for (int j = 0; j < 5; ++j)
                w[j] = *(const float2*)(sm + OFF_T + (unsigned)((j * 64 + nt * 8 + tig * 2) * 4));
#pragma unroll
            for (int mt = 0; mt < 2; ++mt)
#pragma unroll
                for (int h = 0; h < 2; ++h) {
                    float y0 = acc[mt][nt][2 * h], y1 = acc[mt][nt][2 * h + 1];
#pragma unroll
                    for (int j = 0; j < 5; ++j) {
                        y0 = fmaf(eav[mt][h][j], w[j].x, y0);
                        y1 = fmaf(eav[mt][h][j], w[j].y, y1);
                    }
                    y0 = silu_f(y0); y1 = silu_f(y1);
                    __nv_bfloat162 hb = __float22bfloat162_rn(make_float2(y0, y1));
                    float2 f = __bfloat1622float2(hb);
                    __nv_bfloat162 lb = __float22bfloat162_rn(make_float2(y0 - f.x, y1 - f.y));
                    uh[mt][h][nt]  = *(unsigned*)&hb;
                    ulo[mt][h][nt] = *(unsigned*)&lb;
                }
        }

        // ===== GEMM2 (A from registers, B from SMEM): 3 passes =====
        float acc2[2][8][4];
#pragma unroll
        for (int nt = 0; nt < 8; ++nt) {
            float2 bv = *(const float2*)(sm + OFF_BB2 + (unsigned)((nt * 8 + tig * 2) * 4));
#pragma unroll
            for (int mt = 0; mt < 2; ++mt) {
                acc2[mt][nt][0] = bv.x; acc2[mt][nt][1] = bv.y;
                acc2[mt][nt][2] = bv.x; acc2[mt][nt][3] = bv.y;
            }
        }
        const unsigned b2H = sbase + OFF_B2H + bLane;
        const unsigned b2L = sbase + OFF_B2L + bLane;
#pragma unroll
        for (int p = 0; p < 3; ++p) {
            const unsigned bB = (p == 1) ? b2L : b2H;
#pragma unroll
            for (int kt = 0; kt < 4; ++kt) {
                unsigned af0[4], af1[4];
                if (p == 2) {
                    af0[0] = ulo[0][0][2 * kt]; af0[1] = ulo[0][1][2 * kt];
                    af0[2] = ulo[0][0][2 * kt + 1]; af0[3] = ulo[0][1][2 * kt + 1];
                    af1[0] = ulo[1][0][2 * kt]; af1[1] = ulo[1][1][2 * kt];
                    af1[2] = ulo[1][0][2 * kt + 1]; af1[3] = ulo[1][1][2 * kt + 1];
                } else {
                    af0[0] = uh[0][0][2 * kt]; af0[1] = uh[0][1][2 * kt];
                    af0[2] = uh[0][0][2 * kt + 1]; af0[3] = uh[0][1][2 * kt + 1];
                    af1[0] = uh[1][0][2 * kt]; af1[1] = uh[1][1][2 * kt];
                    af1[2] = uh[1][0][2 * kt + 1]; af1[3] = uh[1][1][2 * kt + 1];
                }
#pragma unroll
                for (int q = 0; q < 4; ++q) {
                    unsigned b[4];
                    ldsm4(b, bB + q * 2304u + kt * 32u);
                    mma16816(acc2[0][2 * q],     af0, b[0], b[1]);
                    mma16816(acc2[0][2 * q + 1], af0, b[2], b[3]);
                    mma16816(acc2[1][2 * q],     af1, b[0], b[1]);
                    mma16816(acc2[1][2 * q + 1], af1, b[2], b[3]);
                }
            }
        }

        // ===== epilogue2: LayerNorm (shuffles) + scatter (red.v4) =====
        float mArr[2][2], rsArr[2][2];
#pragma unroll
        for (int mt = 0; mt < 2; ++mt)
#pragma unroll
            for (int h = 0; h < 2; ++h) {
                float s = 0.f, ssum = 0.f;
#pragma unroll
                for (int nt = 0; nt < 8; ++nt) {
                    float v0 = acc2[mt][nt][2 * h], v1 = acc2[mt][nt][2 * h + 1];
                    s += v0 + v1; ssum += v0 * v0 + v1 * v1;
                }
                s    += __shfl_xor_sync(0xffffffffu, s, 1);
                ssum += __shfl_xor_sync(0xffffffffu, ssum, 1);
                s    += __shfl_xor_sync(0xffffffffu, s, 2);
                ssum += __shfl_xor_sync(0xffffffffu, ssum, 2);
                float m = s * (1.f / 64.f);
                mArr[mt][h]  = m;
                rsArr[mt][h] = rsqrtf(ssum * (1.f / 64.f) - m * m + 1e-5f);
            }
        const int cq = (tig & 1) * 2 + (tig >> 1);
        float4 gq[4], beq[4];
#pragma unroll
        for (int j = 0; j < 4; ++j) {
            gq[j]  = ((const float4*)(sm + OFF_G))[4 * j + cq];
            beq[j] = ((const float4*)(sm + OFF_BE))[4 * j + cq];
        }
        const unsigned colb = (unsigned)((tig & 1) * 8 + (tig >> 1) * 4);
#pragma unroll
        for (int mt = 0; mt < 2; ++mt)
#pragma unroll
            for (int h = 0; h < 2; ++h) {
                int row = warp * 32 + mt * 16 + h * 8 + gID;
                float* ag = g_agg + (ull)sdst[row] * 64 + colb;
                float m = mArr[mt][h], rs = rsArr[mt][h];
#pragma unroll
                for (int j = 0; j < 4; ++j) {
                    ull p0 = pack2(acc2[mt][2 * j][2 * h],     acc2[mt][2 * j][2 * h + 1]);
                    ull p1 = pack2(acc2[mt][2 * j + 1][2 * h], acc2[mt][2 * j + 1][2 * h + 1]);
                    ull sel = (tig & 1) ? p0 : p1;
                    ull rv = __shfl_xor_sync(0xffffffffu, sel, 1);
                    float q0, q1, q2, q3;
                    if (tig & 1) { unpack2(rv, q0, q1); unpack2(p1, q2, q3); }
                    else         { unpack2(p0, q0, q1); unpack2(rv, q2, q3); }
                    float o0 = (q0 - m) * rs * gq[j].x + beq[j].x;
                    float o1 = (q1 - m) * rs * gq[j].y + beq[j].y;
                    float o2 = (q2 - m) * rs * gq[j].z + beq[j].z;
                    float o3 = (q3 - m) * rs * gq[j].w + beq[j].w;
                    red_add4(ag + 16 * j, o0, o1, o2, o3);
                }
            }
    }
}

// ---------------- node MLP (fp32 register-tiled; also writes g_hs) ----------------
#define FMA16(AA, AB, W0, W1, W2, W3, ACC)                               \
    do {                                                                 \
        ACC[0][0]=fma2(AA.x,W0,ACC[0][0]); ACC[0][1]=fma2(AA.x,W1,ACC[0][1]); \
        ACC[0][2]=fma2(AA.x,W2,ACC[0][2]); ACC[0][3]=fma2(AA.x,W3,ACC[0][3]); \
        ACC[1][0]=fma2(AA.y,W0,ACC[1][0]); ACC[1][1]=fma2(AA.y,W1,ACC[1][1]); \
        ACC[1][2]=fma2(AA.y,W2,ACC[1][2]); ACC[1][3]=fma2(AA.y,W3,ACC[1][3]); \
        ACC[2][0]=fma2(AB.x,W0,ACC[2][0]); ACC[2][1]=fma2(AB.x,W1,ACC[2][1]); \
        ACC[2][2]=fma2(AB.x,W2,ACC[2][2]); ACC[2][3]=fma2(AB.x,W3,ACC[2][3]); \
        ACC[3][0]=fma2(AB.y,W0,ACC[3][0]); ACC[3][1]=fma2(AB.y,W1,ACC[3][1]); \
        ACC[3][2]=fma2(AB.y,W2,ACC[3][2]); ACC[3][3]=fma2(AB.y,W3,ACC[3][3]); \
    } while (0)

__global__ void __launch_bounds__(256, 2) node2_kernel(
    const float* __restrict__ W1, const float* __restrict__ b1,
    const float* __restrict__ W2, const float* __restrict__ b2,
    const float* __restrict__ gam, const float* __restrict__ bet)
{
    extern __shared__ float smem[];
    float* sW1 = smem;
    float* sW2 = sW1 + 8192;
    float* sg  = sW2 + 4096;
    float* sbe = sg + 64;
    float* buf = sbe + 64;

    const int tid = threadIdx.x;
    for (int i = tid; i < 8192; i += 256) sW1[i] = W1[i];
    for (int i = tid; i < 4096; i += 256) sW2[i] = W2[i];
    if (tid < 64) { sg[tid] = gam[tid]; sbe[tid] = bet[tid]; }

    const int n0 = blockIdx.x * 128;
    const int tn = tid & 15, tm = tid >> 4;
    const int eg_ = tid & 127;
    const int kq  = (tid >> 7) * 4;

    ull acc[4][4];
    {
        float4 bv = *(const float4*)(b1 + tn * 4);
#pragma unroll
        for (int ep = 0; ep < 4; ++ep) {
            acc[ep][0] = dup2(bv.x); acc[ep][1] = dup2(bv.y);
            acc[ep][2] = dup2(bv.z); acc[ep][3] = dup2(bv.w);
        }
    }

    int ngi = n0 + eg_;
    if (ngi >= NNODES) ngi = 0;

#pragma unroll
    for (int ch = 0; ch < 2; ++ch) {
        const float* srcp = (ch == 0) ? g_h : g_agg;
        const float4* hp = (const float4*)(srcp + (ull)ngi * 64);
        __syncthreads();
#pragma unroll
        for (int r = 0; r < 8; ++r) {
            int k = r * 8 + kq;
            float4 v = hp[2 * r + (kq >> 2)];
            buf[(k + 0) * 128 + eg_] = v.x;
            buf[(k + 1) * 128 + eg_] = v.y;
            buf[(k + 2) * 128 + eg_] = v.z;
            buf[(k + 3) * 128 + eg_] = v.w;
        }
        __syncthreads();
        const float* wbase = sW1 + ch * 64 * 64;
#pragma unroll 2
        for (int k = 0; k < 64; ++k) {
            const ulonglong2* ar = (const ulonglong2*)(buf + k * 128 + tm * 8);
            ulonglong2 aA = ar[0], aB = ar[1];
            float4 wv = *(const float4*)(wbase + k * 64 + tn * 4);
            ull w0 = dup2(wv.x), w1 = dup2(wv.y), w2 = dup2(wv.z), w3 = dup2(wv.w);
            FMA16(aA, aB, w0, w1, w2, w3, acc);
        }
    }
    __syncthreads();

#pragma unroll
    for (int ep = 0; ep < 4; ++ep)
#pragma unroll
        for (int j = 0; j < 4; ++j) {
            float x0, x1;
            unpack2(acc[ep][j], x0, x1);
            *(ull*)(buf + (tn * 4 + j) * 132 + tm * 8 + 2 * ep) = pack2(silu_f(x0), silu_f(x1));
        }
    __syncthreads();

    ull acc2[4][4];
    {
        float4 bv = *(const float4*)(b2 + tn * 4);
#pragma unroll
        for (int ep = 0; ep < 4; ++ep) {
            acc2[ep][0] = dup2(bv.x); acc2[ep][1] = dup2(bv.y);
            acc2[ep][2] = dup2(bv.z); acc2[ep][3] = dup2(bv.w);
        }
    }
#pragma unroll 2
    for (int k = 0; k < 64; ++k) {
        const ulonglong2* ar = (const ulonglong2*)(buf + k * 132 + tm * 8);
        ulonglong2 aA = ar[0], aB = ar[1];
        float4 wv = *(const float4*)(sW2 + k * 64 + tn * 4);
        ull w0 = dup2(wv.x), w1 = dup2(wv.y), w2 = dup2(wv.z), w3 = dup2(wv.w);
        FMA16(aA, aB, w0, w1, w2, w3, acc2);
    }
    __syncthreads();

#pragma unroll
    for (int ep = 0; ep < 4; ++ep)
#pragma unroll
        for (int j = 0; j < 4; ++j) {
            float x0, x1;
            unpack2(acc2[ep][j], x0, x1);
            int e = tm * 8 + 2 * ep;
            buf[e * 66 + tn * 4 + j]       = x0;
            buf[(e + 1) * 66 + tn * 4 + j] = x1;
        }
    __syncthreads();

    if (tid < 128 && n0 + tid < NNODES) {
        const float* z = buf + tid * 66;
        float s = 0.f, ss = 0.f;
#pragma unroll 8
        for (int c = 0; c < 64; ++c) { float v = z[c]; s += v; ss += v * v; }
        float m  = s * (1.f / 64.f);
        float rs = rsqrtf(ss * (1.f / 64.f) - m * m + 1e-5f);
        float4* hp = (float4*)(g_h + (ull)(n0 + tid) * 64);
        __nv_bfloat16* hs = g_hs + (ull)(n0 + tid) * 128;
#pragma unroll
        for (int q = 0; q < 16; ++q) {
            float4 hv = hp[q];
            hv.x += (z[4 * q + 0] - m) * rs * sg[4 * q + 0] + sbe[4 * q + 0];
            hv.y += (z[4 * q + 1] - m) * rs * sg[4 * q + 1] + sbe[4 * q + 1];
            hv.z += (z[4 * q + 2] - m) * rs * sg[4 * q + 2] + sbe[4 * q + 2];
            hv.w += (z[4 * q + 3] - m) * rs * sg[4 * q + 3] + sbe[4 * q + 3];
            hp[q] = hv;
            __nv_bfloat162 h01 = __float22bfloat162_rn(make_float2(hv.x, hv.y));
            __nv_bfloat162 h23 = __float22bfloat162_rn(make_float2(hv.z, hv.w));
            float2 f01 = __bfloat1622float2(h01);
            float2 f23 = __bfloat1622float2(h23);
            __nv_bfloat162 l01 = __float22bfloat162_rn(make_float2(hv.x - f01.x, hv.y - f01.y));
            __nv_bfloat162 l23 = __float22bfloat162_rn(make_float2(hv.z - f23.x, hv.w - f23.y));
            *(unsigned*)(hs + 4 * q)     = *(unsigned*)&h01;
            *(unsigned*)(hs + 4 * q + 2) = *(unsigned*)&h23;
            *(unsigned*)(hs + 64 + 4 * q)     = *(unsigned*)&l01;
            *(unsigned*)(hs + 64 + 4 * q + 2) = *(unsigned*)&l23;
        }
    }
}

// ---------------- local decoder ----------------
__global__ void __launch_bounds__(128) dec_local_kernel(
    const float* __restrict__ W1, const float* __restrict__ b1,
    const float* __restrict__ W2, const float* __restrict__ b2,
    float* __restrict__ out)
{
    __shared__ float sW1[64 * 64];
    __shared__ float sW2[64 * 6];
    __shared__ float sb1[64];
    __shared__ float sb2[8];
    __shared__ float sy[4][64];
    int tid = threadIdx.x;
    for (int i = tid; i < 64 * 64; i += 128) sW1[i] = W1[i];
    for (int i = tid; i < 64 * 6; i += 128) sW2[i] = W2[i];
    if (tid < 64) sb1[tid] = b1[tid];
    if (tid < 6)  sb2[tid] = b2[tid];
    __syncthreads();

    int lane = tid & 31, warp = tid >> 5;
    int j0 = lane, j1 = lane + 32;
    for (int n = blockIdx.x * 4 + warp; n < NNODES; n += gridDim.x * 4) {
        const float4* Hr = reinterpret_cast<const float4*>(g_h + n * HID);
        float a0 = sb1[j0], a1 = sb1[j1];
#pragma unroll 4
        for (int c = 0; c < 16; ++c) {
            float4 v = Hr[c];
            const float* w = sW1 + 4 * c * 64;
            a0 = fmaf(v.x, w[j0], a0);           a1 = fmaf(v.x, w[j1], a1);
            a0 = fmaf(v.y, w[64 + j0], a0);      a1 = fmaf(v.y, w[64 + j1], a1);
            a0 = fmaf(v.z, w[128 + j0], a0);     a1 = fmaf(v.z, w[128 + j1], a1);
            a0 = fmaf(v.w, w[192 + j0], a0);     a1 = fmaf(v.w, w[192 + j1], a1);
        }
        a0 = silu_f(a0); a1 = silu_f(a1);
        sy[warp][j0] = a0; sy[warp][j1] = a1;
        __syncwarp();
        if (lane < 6) {
            float o = sb2[lane];
#pragma unroll 8
            for (int k = 0; k < 64; ++k) o = fmaf(sy[warp][k], sW2[k * 6 + lane], o);
            out[n * 6 + lane] = o;
        }
        __syncwarp();
    }
}

// ---------------- pooling ----------------
__global__ void __launch_bounds__(256) pool_kernel(const int* __restrict__ batch)
{
    __shared__ float sacc[NGRAPH * HID];
    __shared__ int   scnt[NGRAPH];
    int tid = threadIdx.x;
    sacc[tid] = 0.f;
    if (tid < NGRAPH) scnt[tid] = 0;
    __syncthreads();
    int j = tid & 63;
    int r = tid >> 6;
    int base = blockIdx.x * 512;
    int end = min(base + 512, NNODES);
    for (int n = base + r; n < end; n += 4) {
        int b = batch[n];
        atomicAdd(&sacc[b * HID + j], g_h[n * HID + j]);
        if (j == 0) atomicAdd(&scnt[b], 1);
    }
    __syncthreads();
    atomicAdd(&g_pooled[tid], sacc[tid]);
    if (tid < NGRAPH) atomicAdd(&g_cnt[tid], scnt[tid]);
}

// ---------------- global decoder ----------------
__global__ void dec_global_kernel(
    const float* __restrict__ W1, const float* __restrict__ b1,
    const float* __restrict__ W2, const float* __restrict__ b2,
    float* __restrict__ out)
{
    __shared__ float sy[NGRAPH][32];
    int g = threadIdx.x >> 5;
    int lane = threadIdx.x & 31;
    float inv = 1.f / fmaxf((float)g_cnt[g], 1.f);
    float a = b1[lane];
#pragma unroll 8
    for (int k = 0; k < 64; ++k)
        a = fmaf(g_pooled[g * HID + k] * inv, W1[k * 32 + lane], a);
    a = silu_f(a);
    sy[g][lane] = a;
    __syncwarp();
    if (lane < 4) {
        float o = b2[lane];
#pragma unroll 8
        for (int k = 0; k < 32; ++k) o = fmaf(sy[g][k], W2[k * 4 + lane], o);
        out[g * 4 + lane] = o;
    }
}

// ---------------- launch ----------------
extern "C" void kernel_launch(void* const* d_in, const int* in_sizes, int n_in,
                              void* d_out, int out_size)
{
    (void)in_sizes; (void)n_in; (void)out_size;
    const float* x      = (const float*)d_in[0];
    const int*   ei     = (const int*)  d_in[1];
    const float* ea     = (const float*)d_in[2];
    const int*   batch  = (const int*)  d_in[3];
    const float* caseP  = (const float*)d_in[4];
    const float* bcP    = (const float*)d_in[5];
    const float* encW1  = (const float*)d_in[6];
    const float* encb1  = (const float*)d_in[7];
    const float* encW2  = (const float*)d_in[8];
    const float* encb2  = (const float*)d_in[9];
    const float* encg   = (const float*)d_in[10];
    const float* encbe  = (const float*)d_in[11];
    const float* eW1    = (const float*)d_in[12];
    const float* eb1    = (const float*)d_in[13];
    const float* eW2    = (const float*)d_in[14];
    const float* eb2    = (const float*)d_in[15];
    const float* egm    = (const float*)d_in[16];
    const float* ebe    = (const float*)d_in[17];
    const float* nW1    = (const float*)d_in[18];
    const float* nb1    = (const float*)d_in[19];
    const float* nW2    = (const float*)d_in[20];
    const float* nb2    = (const float*)d_in[21];
    const float* ngm    = (const float*)d_in[22];
    const float* nbe    = (const float*)d_in[23];
    const float* dlW1   = (const float*)d_in[24];
    const float* dlb1   = (const float*)d_in[25];
    const float* dlW2   = (const float*)d_in[26];
    const float* dlb2   = (const float*)d_in[27];
    const float* dgW1   = (const float*)d_in[28];
    const float* dgb1   = (const float*)d_in[29];
    const float* dgW2   = (const float*)d_in[30];
    const float* dgb2   = (const float*)d_in[31];
    float* out = (float*)d_out;

    const int NODE_SMEM = (8192 + 4096 + 128 + 8448) * 4;
    cudaFuncSetAttribute(edge7_kernel, cudaFuncAttributeMaxDynamicSharedMemorySize, EDGE_SMEM);
    cudaFuncSetAttribute(node2_kernel, cudaFuncAttributeMaxDynamicSharedMemorySize, NODE_SMEM);

    prep_weights<<<(NLAYERS * 12288 + 255) / 256, 256>>>(eW1, eW2);
    encoder_kernel<<<200, 128>>>(x, batch, caseP, bcP,
                                 encW1, encb1, encW2, encb2, encg, encbe);

    const int NODE_GRID = (NNODES + 127) / 128;

    for (int l = 0; l < NLAYERS; ++l) {
        zero_agg_kernel<<<512, 256>>>();
        edge7_kernel<<<296, 128, EDGE_SMEM>>>(
            ei, ea, l,
            eW1 + l * 133 * 64, eb1 + l * 64, eb2 + l * 64,
            egm + l * 64, ebe + l * 64);
        node2_kernel<<<NODE_GRID, 256, NODE_SMEM>>>(
            nW1 + l * 128 * 64, nb1 + l * 64,
            nW2 + l * 64 * 64,  nb2 + l * 64,
            ngm + l * 64,       nbe + l * 64);
    }

    zero_pool_kernel<<<1, 256>>>();
    dec_local_kernel<<<200, 128>>>(dlW1, dlb1, dlW2, dlb2, out);
    pool_kernel<<<(NNODES + 511) / 512, 256>>>(batch);
    dec_global_kernel<<<1, 128>>>(dgW1, dgb1, dgW2, dgb2, out + NNODES * 6);
}

// round 8
// speedup vs baseline: 1.1145x; 1.0770x over previous
#include <cuda_runtime.h>
#include <cuda_fp16.h>

typedef unsigned long long ull;

#define NNODES 50000
#define NEDGES 1600000
#define NGRAPH 4
#define HID    64
#define NLAYERS 5
#define NTILES (NEDGES / 128)   // 12500

// ---------------- device scratch ----------------
__device__ float g_h[NNODES * HID];
__device__ __align__(16) __half g_hs[NNODES * 128];   // per node: 64 fp16 hi, 64 fp16 lo
__device__ float g_agg[NNODES * HID];
__device__ float g_pooled[NGRAPH * HID];
__device__ int   g_cnt[NGRAPH];
// per-layer fp16 weights [n][k] stride-144: B1 (2 chunks x 9216) + B2 (9216) = 27648 B
__device__ __align__(16) unsigned char g_wB[NLAYERS * 27648];

// ---------------- SMEM layout (bytes) ----------------
#define OFF_A    0u        // A hi 128x72 fp16 (18432) + A lo (18432)
#define OFF_B1   36864u    // chunk0 9216, chunk1 9216
#define OFF_B2   55296u    // 9216
#define OFF_T    64512u    // W1 tail rows 128..132 fp32 [5][64] (1280)
#define OFF_BB1  65792u
#define OFF_BB2  66048u
#define OFF_G    66304u
#define OFF_BE   66560u
#define OFF_SDST 66816u    // 128 ints
#define OFF_SEA  67328u    // 128x5 fp32 (2560)
#define EDGE_SMEM 69888

// ---------------- generic helpers ----------------
__device__ __forceinline__ float silu_f(float x) {
    float t;
    asm("tanh.approx.f32 %0, %1;" : "=f"(t) : "f"(x * 0.5f));
    return x * 0.5f * t + x * 0.5f;
}
__device__ __forceinline__ ull fma2(ull a, ull b, ull c) {
    ull d;
    asm("fma.rn.f32x2 %0, %1, %2, %3;" : "=l"(d) : "l"(a), "l"(b), "l"(c));
    return d;
}
__device__ __forceinline__ ull pack2(float lo, float hi) {
    ull r;
    asm("mov.b64 %0, {%1, %2};" : "=l"(r) : "f"(lo), "f"(hi));
    return r;
}
__device__ __forceinline__ ull dup2(float x) {
    ull r;
    asm("mov.b64 %0, {%1, %1};" : "=l"(r) : "f"(x));
    return r;
}
__device__ __forceinline__ void unpack2(ull v, float& lo, float& hi) {
    asm("mov.b64 {%0, %1}, %2;" : "=f"(lo), "=f"(hi) : "l"(v));
}
__device__ __forceinline__ void red_add4(float* p, float a, float b, float c, float d) {
    asm volatile("red.global.add.v4.f32 [%0], {%1, %2, %3, %4};"
                 :: "l"(p), "f"(a), "f"(b), "f"(c), "f"(d) : "memory");
}
__device__ __forceinline__ unsigned smem_u32(const void* p) {
    unsigned a;
    asm("{ .reg .u64 t; cvta.to.shared.u64 t, %1; cvt.u32.u64 %0, t; }" : "=r"(a) : "l"(p));
    return a;
}

// ---------------- mma.sync helpers (fp16 in, fp32 accum) ----------------
__device__ __forceinline__ void ldsm4(unsigned* r, unsigned addr) {
    asm volatile("ldmatrix.sync.aligned.m8n8.x4.shared.b16 {%0,%1,%2,%3}, [%4];"
                 : "=r"(r[0]), "=r"(r[1]), "=r"(r[2]), "=r"(r[3]) : "r"(addr));
}
__device__ __forceinline__ void mma16816(float* c, const unsigned* a, unsigned b0, unsigned b1) {
    asm volatile("mma.sync.aligned.m16n8k16.row.col.f32.f16.f16.f32 "
                 "{%0,%1,%2,%3}, {%4,%5,%6,%7}, {%8,%9}, {%0,%1,%2,%3};"
                 : "+f"(c[0]), "+f"(c[1]), "+f"(c[2]), "+f"(c[3])
                 : "r"(a[0]), "r"(a[1]), "r"(a[2]), "r"(a[3]), "r"(b0), "r"(b1));
}

// ---------------- zero kernels ----------------
__global__ void zero_agg_kernel() {
    int i = blockIdx.x * blockDim.x + threadIdx.x;
    for (; i < NNODES * HID; i += gridDim.x * blockDim.x) g_agg[i] = 0.f;
}
__global__ void zero_pool_kernel() {
    int t = threadIdx.x;
    if (t < NGRAPH * HID) g_pooled[t] = 0.f;
    if (t < NGRAPH) g_cnt[t] = 0;
}

// ---------------- weight prep: fp32 -> fp16, padded [n][k] ----------------
__global__ void prep_weights(const float* __restrict__ eW1, const float* __restrict__ eW2) {
    int idx = blockIdx.x * blockDim.x + threadIdx.x;
    if (idx >= NLAYERS * 12288) return;
    int l = idx / 12288, r = idx % 12288;
    unsigned char* base = g_wB + l * 27648;
    float w;
    unsigned off;
    if (r < 8192) {                        // B1 chunks (k rows 0..127 of W1)
        int c = r >> 12, rr = r & 4095, n = rr >> 6, kk = rr & 63;
        w = eW1[l * 133 * 64 + (c * 64 + kk) * 64 + n];
        off = (unsigned)(c * 9216 + n * 144 + kk * 2);
    } else {                               // B2
        int rr = r - 8192, n = rr >> 6, kk = rr & 63;
        w = eW2[l * 4096 + kk * 64 + n];
        off = (unsigned)(18432 + n * 144 + kk * 2);
    }
    *(__half*)(base + off) = __float2half_rn(w);
}

// ---------------- encoder (also writes split-fp16 g_hs) ----------------
__global__ void __launch_bounds__(128) encoder_kernel(
    const float* __restrict__ x, const int* __restrict__ batch,
    const float* __restrict__ caseP, const float* __restrict__ bcP,
    const float* __restrict__ W1, const float* __restrict__ b1,
    const float* __restrict__ W2, const float* __restrict__ b2,
    const float* __restrict__ gam, const float* __restrict__ bet)
{
    __shared__ float sW1[16 * 64];
    __shared__ float sW2[64 * 64];
    __shared__ float sb1[64], sb2[64], sg[64], sbe[64];
    __shared__ float sy[4][64];
    int tid = threadIdx.x;
    for (int i = tid; i < 16 * 64; i += 128) sW1[i] = W1[i];
    for (int i = tid; i < 64 * 64; i += 128) sW2[i] = W2[i];
    if (tid < 64) { sb1[tid] = b1[tid]; sb2[tid] = b2[tid]; sg[tid] = gam[tid]; sbe[tid] = bet[tid]; }
    __syncthreads();

    int lane = tid & 31, warp = tid >> 5;
    int j0 = lane, j1 = lane + 32;
    for (int n = blockIdx.x * 4 + warp; n < NNODES; n += gridDim.x * 4) {
        float in[16];
        const float* xr = x + n * 8;
#pragma unroll
        for (int k = 0; k < 8; ++k) in[k] = xr[k];
        int b = batch[n];
#pragma unroll
        for (int k = 0; k < 4; ++k) in[8 + k]  = caseP[b * 4 + k];
#pragma unroll
        for (int k = 0; k < 4; ++k) in[12 + k] = bcP[b * 4 + k];

        float a0 = sb1[j0], a1 = sb1[j1];
#pragma unroll
        for (int k = 0; k < 16; ++k) {
            a0 = fmaf(in[k], sW1[k * 64 + j0], a0);
            a1 = fmaf(in[k], sW1[k * 64 + j1], a1);
        }
        a0 = silu_f(a0); a1 = silu_f(a1);
        sy[warp][j0] = a0; sy[warp][j1] = a1;
        __syncwarp();
        float z0 = sb2[j0], z1 = sb2[j1];
#pragma unroll 4
        for (int k = 0; k < 64; ++k) {
            float v = sy[warp][k];
            z0 = fmaf(v, sW2[k * 64 + j0], z0);
            z1 = fmaf(v, sW2[k * 64 + j1], z1);
        }
        float s = z0 + z1, ss = z0 * z0 + z1 * z1;
#pragma unroll
        for (int o = 16; o > 0; o >>= 1) {
            s  += __shfl_xor_sync(0xffffffffu, s, o);
            ss += __shfl_xor_sync(0xffffffffu, ss, o);
        }
        float m = s * (1.f / 64.f);
        float rs = rsqrtf(ss * (1.f / 64.f) - m * m + 1e-5f);
        float v0 = (z0 - m) * rs * sg[j0] + sbe[j0];
        float v1 = (z1 - m) * rs * sg[j1] + sbe[j1];
        g_h[n * HID + j0] = v0;
        g_h[n * HID + j1] = v1;
        __half h0 = __float2half_rn(v0);
        __half h1 = __float2half_rn(v1);
        g_hs[n * 128 + j0] = h0;
        g_hs[n * 128 + j1] = h1;
        g_hs[n * 128 + 64 + j0] = __float2half_rn(v0 - __half2float(h0));
        g_hs[n * 128 + 64 + j1] = __float2half_rn(v1 - __half2float(h1));
        __syncwarp();
    }
}

// ---------------- edge MLP v8: fp16 2-pass, 3 CTAs/SM ----------------
__global__ void __launch_bounds__(128, 3) edge8_kernel(
    const int* __restrict__ ei, const float* __restrict__ ea, int layer,
    const float* __restrict__ W1full, const float* __restrict__ b1,
    const float* __restrict__ b2,
    const float* __restrict__ gam, const float* __restrict__ bet)
{
    extern __shared__ unsigned char sm[];
    const unsigned sbase = smem_u32(sm);
    const int tid = threadIdx.x;
    const int lane = tid & 31, warp = tid >> 5;
    const int gID = lane >> 2, tig = lane & 3;
    const int lt = lane >> 3, lr = lane & 7;

    // --- one-time loads ---
    {
        const uint4* srcw = (const uint4*)(g_wB + layer * 27648);
        uint4* dstw = (uint4*)(sm + OFF_B1);
#pragma unroll 4
        for (int i = tid; i < 1728; i += 128) dstw[i] = srcw[i];
    }
    for (int i = tid; i < 320; i += 128) ((float*)(sm + OFF_T))[i] = W1full[128 * 64 + i];
    if (tid < 64) {
        ((float*)(sm + OFF_BB1))[tid] = b1[tid];
        ((float*)(sm + OFF_BB2))[tid] = b2[tid];
        ((float*)(sm + OFF_G))[tid]   = gam[tid];
        ((float*)(sm + OFF_BE))[tid]  = bet[tid];
    }
    __syncthreads();

    // ldmatrix lane addressing
    const unsigned aLane = (unsigned)((lr + ((lt & 1) << 3)) * 144 + ((lt >> 1) << 4));
    const unsigned bLane = (unsigned)(((lt >> 1) * 8 + lr) * 144 + ((lt & 1) << 4));
    const unsigned AHb = sbase + OFF_A + (unsigned)(warp * 32 * 144) + aLane;
    const unsigned ALb = AHb + 18432u;
    const float* bb1 = (const float*)(sm + OFF_BB1);
    int* sdst = (int*)(sm + OFF_SDST);
    float* sea = (float*)(sm + OFF_SEA);

    for (int t = blockIdx.x; t < NTILES; t += gridDim.x) {
        __syncthreads();   // protect sdst/sea/A against previous tile's readers
        const int e0 = t * 128;
        sdst[tid] = ei[NEDGES + e0 + tid];
        for (int i = tid; i < 640; i += 128) sea[i] = ea[(ull)e0 * 5 + i];

        // acc init with b1 (C-frag layout: cols 8nt+2tig)
        float acc[2][8][4];
#pragma unroll
        for (int nt = 0; nt < 8; ++nt) {
            float2 bv = *(const float2*)(bb1 + nt * 8 + 2 * tig);
#pragma unroll
            for (int mt = 0; mt < 2; ++mt) {
                acc[mt][nt][0] = bv.x; acc[mt][nt][1] = bv.y;
                acc[mt][nt][2] = bv.x; acc[mt][nt][3] = bv.y;
            }
        }

        // ===== GEMM1: chunk0 = h[dst], chunk1 = h[src]; 2 passes each =====
#pragma unroll 1
        for (int c = 0; c < 2; ++c) {
            const int node = ei[(c == 0 ? NEDGES : 0) + e0 + tid];
            const uint4* hp = (const uint4*)(g_hs + (ull)node * 128);
            unsigned char* hrow = sm + OFF_A + tid * 144;
#pragma unroll
            for (int i = 0; i < 8; ++i) *(uint4*)(hrow + i * 16) = hp[i];
#pragma unroll
            for (int i = 0; i < 8; ++i) *(uint4*)(hrow + 18432 + i * 16) = hp[8 + i];
            __syncthreads();

            const unsigned bB = sbase + OFF_B1 + (unsigned)c * 9216u + bLane;
#pragma unroll 1
            for (int p = 0; p < 2; ++p) {
                const unsigned aB = (p == 0) ? AHb : ALb;
#pragma unroll
                for (int kt = 0; kt < 4; ++kt) {
                    unsigned a0[4], a1[4];
                    ldsm4(a0, aB + kt * 32u);
                    ldsm4(a1, aB + 2304u + kt * 32u);
#pragma unroll
                    for (int q = 0; q < 4; ++q) {
                        unsigned b[4];
                        ldsm4(b, bB + q * 2304u + kt * 32u);
                        mma16816(acc[0][2 * q],     a0, b[0], b[1]);
                        mma16816(acc[0][2 * q + 1], a0, b[2], b[3]);
                        mma16816(acc[1][2 * q],     a1, b[0], b[1]);
                        mma16816(acc[1][2 * q + 1], a1, b[2], b[3]);
                    }
                }
            }
            if (c == 0) __syncthreads();   // before chunk1 gather overwrites A
        }

        // ===== epilogue1 (registers): fp32 edge_attr tail + silu + fp16 split =====
        float eav[2][2][5];
#pragma unroll
        for (int mt = 0; mt < 2; ++mt)
#pragma unroll
            for (int h = 0; h < 2; ++h) {
                const float* er = sea + (warp * 32 + mt * 16 + h * 8 + gID) * 5;
#pragma unroll
                for (int j = 0; j < 5; ++j) eav[mt][h][j] = er[j];
            }
        unsigned uh[2][2][8], ulo[2][2][8];
#pragma unroll
        for (int nt = 0; nt < 8; ++nt) {
            float2 w[5];
#pragma unroll
            for (int j = 0; j < 5; ++j)
                w[j] = *(const float2*)(sm + OFF_T + (unsigned)((j * 64 + nt * 8 + tig * 2) * 4));
#pragma unroll
            for (int mt = 0; mt < 2; ++mt)
#pragma unroll
                for (int h = 0; h < 2; ++h) {
                    float y0 = acc[mt][nt][2 * h], y1 = acc[mt][nt][2 * h + 1];
#pragma unroll
                    for (int j = 0; j < 5; ++j) {
                        y0 = fmaf(eav[mt][h][j], w[j].x, y0);
                        y1 = fmaf(eav[mt][h][j], w[j].y, y1);
                    }
                    y0 = silu_f(y0); y1 = silu_f(y1);
                    __half2 hb = __float22half2_rn(make_float2(y0, y1));
                    float2 f = __half22float2(hb);
                    __half2 lb = __float22half2_rn(make_float2(y0 - f.x, y1 - f.y));
                    uh[mt][h][nt]  = *(unsigned*)&hb;
                    ulo[mt][h][nt] = *(unsigned*)&lb;
                }
        }

        // ===== GEMM2 (A from registers, B from SMEM): 2 passes =====
        float acc2[2][8][4];
#pragma unroll
        for (int nt = 0; nt < 8; ++nt) {
            float2 bv = *(const float2*)(sm + OFF_BB2 + (unsigned)((nt * 8 + tig * 2) * 4));
#pragma unroll
            for (int mt = 0; mt < 2; ++mt) {
                acc2[mt][nt][0] = bv.x; acc2[mt][nt][1] = bv.y;
                acc2[mt][nt][2] = bv.x; acc2[mt][nt][3] = bv.y;
            }
        }
        const unsigned b2B = sbase + OFF_B2 + bLane;
#pragma unroll
        for (int p = 0; p < 2; ++p) {
#pragma unroll
            for (int kt = 0; kt < 4; ++kt) {
                unsigned af0[4], af1[4];
                if (p == 1) {
                    af0[0] = ulo[0][0][2 * kt]; af0[1] = ulo[0][1][2 * kt];
                    af0[2] = ulo[0][0][2 * kt + 1]; af0[3] = ulo[0][1][2 * kt + 1];
                    af1[0] = ulo[1][0][2 * kt]; af1[1] = ulo[1][1][2 * kt];
                    af1[2] = ulo[1][0][2 * kt + 1]; af1[3] = ulo[1][1][2 * kt + 1];
                } else {
                    af0[0] = uh[0][0][2 * kt]; af0[1] = uh[0][1][2 * kt];
                    af0[2] = uh[0][0][2 * kt + 1]; af0[3] = uh[0][1][2 * kt + 1];
                    af1[0] = uh[1][0][2 * kt]; af1[1] = uh[1][1][2 * kt];
                    af1[2] = uh[1][0][2 * kt + 1]; af1[3] = uh[1][1][2 * kt + 1];
                }
#pragma unroll
                for (int q = 0; q < 4; ++q) {
                    unsigned b[4];
                    ldsm4(b, b2B + q * 2304u + kt * 32u);
                    mma16816(acc2[0][2 * q],     af0, b[0], b[1]);
                    mma16816(acc2[0][2 * q + 1], af0, b[2], b[3]);
                    mma16816(acc2[1][2 * q],     af1, b[0], b[1]);
                    mma16816(acc2[1][2 * q + 1], af1, b[2], b[3]);
                }
            }
        }

        // ===== epilogue2: LayerNorm (shuffles) + scatter (red.v4) =====
        float mArr[2][2], rsArr[2][2];
#pragma unroll
        for (int mt = 0; mt < 2; ++mt)
#pragma unroll
            for (int h = 0; h < 2; ++h) {
                float s = 0.f, ssum = 0.f;
#pragma unroll
                for (int nt = 0; nt < 8; ++nt) {
                    float v0 = acc2[mt][nt][2 * h], v1 = acc2[mt][nt][2 * h + 1];
                    s += v0 + v1; ssum += v0 * v0 + v1 * v1;
                }
                s    += __shfl_xor_sync(0xffffffffu, s, 1);
                ssum += __shfl_xor_sync(0xffffffffu, ssum, 1);
                s    += __shfl_xor_sync(0xffffffffu, s, 2);
                ssum += __shfl_xor_sync(0xffffffffu, ssum, 2);
                float m = s * (1.f / 64.f);
                mArr[mt][h]  = m;
                rsArr[mt][h] = rsqrtf(ssum * (1.f / 64.f) - m * m + 1e-5f);
            }
        const int cq = (tig & 1) * 2 + (tig >> 1);
        float4 gq[4], beq[4];
#pragma unroll
        for (int j = 0; j < 4; ++j) {
            gq[j]  = ((const float4*)(sm + OFF_G))[4 * j + cq];
            beq[j] = ((const float4*)(sm + OFF_BE))[4 * j + cq];
        }
        const unsigned colb = (unsigned)((tig & 1) * 8 + (tig >> 1) * 4);
#pragma unroll
        for (int mt = 0; mt < 2; ++mt)
#pragma unroll
            for (int h = 0; h < 2; ++h) {
                int row = warp * 32 + mt * 16 + h * 8 + gID;
                float* ag = g_agg + (ull)sdst[row] * 64 + colb;
                float m = mArr[mt][h], rs = rsArr[mt][h];
#pragma unroll
                for (int j = 0; j < 4; ++j) {
                    ull p0 = pack2(acc2[mt][2 * j][2 * h],     acc2[mt][2 * j][2 * h + 1]);
                    ull p1 = pack2(acc2[mt][2 * j + 1][2 * h], acc2[mt][2 * j + 1][2 * h + 1]);
                    ull sel = (tig & 1) ? p0 : p1;
                    ull rv = __shfl_xor_sync(0xffffffffu, sel, 1);
                    float q0, q1, q2, q3;
                    if (tig & 1) { unpack2(rv, q0, q1); unpack2(p1, q2, q3); }
                    else         { unpack2(p0, q0, q1); unpack2(rv, q2, q3); }
                    float o0 = (q0 - m) * rs * gq[j].x + beq[j].x;
                    float o1 = (q1 - m) * rs * gq[j].y + beq[j].y;
                    float o2 = (q2 - m) * rs * gq[j].z + beq[j].z;
                    float o3 = (q3 - m) * rs * gq[j].w + beq[j].w;
                    red_add4(ag + 16 * j, o0, o1, o2, o3);
                }
            }
    }
}

// ---------------- node MLP (fp32 register-tiled; also writes fp16 g_hs) ----------------
#define FMA16(AA, AB, W0, W1, W2, W3, ACC)                               \
    do {                                                                 \
        ACC[0][0]=fma2(AA.x,W0,ACC[0][0]); ACC[0][1]=fma2(AA.x,W1,ACC[0][1]); \
        ACC[0][2]=fma2(AA.x,W2,ACC[0][2]); ACC[0][3]=fma2(AA.x,W3,ACC[0][3]); \
        ACC[1][0]=fma2(AA.y,W0,ACC[1][0]); ACC[1][1]=fma2(AA.y,W1,ACC[1][1]); \
        ACC[1][2]=fma2(AA.y,W2,ACC[1][2]); ACC[1][3]=fma2(AA.y,W3,ACC[1][3]); \
        ACC[2][0]=fma2(AB.x,W0,ACC[2][0]); ACC[2][1]=fma2(AB.x,W1,ACC[2][1]); \
        ACC[2][2]=fma2(AB.x,W2,ACC[2][2]); ACC[2][3]=fma2(AB.x,W3,ACC[2][3]); \
        ACC[3][0]=fma2(AB.y,W0,ACC[3][0]); ACC[3][1]=fma2(AB.y,W1,ACC[3][1]); \
        ACC[3][2]=fma2(AB.y,W2,ACC[3][2]); ACC[3][3]=fma2(AB.y,W3,ACC[3][3]); \
    } while (0)

__global__ void __launch_bounds__(256, 2) node2_kernel(
    const float* __restrict__ W1, const float* __restrict__ b1,
    const float* __restrict__ W2, const float* __restrict__ b2,
    const float* __restrict__ gam, const float* __restrict__ bet)
{
    extern __shared__ float smem[];
    float* sW1 = smem;
    float* sW2 = sW1 + 8192;
    float* sg  = sW2 + 4096;
    float* sbe = sg + 64;
    float* buf = sbe + 64;

    const int tid = threadIdx.x;
    for (int i = tid; i < 8192; i += 256) sW1[i] = W1[i];
    for (int i = tid; i < 4096; i += 256) sW2[i] = W2[i];
    if (tid < 64) { sg[tid] = gam[tid]; sbe[tid] = bet[tid]; }

    const int n0 = blockIdx.x * 128;
    const int tn = tid & 15, tm = tid >> 4;
    const int eg_ = tid & 127;
    const int kq  = (tid >> 7) * 4;

    ull acc[4][4];
    {
        float4 bv = *(const float4*)(b1 + tn * 4);
#pragma unroll
        for (int ep = 0; ep < 4; ++ep) {
            acc[ep][0] = dup2(bv.x); acc[ep][1] = dup2(bv.y);
            acc[ep][2] = dup2(bv.z); acc[ep][3] = dup2(bv.w);
        }
    }

    int ngi = n0 + eg_;
    if (ngi >= NNODES) ngi = 0;

#pragma unroll
    for (int ch = 0; ch < 2; ++ch) {
        const float* srcp = (ch == 0) ? g_h : g_agg;
        const float4* hp = (const float4*)(srcp + (ull)ngi * 64);
        __syncthreads();
#pragma unroll
        for (int r = 0; r < 8; ++r) {
            int k = r * 8 + kq;
            float4 v = hp[2 * r + (kq >> 2)];
            buf[(k + 0) * 128 + eg_] = v.x;
            buf[(k + 1) * 128 + eg_] = v.y;
            buf[(k + 2) * 128 + eg_] = v.z;
            buf[(k + 3) * 128 + eg_] = v.w;
        }
        __syncthreads();
        const float* wbase = sW1 + ch * 64 * 64;
#pragma unroll 2
        for (int k = 0; k < 64; ++k) {
            const ulonglong2* ar = (const ulonglong2*)(buf + k * 128 + tm * 8);
            ulonglong2 aA = ar[0], aB = ar[1];
            float4 wv = *(const float4*)(wbase + k * 64 + tn * 4);
            ull w0 = dup2(wv.x), w1 = dup2(wv.y), w2 = dup2(wv.z), w3 = dup2(wv.w);
            FMA16(aA, aB, w0, w1, w2, w3, acc);
        }
    }
    __syncthreads();

#pragma unroll
    for (int ep = 0; ep < 4; ++ep)
#pragma unroll
        for (int j = 0; j < 4; ++j) {
            float x0, x1;
            unpack2(acc[ep][j], x0, x1);
            *(ull*)(buf + (tn * 4 + j) * 132 + tm * 8 + 2 * ep) = pack2(silu_f(x0), silu_f(x1));
        }
    __syncthreads();

    ull acc2[4][4];
    {
        float4 bv = *(const float4*)(b2 + tn * 4);
#pragma unroll
        for (int ep = 0; ep < 4; ++ep) {
            acc2[ep][0] = dup2(bv.x); acc2[ep][1] = dup2(bv.y);
            acc2[ep][2] = dup2(bv.z); acc2[ep][3] = dup2(bv.w);
        }
    }
#pragma unroll 2
    for (int k = 0; k < 64; ++k) {
        const ulonglong2* ar = (const ulonglong2*)(buf + k * 132 + tm * 8);
        ulonglong2 aA = ar[0], aB = ar[1];
        float4 wv = *(const float4*)(sW2 + k * 64 + tn * 4);
        ull w0 = dup2(wv.x), w1 = dup2(wv.y), w2 = dup2(wv.z), w3 = dup2(wv.w);
        FMA16(aA, aB, w0, w1, w2, w3, acc2);
    }
    __syncthreads();

#pragma unroll
    for (int ep = 0; ep < 4; ++ep)
#pragma unroll
        for (int j = 0; j < 4; ++j) {
            float x0, x1;
            unpack2(acc2[ep][j], x0, x1);
            int e = tm * 8 + 2 * ep;
            buf[e * 66 + tn * 4 + j]       = x0;
            buf[(e + 1) * 66 + tn * 4 + j] = x1;
        }
    __syncthreads();

    if (tid < 128 && n0 + tid < NNODES) {
        const float* z = buf + tid * 66;
        float s = 0.f, ss = 0.f;
#pragma unroll 8
        for (int c = 0; c < 64; ++c) { float v = z[c]; s += v; ss += v * v; }
        float m  = s * (1.f / 64.f);
        float rs = rsqrtf(ss * (1.f / 64.f) - m * m + 1e-5f);
        float4* hp = (float4*)(g_h + (ull)(n0 + tid) * 64);
        __half* hs = g_hs + (ull)(n0 + tid) * 128;
#pragma unroll
        for (int q = 0; q < 16; ++q) {
            float4 hv = hp[q];
            hv.x += (z[4 * q + 0] - m) * rs * sg[4 * q + 0] + sbe[4 * q + 0];
            hv.y += (z[4 * q + 1] - m) * rs * sg[4 * q + 1] + sbe[4 * q + 1];
            hv.z += (z[4 * q + 2] - m) * rs * sg[4 * q + 2] + sbe[4 * q + 2];
            hv.w += (z[4 * q + 3] - m) * rs * sg[4 * q + 3] + sbe[4 * q + 3];
            hp[q] = hv;
            __half2 h01 = __float22half2_rn(make_float2(hv.x, hv.y));
            __half2 h23 = __float22half2_rn(make_float2(hv.z, hv.w));
            float2 f01 = __half22float2(h01);
            float2 f23 = __half22float2(h23);
            __half2 l01 = __float22half2_rn(make_float2(hv.x - f01.x, hv.y - f01.y));
            __half2 l23 = __float22half2_rn(make_float2(hv.z - f23.x, hv.w - f23.y));
            *(unsigned*)(hs + 4 * q)     = *(unsigned*)&h01;
            *(unsigned*)(hs + 4 * q + 2) = *(unsigned*)&h23;
            *(unsigned*)(hs + 64 + 4 * q)     = *(unsigned*)&l01;
            *(unsigned*)(hs + 64 + 4 * q + 2) = *(unsigned*)&l23;
        }
    }
}

// ---------------- local decoder ----------------
__global__ void __launch_bounds__(128) dec_local_kernel(
    const float* __restrict__ W1, const float* __restrict__ b1,
    const float* __restrict__ W2, const float* __restrict__ b2,
    float* __restrict__ out)
{
    __shared__ float sW1[64 * 64];
    __shared__ float sW2[64 * 6];
    __shared__ float sb1[64];
    __shared__ float sb2[8];
    __shared__ float sy[4][64];
    int tid = threadIdx.x;
    for (int i = tid; i < 64 * 64; i += 128) sW1[i] = W1[i];
    for (int i = tid; i < 64 * 6; i += 128) sW2[i] = W2[i];
    if (tid < 64) sb1[tid] = b1[tid];
    if (tid < 6)  sb2[tid] = b2[tid];
    __syncthreads();

    int lane = tid & 31, warp = tid >> 5;
    int j0 = lane, j1 = lane + 32;
    for (int n = blockIdx.x * 4 + warp; n < NNODES; n += gridDim.x * 4) {
        const float4* Hr = reinterpret_cast<const float4*>(g_h + n * HID);
        float a0 = sb1[j0], a1 = sb1[j1];
#pragma unroll 4
        for (int c = 0; c < 16; ++c) {
            float4 v = Hr[c];
            const float* w = sW1 + 4 * c * 64;
            a0 = fmaf(v.x, w[j0], a0);           a1 = fmaf(v.x, w[j1], a1);
            a0 = fmaf(v.y, w[64 + j0], a0);      a1 = fmaf(v.y, w[64 + j1], a1);
            a0 = fmaf(v.z, w[128 + j0], a0);     a1 = fmaf(v.z, w[128 + j1], a1);
            a0 = fmaf(v.w, w[192 + j0], a0);     a1 = fmaf(v.w, w[192 + j1], a1);
        }
        a0 = silu_f(a0); a1 = silu_f(a1);
        sy[warp][j0] = a0; sy[warp][j1] = a1;
        __syncwarp();
        if (lane < 6) {
            float o = sb2[lane];
#pragma unroll 8
            for (int k = 0; k < 64; ++k) o = fmaf(sy[warp][k], sW2[k * 6 + lane], o);
            out[n * 6 + lane] = o;
        }
        __syncwarp();
    }
}

// ---------------- pooling ----------------
__global__ void __launch_bounds__(256) pool_kernel(const int* __restrict__ batch)
{
    __shared__ float sacc[NGRAPH * HID];
    __shared__ int   scnt[NGRAPH];
    int tid = threadIdx.x;
    sacc[tid] = 0.f;
    if (tid < NGRAPH) scnt[tid] = 0;
    __syncthreads();
    int j = tid & 63;
    int r = tid >> 6;
    int base = blockIdx.x * 512;
    int end = min(base + 512, NNODES);
    for (int n = base + r; n < end; n += 4) {
        int b = batch[n];
        atomicAdd(&sacc[b * HID + j], g_h[n * HID + j]);
        if (j == 0) atomicAdd(&scnt[b], 1);
    }
    __syncthreads();
    atomicAdd(&g_pooled[tid], sacc[tid]);
    if (tid < NGRAPH) atomicAdd(&g_cnt[tid], scnt[tid]);
}

// ---------------- global decoder ----------------
__global__ void dec_global_kernel(
    const float* __restrict__ W1, const float* __restrict__ b1,
    const float* __restrict__ W2, const float* __restrict__ b2,
    float* __restrict__ out)
{
    __shared__ float sy[NGRAPH][32];
    int g = threadIdx.x >> 5;
    int lane = threadIdx.x & 31;
    float inv = 1.f / fmaxf((float)g_cnt[g], 1.f);
    float a = b1[lane];
#pragma unroll 8
    for (int k = 0; k < 64; ++k)
        a = fmaf(g_pooled[g * HID + k] * inv, W1[k * 32 + lane], a);
    a = silu_f(a);
    sy[g][lane] = a;
    __syncwarp();
    if (lane < 4) {
        float o = b2[lane];
#pragma unroll 8
        for (int k = 0; k < 32; ++k) o = fmaf(sy[g][k], W2[k * 4 + lane], o);
        out[g * 4 + lane] = o;
    }
}

// ---------------- launch ----------------
extern "C" void kernel_launch(void* const* d_in, const int* in_sizes, int n_in,
                              void* d_out, int out_size)
{
    (void)in_sizes; (void)n_in; (void)out_size;
    const float* x      = (const float*)d_in[0];
    const int*   ei     = (const int*)  d_in[1];
    const float* ea     = (const float*)d_in[2];
    const int*   batch  = (const int*)  d_in[3];
    const float* caseP  = (const float*)d_in[4];
    const float* bcP    = (const float*)d_in[5];
    const float* encW1  = (const float*)d_in[6];
    const float* encb1  = (const float*)d_in[7];
    const float* encW2  = (const float*)d_in[8];
    const float* encb2  = (const float*)d_in[9];
    const float* encg   = (const float*)d_in[10];
    const float* encbe  = (const float*)d_in[11];
    const float* eW1    = (const float*)d_in[12];
    const float* eb1    = (const float*)d_in[13];
    const float* eW2    = (const float*)d_in[14];
    const float* eb2    = (const float*)d_in[15];
    const float* egm    = (const float*)d_in[16];
    const float* ebe    = (const float*)d_in[17];
    const float* nW1    = (const float*)d_in[18];
    const float* nb1    = (const float*)d_in[19];
    const float* nW2    = (const float*)d_in[20];
    const float* nb2    = (const float*)d_in[21];
    const float* ngm    = (const float*)d_in[22];
    const float* nbe    = (const float*)d_in[23];
    const float* dlW1   = (const float*)d_in[24];
    const float* dlb1   = (const float*)d_in[25];
    const float* dlW2   = (const float*)d_in[26];
    const float* dlb2   = (const float*)d_in[27];
    const float* dgW1   = (const float*)d_in[28];
    const float* dgb1   = (const float*)d_in[29];
    const float* dgW2   = (const float*)d_in[30];
    const float* dgb2   = (const float*)d_in[31];
    float* out = (float*)d_out;

    const int NODE_SMEM = (8192 + 4096 + 128 + 8448) * 4;
    cudaFuncSetAttribute(edge8_kernel, cudaFuncAttributeMaxDynamicSharedMemorySize, EDGE_SMEM);
    cudaFuncSetAttribute(node2_kernel, cudaFuncAttributeMaxDynamicSharedMemorySize, NODE_SMEM);

    prep_weights<<<(NLAYERS * 12288 + 255) / 256, 256>>>(eW1, eW2);
    encoder_kernel<<<200, 128>>>(x, batch, caseP, bcP,
                                 encW1, encb1, encW2, encb2, encg, encbe);

    const int NODE_GRID = (NNODES + 127) / 128;

    for (int l = 0; l < NLAYERS; ++l) {
        zero_agg_kernel<<<512, 256>>>();
        edge8_kernel<<<444, 128, EDGE_SMEM>>>(
            ei, ea, l,
            eW1 + l * 133 * 64, eb1 + l * 64, eb2 + l * 64,
            egm + l * 64, ebe + l * 64);
        node2_kernel<<<NODE_GRID, 256, NODE_SMEM>>>(
            nW1 + l * 128 * 64, nb1 + l * 64,
            nW2 + l * 64 * 64,  nb2 + l * 64,
            ngm + l * 64,       nbe + l * 64);
    }

    zero_pool_kernel<<<1, 256>>>();
    dec_local_kernel<<<200, 128>>>(dlW1, dlb1, dlW2, dlb2, out);
    pool_kernel<<<(NNODES + 511) / 512, 256>>>(batch);
    dec_global_kernel<<<1, 128>>>(dgW1, dgb1, dgW2, dgb2, out + NNODES * 6);
}

// round 9
// speedup vs baseline: 1.1657x; 1.0459x over previous
#include <cuda_runtime.h>
#include <cuda_fp16.h>

typedef unsigned long long ull;

#define NNODES 50000
#define NEDGES 1600000
#define NGRAPH 4
#define HID    64
#define NLAYERS 5
#define NTILES (NEDGES / 128)   // 12500

// ---------------- device scratch ----------------
__device__ float g_h[NNODES * HID];
__device__ __align__(16) __half g_hs[NNODES * 128];   // per node: 64 fp16 hi, 64 fp16 lo
__device__ float g_agg[NNODES * HID];
__device__ float g_pooled[NGRAPH * HID];
__device__ int   g_cnt[NGRAPH];
// per-layer fp16 weights [n][k] stride-144: B1 (2 chunks x 9216) + B2 (9216) = 27648 B
__device__ __align__(16) unsigned char g_wB[NLAYERS * 27648];

// ---------------- SMEM layout (bytes) ----------------
#define OFF_AH   0u        // A hi 128 rows x 128B, SW128-swizzled (16384)
#define OFF_AL   16384u    // A lo (16384)
#define OFF_B1   32768u    // chunk0 9216, chunk1 9216
#define OFF_B2   51200u    // 9216
#define OFF_T    60416u    // W1 tail rows 128..132 fp32 [5][64] (1280)
#define OFF_BB1  61696u
#define OFF_BB2  61952u
#define OFF_G    62208u
#define OFF_BE   62464u
#define OFF_SDST 62720u    // 128 ints
#define OFF_SSRC 63232u    // 128 ints
#define OFF_SEA  63744u    // 128x5 fp32 (2560)
#define EDGE_SMEM 66304

// ---------------- generic helpers ----------------
__device__ __forceinline__ float silu_f(float x) {
    float t;
    asm("tanh.approx.f32 %0, %1;" : "=f"(t) : "f"(x * 0.5f));
    return x * 0.5f * t + x * 0.5f;
}
__device__ __forceinline__ ull fma2(ull a, ull b, ull c) {
    ull d;
    asm("fma.rn.f32x2 %0, %1, %2, %3;" : "=l"(d) : "l"(a), "l"(b), "l"(c));
    return d;
}
__device__ __forceinline__ ull pack2(float lo, float hi) {
    ull r;
    asm("mov.b64 %0, {%1, %2};" : "=l"(r) : "f"(lo), "f"(hi));
    return r;
}
__device__ __forceinline__ ull dup2(float x) {
    ull r;
    asm("mov.b64 %0, {%1, %1};" : "=l"(r) : "f"(x));
    return r;
}
__device__ __forceinline__ void unpack2(ull v, float& lo, float& hi) {
    asm("mov.b64 {%0, %1}, %2;" : "=f"(lo), "=f"(hi) : "l"(v));
}
__device__ __forceinline__ void red_add4(float* p, float a, float b, float c, float d) {
    asm volatile("red.global.add.v4.f32 [%0], {%1, %2, %3, %4};"
                 :: "l"(p), "f"(a), "f"(b), "f"(c), "f"(d) : "memory");
}
__device__ __forceinline__ unsigned smem_u32(const void* p) {
    unsigned a;
    asm("{ .reg .u64 t; cvta.to.shared.u64 t, %1; cvt.u32.u64 %0, t; }" : "=r"(a) : "l"(p));
    return a;
}

// ---------------- mma.sync helpers (fp16 in, fp32 accum) ----------------
__device__ __forceinline__ void ldsm4(unsigned* r, unsigned addr) {
    asm volatile("ldmatrix.sync.aligned.m8n8.x4.shared.b16 {%0,%1,%2,%3}, [%4];"
                 : "=r"(r[0]), "=r"(r[1]), "=r"(r[2]), "=r"(r[3]) : "r"(addr));
}
__device__ __forceinline__ void mma16816(float* c, const unsigned* a, unsigned b0, unsigned b1) {
    asm volatile("mma.sync.aligned.m16n8k16.row.col.f32.f16.f16.f32 "
                 "{%0,%1,%2,%3}, {%4,%5,%6,%7}, {%8,%9}, {%0,%1,%2,%3};"
                 : "+f"(c[0]), "+f"(c[1]), "+f"(c[2]), "+f"(c[3])
                 : "r"(a[0]), "r"(a[1]), "r"(a[2]), "r"(a[3]), "r"(b0), "r"(b1));
}

// ---------------- zero kernels ----------------
__global__ void zero_agg_kernel() {
    int i = blockIdx.x * blockDim.x + threadIdx.x;
    for (; i < NNODES * HID; i += gridDim.x * blockDim.x) g_agg[i] = 0.f;
}
__global__ void zero_pool_kernel() {
    int t = threadIdx.x;
    if (t < NGRAPH * HID) g_pooled[t] = 0.f;
    if (t < NGRAPH) g_cnt[t] = 0;
}

// ---------------- weight prep: fp32 -> fp16, padded [n][k] ----------------
__global__ void prep_weights(const float* __restrict__ eW1, const float* __restrict__ eW2) {
    int idx = blockIdx.x * blockDim.x + threadIdx.x;
    if (idx >= NLAYERS * 12288) return;
    int l = idx / 12288, r = idx % 12288;
    unsigned char* base = g_wB + l * 27648;
    float w;
    unsigned off;
    if (r < 8192) {                        // B1 chunks (k rows 0..127 of W1)
        int c = r >> 12, rr = r & 4095, n = rr >> 6, kk = rr & 63;
        w = eW1[l * 133 * 64 + (c * 64 + kk) * 64 + n];
        off = (unsigned)(c * 9216 + n * 144 + kk * 2);
    } else {                               // B2
        int rr = r - 8192, n = rr >> 6, kk = rr & 63;
        w = eW2[l * 4096 + kk * 64 + n];
        off = (unsigned)(18432 + n * 144 + kk * 2);
    }
    *(__half*)(base + off) = __float2half_rn(w);
}

// ---------------- encoder (also writes split-fp16 g_hs) ----------------
__global__ void __launch_bounds__(128) encoder_kernel(
    const float* __restrict__ x, const int* __restrict__ batch,
    const float* __restrict__ caseP, const float* __restrict__ bcP,
    const float* __restrict__ W1, const float* __restrict__ b1,
    const float* __restrict__ W2, const float* __restrict__ b2,
    const float* __restrict__ gam, const float* __restrict__ bet)
{
    __shared__ float sW1[16 * 64];
    __shared__ float sW2[64 * 64];
    __shared__ float sb1[64], sb2[64], sg[64], sbe[64];
    __shared__ float sy[4][64];
    int tid = threadIdx.x;
    for (int i = tid; i < 16 * 64; i += 128) sW1[i] = W1[i];
    for (int i = tid; i < 64 * 64; i += 128) sW2[i] = W2[i];
    if (tid < 64) { sb1[tid] = b1[tid]; sb2[tid] = b2[tid]; sg[tid] = gam[tid]; sbe[tid] = bet[tid]; }
    __syncthreads();

    int lane = tid & 31, warp = tid >> 5;
    int j0 = lane, j1 = lane + 32;
    for (int n = blockIdx.x * 4 + warp; n < NNODES; n += gridDim.x * 4) {
        float in[16];
        const float* xr = x + n * 8;
#pragma unroll
        for (int k = 0; k < 8; ++k) in[k] = xr[k];
        int b = batch[n];
#pragma unroll
        for (int k = 0; k < 4; ++k) in[8 + k]  = caseP[b * 4 + k];
#pragma unroll
        for (int k = 0; k < 4; ++k) in[12 + k] = bcP[b * 4 + k];

        float a0 = sb1[j0], a1 = sb1[j1];
#pragma unroll
        for (int k = 0; k < 16; ++k) {
            a0 = fmaf(in[k], sW1[k * 64 + j0], a0);
            a1 = fmaf(in[k], sW1[k * 64 + j1], a1);
        }
        a0 = silu_f(a0); a1 = silu_f(a1);
        sy[warp][j0] = a0; sy[warp][j1] = a1;
        __syncwarp();
        float z0 = sb2[j0], z1 = sb2[j1];
#pragma unroll 4
        for (int k = 0; k < 64; ++k) {
            float v = sy[warp][k];
            z0 = fmaf(v, sW2[k * 64 + j0], z0);
            z1 = fmaf(v, sW2[k * 64 + j1], z1);
        }
        float s = z0 + z1, ss = z0 * z0 + z1 * z1;
#pragma unroll
        for (int o = 16; o > 0; o >>= 1) {
            s  += __shfl_xor_sync(0xffffffffu, s, o);
            ss += __shfl_xor_sync(0xffffffffu, ss, o);
        }
        float m = s * (1.f / 64.f);
        float rs = rsqrtf(ss * (1.f / 64.f) - m * m + 1e-5f);
        float v0 = (z0 - m) * rs * sg[j0] + sbe[j0];
        float v1 = (z1 - m) * rs * sg[j1] + sbe[j1];
        g_h[n * HID + j0] = v0;
        g_h[n * HID + j1] = v1;
        __half h0 = __float2half_rn(v0);
        __half h1 = __float2half_rn(v1);
        g_hs[n * 128 + j0] = h0;
        g_hs[n * 128 + j1] = h1;
        g_hs[n * 128 + 64 + j0] = __float2half_rn(v0 - __half2float(h0));
        g_hs[n * 128 + 64 + j1] = __float2half_rn(v1 - __half2float(h1));
        __syncwarp();
    }
}

// ---------------- edge MLP v9: coalesced gather + B reuse + swizzled A ----------------
__global__ void __launch_bounds__(128, 3) edge9_kernel(
    const int* __restrict__ ei, const float* __restrict__ ea, int layer,
    const float* __restrict__ W1full, const float* __restrict__ b1,
    const float* __restrict__ b2,
    const float* __restrict__ gam, const float* __restrict__ bet)
{
    extern __shared__ unsigned char sm[];
    const unsigned sbase = smem_u32(sm);
    const int tid = threadIdx.x;
    const int lane = tid & 31, warp = tid >> 5;
    const int gID = lane >> 2, tig = lane & 3;
    const int lt = lane >> 3, lr = lane & 7;

    // --- one-time loads ---
    {
        const uint4* srcw = (const uint4*)(g_wB + layer * 27648);
        uint4* dstw = (uint4*)(sm + OFF_B1);
#pragma unroll 4
        for (int i = tid; i < 1728; i += 128) dstw[i] = srcw[i];
    }
    for (int i = tid; i < 320; i += 128) ((float*)(sm + OFF_T))[i] = W1full[128 * 64 + i];
    if (tid < 64) {
        ((float*)(sm + OFF_BB1))[tid] = b1[tid];
        ((float*)(sm + OFF_BB2))[tid] = b2[tid];
        ((float*)(sm + OFF_G))[tid]   = gam[tid];
        ((float*)(sm + OFF_BE))[tid]  = bet[tid];
    }
    __syncthreads();

    // A ldsm addressing (SW128-swizzled, 128B rows):
    // logical row (within tile) = warp*32 + mt*16 + (lt&1)*8 + lr; col16 = (lt>>1)*16
    const unsigned aOff = (unsigned)((warp * 32 + (lt & 1) * 8 + lr) * 128
                                     + ((unsigned)((lt >> 1) << 4) ^ ((unsigned)lr << 4)));
    // B ldsm addressing (144-stride padded, conflict-free)
    const unsigned bLane = (unsigned)(((lt >> 1) * 8 + lr) * 144 + ((lt & 1) << 4));
    const float* bb1 = (const float*)(sm + OFF_BB1);
    int* sdst = (int*)(sm + OFF_SDST);
    int* ssrc = (int*)(sm + OFF_SSRC);
    float* sea = (float*)(sm + OFF_SEA);

    // gather lane mapping: lanes 0-15 -> row rbase, lanes 16-31 -> rbase+1
    const int grow = warp * 32 + (lane >> 4);
    const int cp = lane & 15;                       // 16B chunk within 256B node row
    const unsigned gcolb = (unsigned)((cp & 7) * 16);
    unsigned char* gabuf = sm + ((cp < 8) ? OFF_AH : OFF_AL);

    for (int t = blockIdx.x; t < NTILES; t += gridDim.x) {
        __syncthreads();   // previous tile fully done with smem tables
        const int e0 = t * 128;
        sdst[tid] = ei[NEDGES + e0 + tid];
        ssrc[tid] = ei[e0 + tid];
        for (int i = tid; i < 640; i += 128) sea[i] = ea[(ull)e0 * 5 + i];
        __syncwarp();

        // acc init with b1 (C-frag layout: cols 8nt+2tig)
        float acc[2][8][4];
#pragma unroll
        for (int nt = 0; nt < 8; ++nt) {
            float2 bv = *(const float2*)(bb1 + nt * 8 + 2 * tig);
#pragma unroll
            for (int mt = 0; mt < 2; ++mt) {
                acc[mt][nt][0] = bv.x; acc[mt][nt][1] = bv.y;
                acc[mt][nt][2] = bv.x; acc[mt][nt][3] = bv.y;
            }
        }

        // ===== GEMM1: chunk0 = h[dst], chunk1 = h[src] =====
#pragma unroll 1
        for (int c = 0; c < 2; ++c) {
            // coalesced gather: 2 rows per instruction, 16 lanes per row
            const int* idxp = (c == 0) ? sdst : ssrc;
#pragma unroll
            for (int i = 0; i < 16; ++i) {
                int row = grow + 2 * i;
                int node = idxp[row];
                uint4 v = *(const uint4*)((const unsigned char*)g_hs + (ull)node * 256 + cp * 16);
                *(uint4*)(gabuf + row * 128 + (gcolb ^ (((unsigned)row & 7u) << 4))) = v;
            }
            __syncthreads();

            const unsigned bB = sbase + OFF_B1 + (unsigned)c * 9216u + bLane;
#pragma unroll
            for (int kt = 0; kt < 4; ++kt) {
                const unsigned kx = (unsigned)(kt * 32);
                unsigned ah0[4], ah1[4], al0[4], al1[4];
                ldsm4(ah0, sbase + OFF_AH + (aOff ^ kx));
                ldsm4(ah1, sbase + OFF_AH + ((aOff + 2048u) ^ kx));
                ldsm4(al0, sbase + OFF_AL + (aOff ^ kx));
                ldsm4(al1, sbase + OFF_AL + ((aOff + 2048u) ^ kx));
                unsigned bf[4][4];
#pragma unroll
                for (int q = 0; q < 4; ++q) ldsm4(bf[q], bB + q * 2304u + kx);
#pragma unroll
                for (int q = 0; q < 4; ++q) {
                    mma16816(acc[0][2 * q],     ah0, bf[q][0], bf[q][1]);
                    mma16816(acc[0][2 * q + 1], ah0, bf[q][2], bf[q][3]);
                    mma16816(acc[1][2 * q],     ah1, bf[q][0], bf[q][1]);
                    mma16816(acc[1][2 * q + 1], ah1, bf[q][2], bf[q][3]);
                }
#pragma unroll
                for (int q = 0; q < 4; ++q) {
                    mma16816(acc[0][2 * q],     al0, bf[q][0], bf[q][1]);
                    mma16816(acc[0][2 * q + 1], al0, bf[q][2], bf[q][3]);
                    mma16816(acc[1][2 * q],     al1, bf[q][0], bf[q][1]);
                    mma16816(acc[1][2 * q + 1], al1, bf[q][2], bf[q][3]);
                }
            }
            if (c == 0) __syncthreads();   // before chunk1 gather overwrites A
        }

        // ===== epilogue1 (registers): fp32 edge_attr tail + silu + fp16 split =====
        float eav[2][2][5];
#pragma unroll
        for (int mt = 0; mt < 2; ++mt)
#pragma unroll
            for (int h = 0; h < 2; ++h) {
                const float* er = sea + (warp * 32 + mt * 16 + h * 8 + gID) * 5;
#pragma unroll
                for (int j = 0; j < 5; ++j) eav[mt][h][j] = er[j];
            }
        unsigned uh[2][2][8], ulo[2][2][8];
#pragma unroll
        for (int nt = 0; nt < 8; ++nt) {
            float2 w[5];
#pragma unroll
            for (int j = 0; j < 5; ++j)
                w[j] = *(const float2*)(sm + OFF_T + (unsigned)((j * 64 + nt * 8 + tig * 2) * 4));
#pragma unroll
            for (int mt = 0; mt < 2; ++mt)
#pragma unroll
                for (int h = 0; h < 2; ++h) {
                    float y0 = acc[mt][nt][2 * h], y1 = acc[mt][nt][2 * h + 1];
#pragma unroll
                    for (int j = 0; j < 5; ++j) {
                        y0 = fmaf(eav[mt][h][j], w[j].x, y0);
                        y1 = fmaf(eav[mt][h][j], w[j].y, y1);
                    }
                    y0 = silu_f(y0); y1 = silu_f(y1);
                    __half2 hb = __float22half2_rn(make_float2(y0, y1));
                    float2 f = __half22float2(hb);
                    __half2 lb = __float22half2_rn(make_float2(y0 - f.x, y1 - f.y));
                    uh[mt][h][nt]  = *(unsigned*)&hb;
                    ulo[mt][h][nt] = *(unsigned*)&lb;
                }
        }

        // ===== GEMM2 (A from registers, B frags reused for hi+lo) =====
        float acc2[2][8][4];
#pragma unroll
        for (int nt = 0; nt < 8; ++nt) {
            float2 bv = *(const float2*)(sm + OFF_BB2 + (unsigned)((nt * 8 + tig * 2) * 4));
#pragma unroll
            for (int mt = 0; mt < 2; ++mt) {
                acc2[mt][nt][0] = bv.x; acc2[mt][nt][1] = bv.y;
                acc2[mt][nt][2] = bv.x; acc2[mt][nt][3] = bv.y;
            }
        }
        const unsigned b2B = sbase + OFF_B2 + bLane;
#pragma unroll
        for (int kt = 0; kt < 4; ++kt) {
            unsigned bf[4][4];
#pragma unroll
            for (int q = 0; q < 4; ++q) ldsm4(bf[q], b2B + q * 2304u + kt * 32u);
            unsigned ah0[4] = {uh[0][0][2 * kt], uh[0][1][2 * kt], uh[0][0][2 * kt + 1], uh[0][1][2 * kt + 1]};
            unsigned ah1[4] = {uh[1][0][2 * kt], uh[1][1][2 * kt], uh[1][0][2 * kt + 1], uh[1][1][2 * kt + 1]};
            unsigned al0[4] = {ulo[0][0][2 * kt], ulo[0][1][2 * kt], ulo[0][0][2 * kt + 1], ulo[0][1][2 * kt + 1]};
            unsigned al1[4] = {ulo[1][0][2 * kt], ulo[1][1][2 * kt], ulo[1][0][2 * kt + 1], ulo[1][1][2 * kt + 1]};
#pragma unroll
            for (int q = 0; q < 4; ++q) {
                mma16816(acc2[0][2 * q],     ah0, bf[q][0], bf[q][1]);
                mma16816(acc2[0][2 * q + 1], ah0, bf[q][2], bf[q][3]);
                mma16816(acc2[1][2 * q],     ah1, bf[q][0], bf[q][1]);
                mma16816(acc2[1][2 * q + 1], ah1, bf[q][2], bf[q][3]);
            }
#pragma unroll
            for (int q = 0; q < 4; ++q) {
                mma16816(acc2[0][2 * q],     al0, bf[q][0], bf[q][1]);
                mma16816(acc2[0][2 * q + 1], al0, bf[q][2], bf[q][3]);
                mma16816(acc2[1][2 * q],     al1, bf[q][0], bf[q][1]);
                mma16816(acc2[1][2 * q + 1], al1, bf[q][2], bf[q][3]);
            }
        }

        // ===== epilogue2: LayerNorm (shuffles) + scatter (red.v4) =====
        float mArr[2][2], rsArr[2][2];
#pragma unroll
        for (int mt = 0; mt < 2; ++mt)
#pragma unroll
            for (int h = 0; h < 2; ++h) {
                float s = 0.f, ssum = 0.f;
#pragma unroll
                for (int nt = 0; nt < 8; ++nt) {
                    float v0 = acc2[mt][nt][2 * h], v1 = acc2[mt][nt][2 * h + 1];
                    s += v0 + v1; ssum += v0 * v0 + v1 * v1;
                }
                s    += __shfl_xor_sync(0xffffffffu, s, 1);
                ssum += __shfl_xor_sync(0xffffffffu, ssum, 1);
                s    += __shfl_xor_sync(0xffffffffu, s, 2);
                ssum += __shfl_xor_sync(0xffffffffu, ssum, 2);
                float m = s * (1.f / 64.f);
                mArr[mt][h]  = m;
                rsArr[mt][h] = rsqrtf(ssum * (1.f / 64.f) - m * m + 1e-5f);
            }
        const int cq = (tig & 1) * 2 + (tig >> 1);
        float4 gq[4], beq[4];
#pragma unroll
        for (int j = 0; j < 4; ++j) {
            gq[j]  = ((const float4*)(sm + OFF_G))[4 * j + cq];
            beq[j] = ((const float4*)(sm + OFF_BE))[4 * j + cq];
        }
        const unsigned colb = (unsigned)((tig & 1) * 8 + (tig >> 1) * 4);
#pragma unroll
        for (int mt = 0; mt < 2; ++mt)
#pragma unroll
            for (int h = 0; h < 2; ++h) {
                int row = warp * 32 + mt * 16 + h * 8 + gID;
                float* ag = g_agg + (ull)sdst[row] * 64 + colb;
                float m = mArr[mt][h], rs = rsArr[mt][h];
#pragma unroll
                for (int j = 0; j < 4; ++j) {
                    ull p0 = pack2(acc2[mt][2 * j][2 * h],     acc2[mt][2 * j][2 * h + 1]);
                    ull p1 = pack2(acc2[mt][2 * j + 1][2 * h], acc2[mt][2 * j + 1][2 * h + 1]);
                    ull sel = (tig & 1) ? p0 : p1;
                    ull rv = __shfl_xor_sync(0xffffffffu, sel, 1);
                    float q0, q1, q2, q3;
                    if (tig & 1) { unpack2(rv, q0, q1); unpack2(p1, q2, q3); }
                    else         { unpack2(p0, q0, q1); unpack2(rv, q2, q3); }
                    float o0 = (q0 - m) * rs * gq[j].x + beq[j].x;
                    float o1 = (q1 - m) * rs * gq[j].y + beq[j].y;
                    float o2 = (q2 - m) * rs * gq[j].z + beq[j].z;
                    float o3 = (q3 - m) * rs * gq[j].w + beq[j].w;
                    red_add4(ag + 16 * j, o0, o1, o2, o3);
                }
            }
    }
}

// ---------------- node MLP (fp32 register-tiled; also writes fp16 g_hs) ----------------
#define FMA16(AA, AB, W0, W1, W2, W3, ACC)                               \
    do {                                                                 \
        ACC[0][0]=fma2(AA.x,W0,ACC[0][0]); ACC[0][1]=fma2(AA.x,W1,ACC[0][1]); \
        ACC[0][2]=fma2(AA.x,W2,ACC[0][2]); ACC[0][3]=fma2(AA.x,W3,ACC[0][3]); \
        ACC[1][0]=fma2(AA.y,W0,ACC[1][0]); ACC[1][1]=fma2(AA.y,W1,ACC[1][1]); \
        ACC[1][2]=fma2(AA.y,W2,ACC[1][2]); ACC[1][3]=fma2(AA.y,W3,ACC[1][3]); \
        ACC[2][0]=fma2(AB.x,W0,ACC[2][0]); ACC[2][1]=fma2(AB.x,W1,ACC[2][1]); \
        ACC[2][2]=fma2(AB.x,W2,ACC[2][2]); ACC[2][3]=fma2(AB.x,W3,ACC[2][3]); \
        ACC[3][0]=fma2(AB.y,W0,ACC[3][0]); ACC[3][1]=fma2(AB.y,W1,ACC[3][1]); \
        ACC[3][2]=fma2(AB.y,W2,ACC[3][2]); ACC[3][3]=fma2(AB.y,W3,ACC[3][3]); \
    } while (0)

__global__ void __launch_bounds__(256, 2) node2_kernel(
    const float* __restrict__ W1, const float* __restrict__ b1,
    const float* __restrict__ W2, const float* __restrict__ b2,
    const float* __restrict__ gam, const float* __restrict__ bet)
{
    extern __shared__ float smem[];
    float* sW1 = smem;
    float* sW2 = sW1 + 8192;
    float* sg  = sW2 + 4096;
    float* sbe = sg + 64;
    float* buf = sbe + 64;

    const int tid = threadIdx.x;
    for (int i = tid; i < 8192; i += 256) sW1[i] = W1[i];
    for (int i = tid; i < 4096; i += 256) sW2[i] = W2[i];
    if (tid < 64) { sg[tid] = gam[tid]; sbe[tid] = bet[tid]; }

    const int n0 = blockIdx.x * 128;
    const int tn = tid & 15, tm = tid >> 4;
    const int eg_ = tid & 127;
    const int kq  = (tid >> 7) * 4;

    ull acc[4][4];
    {
        float4 bv = *(const float4*)(b1 + tn * 4);
#pragma unroll
        for (int ep = 0; ep < 4; ++ep) {
            acc[ep][0] = dup2(bv.x); acc[ep][1] = dup2(bv.y);
            acc[ep][2] = dup2(bv.z); acc[ep][3] = dup2(bv.w);
        }
    }

    int ngi = n0 + eg_;
    if (ngi >= NNODES) ngi = 0;

#pragma unroll
    for (int ch = 0; ch < 2; ++ch) {
        const float* srcp = (ch == 0) ? g_h : g_agg;
        const float4* hp = (const float4*)(srcp + (ull)ngi * 64);
        __syncthreads();
#pragma unroll
        for (int r = 0; r < 8; ++r) {
            int k = r * 8 + kq;
            float4 v = hp[2 * r + (kq >> 2)];
            buf[(k + 0) * 128 + eg_] = v.x;
            buf[(k + 1) * 128 + eg_] = v.y;
            buf[(k + 2) * 128 + eg_] = v.z;
            buf[(k + 3) * 128 + eg_] = v.w;
        }
        __syncthreads();
        const float* wbase = sW1 + ch * 64 * 64;
#pragma unroll 2
        for (int k = 0; k < 64; ++k) {
            const ulonglong2* ar = (const ulonglong2*)(buf + k * 128 + tm * 8);
            ulonglong2 aA = ar[0], aB = ar[1];
            float4 wv = *(const float4*)(wbase + k * 64 + tn * 4);
            ull w0 = dup2(wv.x), w1 = dup2(wv.y), w2 = dup2(wv.z), w3 = dup2(wv.w);
            FMA16(aA, aB, w0, w1, w2, w3, acc);
        }
    }
    __syncthreads();

#pragma unroll
    for (int ep = 0; ep < 4; ++ep)
#pragma unroll
        for (int j = 0; j < 4; ++j) {
            float x0, x1;
            unpack2(acc[ep][j], x0, x1);
            *(ull*)(buf + (tn * 4 + j) * 132 + tm * 8 + 2 * ep) = pack2(silu_f(x0), silu_f(x1));
        }
    __syncthreads();

    ull acc2[4][4];
    {
        float4 bv = *(const float4*)(b2 + tn * 4);
#pragma unroll
        for (int ep = 0; ep < 4; ++ep) {
            acc2[ep][0] = dup2(bv.x); acc2[ep][1] = dup2(bv.y);
            acc2[ep][2] = dup2(bv.z); acc2[ep][3] = dup2(bv.w);
        }
    }
#pragma unroll 2
    for (int k = 0; k < 64; ++k) {
        const ulonglong2* ar = (const ulonglong2*)(buf + k * 132 + tm * 8);
        ulonglong2 aA = ar[0], aB = ar[1];
        float4 wv = *(const float4*)(sW2 + k * 64 + tn * 4);
        ull w0 = dup2(wv.x), w1 = dup2(wv.y), w2 = dup2(wv.z), w3 = dup2(wv.w);
        FMA16(aA, aB, w0, w1, w2, w3, acc2);
    }
    __syncthreads();

#pragma unroll
    for (int ep = 0; ep < 4; ++ep)
#pragma unroll
        for (int j = 0; j < 4; ++j) {
            float x0, x1;
            unpack2(acc2[ep][j], x0, x1);
            int e = tm * 8 + 2 * ep;
            buf[e * 66 + tn * 4 + j]       = x0;
            buf[(e + 1) * 66 + tn * 4 + j] = x1;
        }
    __syncthreads();

    if (tid < 128 && n0 + tid < NNODES) {
        const float* z = buf + tid * 66;
        float s = 0.f, ss = 0.f;
#pragma unroll 8
        for (int c = 0; c < 64; ++c) { float v = z[c]; s += v; ss += v * v; }
        float m  = s * (1.f / 64.f);
        float rs = rsqrtf(ss * (1.f / 64.f) - m * m + 1e-5f);
        float4* hp = (float4*)(g_h + (ull)(n0 + tid) * 64);
        __half* hs = g_hs + (ull)(n0 + tid) * 128;
#pragma unroll
        for (int q = 0; q < 16; ++q) {
            float4 hv = hp[q];
            hv.x += (z[4 * q + 0] - m) * rs * sg[4 * q + 0] + sbe[4 * q + 0];
            hv.y += (z[4 * q + 1] - m) * rs * sg[4 * q + 1] + sbe[4 * q + 1];
            hv.z += (z[4 * q + 2] - m) * rs * sg[4 * q + 2] + sbe[4 * q + 2];
            hv.w += (z[4 * q + 3] - m) * rs * sg[4 * q + 3] + sbe[4 * q + 3];
            hp[q] = hv;
            __half2 h01 = __float22half2_rn(make_float2(hv.x, hv.y));
            __half2 h23 = __float22half2_rn(make_float2(hv.z, hv.w));
            float2 f01 = __half22float2(h01);
            float2 f23 = __half22float2(h23);
            __half2 l01 = __float22half2_rn(make_float2(hv.x - f01.x, hv.y - f01.y));
            __half2 l23 = __float22half2_rn(make_float2(hv.z - f23.x, hv.w - f23.y));
            *(unsigned*)(hs + 4 * q)     = *(unsigned*)&h01;
            *(unsigned*)(hs + 4 * q + 2) = *(unsigned*)&h23;
            *(unsigned*)(hs + 64 + 4 * q)     = *(unsigned*)&l01;
            *(unsigned*)(hs + 64 + 4 * q + 2) = *(unsigned*)&l23;
        }
    }
}

// ---------------- local decoder ----------------
__global__ void __launch_bounds__(128) dec_local_kernel(
    const float* __restrict__ W1, const float* __restrict__ b1,
    const float* __restrict__ W2, const float* __restrict__ b2,
    float* __restrict__ out)
{
    __shared__ float sW1[64 * 64];
    __shared__ float sW2[64 * 6];
    __shared__ float sb1[64];
    __shared__ float sb2[8];
    __shared__ float sy[4][64];
    int tid = threadIdx.x;
    for (int i = tid; i < 64 * 64; i += 128) sW1[i] = W1[i];
    for (int i = tid; i < 64 * 6; i += 128) sW2[i] = W2[i];
    if (tid < 64) sb1[tid] = b1[tid];
    if (tid < 6)  sb2[tid] = b2[tid];
    __syncthreads();

    int lane = tid & 31, warp = tid >> 5;
    int j0 = lane, j1 = lane + 32;
    for (int n = blockIdx.x * 4 + warp; n < NNODES; n += gridDim.x * 4) {
        const float4* Hr = reinterpret_cast<const float4*>(g_h + n * HID);
        float a0 = sb1[j0], a1 = sb1[j1];
#pragma unroll 4
        for (int c = 0; c < 16; ++c) {
            float4 v = Hr[c];
            const float* w = sW1 + 4 * c * 64;
            a0 = fmaf(v.x, w[j0], a0);           a1 = fmaf(v.x, w[j1], a1);
            a0 = fmaf(v.y, w[64 + j0], a0);      a1 = fmaf(v.y, w[64 + j1], a1);
            a0 = fmaf(v.z, w[128 + j0], a0);     a1 = fmaf(v.z, w[128 + j1], a1);
            a0 = fmaf(v.w, w[192 + j0], a0);     a1 = fmaf(v.w, w[192 + j1], a1);
        }
        a0 = silu_f(a0); a1 = silu_f(a1);
        sy[warp][j0] = a0; sy[warp][j1] = a1;
        __syncwarp();
        if (lane < 6) {
            float o = sb2[lane];
#pragma unroll 8
            for (int k = 0; k < 64; ++k) o = fmaf(sy[warp][k], sW2[k * 6 + lane], o);
            out[n * 6 + lane] = o;
        }
        __syncwarp();
    }
}

// ---------------- pooling ----------------
__global__ void __launch_bounds__(256) pool_kernel(const int* __restrict__ batch)
{
    __shared__ float sacc[NGRAPH * HID];
    __shared__ int   scnt[NGRAPH];
    int tid = threadIdx.x;
    sacc[tid] = 0.f;
    if (tid < NGRAPH) scnt[tid] = 0;
    __syncthreads();
    int j = tid & 63;
    int r = tid >> 6;
    int base = blockIdx.x * 512;
    int end = min(base + 512, NNODES);
    for (int n = base + r; n < end; n += 4) {
        int b = batch[n];
        atomicAdd(&sacc[b * HID + j], g_h[n * HID + j]);
        if (j == 0) atomicAdd(&scnt[b], 1);
    }
    __syncthreads();
    atomicAdd(&g_pooled[tid], sacc[tid]);
    if (tid < NGRAPH) atomicAdd(&g_cnt[tid], scnt[tid]);
}

// ---------------- global decoder ----------------
__global__ void dec_global_kernel(
    const float* __restrict__ W1, const float* __restrict__ b1,
    const float* __restrict__ W2, const float* __restrict__ b2,
    float* __restrict__ out)
{
    __shared__ float sy[NGRAPH][32];
    int g = threadIdx.x >> 5;
    int lane = threadIdx.x & 31;
    float inv = 1.f / fmaxf((float)g_cnt[g], 1.f);
    float a = b1[lane];
#pragma unroll 8
    for (int k = 0; k < 64; ++k)
        a = fmaf(g_pooled[g * HID + k] * inv, W1[k * 32 + lane], a);
    a = silu_f(a);
    sy[g][lane] = a;
    __syncwarp();
    if (lane < 4) {
        float o = b2[lane];
#pragma unroll 8
        for (int k = 0; k < 32; ++k) o = fmaf(sy[g][k], W2[k * 4 + lane], o);
        out[g * 4 + lane] = o;
    }
}

// ---------------- launch ----------------
extern "C" void kernel_launch(void* const* d_in, const int* in_sizes, int n_in,
                              void* d_out, int out_size)
{
    (void)in_sizes; (void)n_in; (void)out_size;
    const float* x      = (const float*)d_in[0];
    const int*   ei     = (const int*)  d_in[1];
    const float* ea     = (const float*)d_in[2];
    const int*   batch  = (const int*)  d_in[3];
    const float* caseP  = (const float*)d_in[4];
    const float* bcP    = (const float*)d_in[5];
    const float* encW1  = (const float*)d_in[6];
    const float* encb1  = (const float*)d_in[7];
    const float* encW2  = (const float*)d_in[8];
    const float* encb2  = (const float*)d_in[9];
    const float* encg   = (const float*)d_in[10];
    const float* encbe  = (const float*)d_in[11];
    const float* eW1    = (const float*)d_in[12];
    const float* eb1    = (const float*)d_in[13];
    const float* eW2    = (const float*)d_in[14];
    const float* eb2    = (const float*)d_in[15];
    const float* egm    = (const float*)d_in[16];
    const float* ebe    = (const float*)d_in[17];
    const float* nW1    = (const float*)d_in[18];
    const float* nb1    = (const float*)d_in[19];
    const float* nW2    = (const float*)d_in[20];
    const float* nb2    = (const float*)d_in[21];
    const float* ngm    = (const float*)d_in[22];
    const float* nbe    = (const float*)d_in[23];
    const float* dlW1   = (const float*)d_in[24];
    const float* dlb1   = (const float*)d_in[25];
    const float* dlW2   = (const float*)d_in[26];
    const float* dlb2   = (const float*)d_in[27];
    const float* dgW1   = (const float*)d_in[28];
    const float* dgb1   = (const float*)d_in[29];
    const float* dgW2   = (const float*)d_in[30];
    const float* dgb2   = (const float*)d_in[31];
    float* out = (float*)d_out;

    const int NODE_SMEM = (8192 + 4096 + 128 + 8448) * 4;
    cudaFuncSetAttribute(edge9_kernel, cudaFuncAttributeMaxDynamicSharedMemorySize, EDGE_SMEM);
    cudaFuncSetAttribute(node2_kernel, cudaFuncAttributeMaxDynamicSharedMemorySize, NODE_SMEM);

    prep_weights<<<(NLAYERS * 12288 + 255) / 256, 256>>>(eW1, eW2);
    encoder_kernel<<<200, 128>>>(x, batch, caseP, bcP,
                                 encW1, encb1, encW2, encb2, encg, encbe);

    const int NODE_GRID = (NNODES + 127) / 128;

    for (int l = 0; l < NLAYERS; ++l) {
        zero_agg_kernel<<<512, 256>>>();
        edge9_kernel<<<444, 128, EDGE_SMEM>>>(
            ei, ea, l,
            eW1 + l * 133 * 64, eb1 + l * 64, eb2 + l * 64,
            egm + l * 64, ebe + l * 64);
        node2_kernel<<<NODE_GRID, 256, NODE_SMEM>>>(
            nW1 + l * 128 * 64, nb1 + l * 64,
            nW2 + l * 64 * 64,  nb2 + l * 64,
            ngm + l * 64,       nbe + l * 64);
    }

    zero_pool_kernel<<<1, 256>>>();
    dec_local_kernel<<<200, 128>>>(dlW1, dlb1, dlW2, dlb2, out);
    pool_kernel<<<(NNODES + 511) / 512, 256>>>(batch);
    dec_global_kernel<<<1, 128>>>(dgW1, dgb1, dgW2, dgb2, out + NNODES * 6);
}

// round 10
// speedup vs baseline: 1.5081x; 1.2938x over previous
#include <cuda_runtime.h>
#include <cuda_fp16.h>

typedef unsigned long long ull;

#define NNODES 50000
#define NEDGES 1600000
#define NGRAPH 4
#define HID    64
#define NLAYERS 5
#define NTILES (NEDGES / 128)   // 12500

// ---------------- device scratch ----------------
__device__ float g_h[NNODES * HID];
__device__ __align__(16) __half g_hs[NNODES * 128];   // per node: 64 fp16 hi, 64 fp16 lo
__device__ float g_agg[NNODES * HID];
__device__ float g_pooled[NGRAPH * HID];
__device__ int   g_cnt[NGRAPH];
// per-layer fp16 weights [n][k] stride-144: B1 (2 chunks x 9216) + B2 (9216) = 27648 B
__device__ __align__(16) unsigned char g_wB[NLAYERS * 27648];

// ---------------- SMEM layout (bytes) ----------------
#define OFF_A0H  0u        // chunk0: A hi 128x128B SW128 (16384)
#define OFF_A0L  16384u
#define OFF_A1H  32768u    // chunk1
#define OFF_A1L  49152u
#define OFF_B1   65536u    // 2 x 9216
#define OFF_B2   83968u    // 9216
#define OFF_T    93184u    // W1 tail rows 128..132 fp32 [5][64] (1280)
#define OFF_BB1  94464u
#define OFF_BB2  94720u
#define OFF_G    94976u
#define OFF_BE   95232u
#define OFF_SDST 95488u    // 2 x 128 ints (1024)
#define OFF_SEA  96512u    // 2 x 640 fp32 (5120)
#define EDGE_SMEM 101632

// ---------------- generic helpers ----------------
__device__ __forceinline__ float silu_f(float x) {
    float t;
    asm("tanh.approx.f32 %0, %1;" : "=f"(t) : "f"(x * 0.5f));
    return x * 0.5f * t + x * 0.5f;
}
__device__ __forceinline__ ull fma2(ull a, ull b, ull c) {
    ull d;
    asm("fma.rn.f32x2 %0, %1, %2, %3;" : "=l"(d) : "l"(a), "l"(b), "l"(c));
    return d;
}
__device__ __forceinline__ ull pack2(float lo, float hi) {
    ull r;
    asm("mov.b64 %0, {%1, %2};" : "=l"(r) : "f"(lo), "f"(hi));
    return r;
}
__device__ __forceinline__ ull dup2(float x) {
    ull r;
    asm("mov.b64 %0, {%1, %1};" : "=l"(r) : "f"(x));
    return r;
}
__device__ __forceinline__ void unpack2(ull v, float& lo, float& hi) {
    asm("mov.b64 {%0, %1}, %2;" : "=f"(lo), "=f"(hi) : "l"(v));
}
__device__ __forceinline__ void red_add4(float* p, float a, float b, float c, float d) {
    asm volatile("red.global.add.v4.f32 [%0], {%1, %2, %3, %4};"
                 :: "l"(p), "f"(a), "f"(b), "f"(c), "f"(d) : "memory");
}
__device__ __forceinline__ unsigned smem_u32(const void* p) {
    unsigned a;
    asm("{ .reg .u64 t; cvta.to.shared.u64 t, %1; cvt.u32.u64 %0, t; }" : "=r"(a) : "l"(p));
    return a;
}

// ---------------- cp.async helpers ----------------
__device__ __forceinline__ void cpasync16(unsigned dst, const void* src) {
    asm volatile("cp.async.cg.shared.global [%0], [%1], 16;" :: "r"(dst), "l"(src) : "memory");
}
#define CP_COMMIT() asm volatile("cp.async.commit_group;" ::: "memory")
#define CP_WAIT1()  asm volatile("cp.async.wait_group 1;" ::: "memory")
#define CP_WAIT0()  asm volatile("cp.async.wait_group 0;" ::: "memory")

// ---------------- mma.sync helpers (fp16 in, fp32 accum) ----------------
__device__ __forceinline__ void ldsm4(unsigned* r, unsigned addr) {
    asm volatile("ldmatrix.sync.aligned.m8n8.x4.shared.b16 {%0,%1,%2,%3}, [%4];"
                 : "=r"(r[0]), "=r"(r[1]), "=r"(r[2]), "=r"(r[3]) : "r"(addr));
}
__device__ __forceinline__ void mma16816(float* c, const unsigned* a, unsigned b0, unsigned b1) {
    asm volatile("mma.sync.aligned.m16n8k16.row.col.f32.f16.f16.f32 "
                 "{%0,%1,%2,%3}, {%4,%5,%6,%7}, {%8,%9}, {%0,%1,%2,%3};"
                 : "+f"(c[0]), "+f"(c[1]), "+f"(c[2]), "+f"(c[3])
                 : "r"(a[0]), "r"(a[1]), "r"(a[2]), "r"(a[3]), "r"(b0), "r"(b1));
}

// ---------------- zero kernels ----------------
__global__ void zero_agg_kernel() {
    int i = blockIdx.x * blockDim.x + threadIdx.x;
    for (; i < NNODES * HID; i += gridDim.x * blockDim.x) g_agg[i] = 0.f;
}
__global__ void zero_pool_kernel() {
    int t = threadIdx.x;
    if (t < NGRAPH * HID) g_pooled[t] = 0.f;
    if (t < NGRAPH) g_cnt[t] = 0;
}

// ---------------- weight prep: fp32 -> fp16, padded [n][k] ----------------
__global__ void prep_weights(const float* __restrict__ eW1, const float* __restrict__ eW2) {
    int idx = blockIdx.x * blockDim.x + threadIdx.x;
    if (idx >= NLAYERS * 12288) return;
    int l = idx / 12288, r = idx % 12288;
    unsigned char* base = g_wB + l * 27648;
    float w;
    unsigned off;
    if (r < 8192) {
        int c = r >> 12, rr = r & 4095, n = rr >> 6, kk = rr & 63;
        w = eW1[l * 133 * 64 + (c * 64 + kk) * 64 + n];
        off = (unsigned)(c * 9216 + n * 144 + kk * 2);
    } else {
        int rr = r - 8192, n = rr >> 6, kk = rr & 63;
        w = eW2[l * 4096 + kk * 64 + n];
        off = (unsigned)(18432 + n * 144 + kk * 2);
    }
    *(__half*)(base + off) = __float2half_rn(w);
}

// ---------------- encoder (also writes split-fp16 g_hs) ----------------
__global__ void __launch_bounds__(128) encoder_kernel(
    const float* __restrict__ x, const int* __restrict__ batch,
    const float* __restrict__ caseP, const float* __restrict__ bcP,
    const float* __restrict__ W1, const float* __restrict__ b1,
    const float* __restrict__ W2, const float* __restrict__ b2,
    const float* __restrict__ gam, const float* __restrict__ bet)
{
    __shared__ float sW1[16 * 64];
    __shared__ float sW2[64 * 64];
    __shared__ float sb1[64], sb2[64], sg[64], sbe[64];
    __shared__ float sy[4][64];
    int tid = threadIdx.x;
    for (int i = tid; i < 16 * 64; i += 128) sW1[i] = W1[i];
    for (int i = tid; i < 64 * 64; i += 128) sW2[i] = W2[i];
    if (tid < 64) { sb1[tid] = b1[tid]; sb2[tid] = b2[tid]; sg[tid] = gam[tid]; sbe[tid] = bet[tid]; }
    __syncthreads();

    int lane = tid & 31, warp = tid >> 5;
    int j0 = lane, j1 = lane + 32;
    for (int n = blockIdx.x * 4 + warp; n < NNODES; n += gridDim.x * 4) {
        float in[16];
        const float* xr = x + n * 8;
#pragma unroll
        for (int k = 0; k < 8; ++k) in[k] = xr[k];
        int b = batch[n];
#pragma unroll
        for (int k = 0; k < 4; ++k) in[8 + k]  = caseP[b * 4 + k];
#pragma unroll
        for (int k = 0; k < 4; ++k) in[12 + k] = bcP[b * 4 + k];

        float a0 = sb1[j0], a1 = sb1[j1];
#pragma unroll
        for (int k = 0; k < 16; ++k) {
            a0 = fmaf(in[k], sW1[k * 64 + j0], a0);
            a1 = fmaf(in[k], sW1[k * 64 + j1], a1);
        }
        a0 = silu_f(a0); a1 = silu_f(a1);
        sy[warp][j0] = a0; sy[warp][j1] = a1;
        __syncwarp();
        float z0 = sb2[j0], z1 = sb2[j1];
#pragma unroll 4
        for (int k = 0; k < 64; ++k) {
            float v = sy[warp][k];
            z0 = fmaf(v, sW2[k * 64 + j0], z0);
            z1 = fmaf(v, sW2[k * 64 + j1], z1);
        }
        float s = z0 + z1, ss = z0 * z0 + z1 * z1;
#pragma unroll
        for (int o = 16; o > 0; o >>= 1) {
            s  += __shfl_xor_sync(0xffffffffu, s, o);
            ss += __shfl_xor_sync(0xffffffffu, ss, o);
        }
        float m = s * (1.f / 64.f);
        float rs = rsqrtf(ss * (1.f / 64.f) - m * m + 1e-5f);
        float v0 = (z0 - m) * rs * sg[j0] + sbe[j0];
        float v1 = (z1 - m) * rs * sg[j1] + sbe[j1];
        g_h[n * HID + j0] = v0;
        g_h[n * HID + j1] = v1;
        __half h0 = __float2half_rn(v0);
        __half h1 = __float2half_rn(v1);
        g_hs[n * 128 + j0] = h0;
        g_hs[n * 128 + j1] = h1;
        g_hs[n * 128 + 64 + j0] = __float2half_rn(v0 - __half2float(h0));
        g_hs[n * 128 + 64 + j1] = __float2half_rn(v1 - __half2float(h1));
        __syncwarp();
    }
}

// ---------------- edge MLP v10: cp.async double-buffered pipeline ----------------
__global__ void __launch_bounds__(128, 2) edge10_kernel(
    const int* __restrict__ ei, const float* __restrict__ ea, int layer,
    const float* __restrict__ W1full, const float* __restrict__ b1,
    const float* __restrict__ b2,
    const float* __restrict__ gam, const float* __restrict__ bet)
{
    extern __shared__ unsigned char sm[];
    const unsigned sbase = smem_u32(sm);
    const int tid = threadIdx.x;
    const int lane = tid & 31, warp = tid >> 5;
    const int gID = lane >> 2, tig = lane & 3;
    const int lt = lane >> 3, lr = lane & 7;

    // --- one-time loads ---
    {
        const uint4* srcw = (const uint4*)(g_wB + layer * 27648);
        uint4* dstw = (uint4*)(sm + OFF_B1);
#pragma unroll 4
        for (int i = tid; i < 1728; i += 128) dstw[i] = srcw[i];
    }
    for (int i = tid; i < 320; i += 128) ((float*)(sm + OFF_T))[i] = W1full[128 * 64 + i];
    if (tid < 64) {
        ((float*)(sm + OFF_BB1))[tid] = b1[tid];
        ((float*)(sm + OFF_BB2))[tid] = b2[tid];
        ((float*)(sm + OFF_G))[tid]   = gam[tid];
        ((float*)(sm + OFF_BE))[tid]  = bet[tid];
    }

    // A ldsm addressing (SW128-swizzled, 128B rows)
    const unsigned aOff = (unsigned)((warp * 32 + (lt & 1) * 8 + lr) * 128
                                     + ((unsigned)((lt >> 1) << 4) ^ ((unsigned)lr << 4)));
    const unsigned bLane = (unsigned)(((lt >> 1) * 8 + lr) * 144 + ((lt & 1) << 4));
    const float* bb1 = (const float*)(sm + OFF_BB1);
    int* sdst_all = (int*)(sm + OFF_SDST);
    float* sea_all = (float*)(sm + OFF_SEA);

    // gather lane mapping: lanes 0-15 -> even rows, lanes 16-31 -> odd rows
    const int grow = warp * 32 + (lane >> 4);
    const int cp = lane & 15;                       // 16B chunk within 256B node row
    const unsigned gdoff = ((cp < 8) ? 0u : 16384u)
                         + ((unsigned)((cp & 7) * 16));

    // --- prologue: stage tables(t0) + launch both gathers of t0 ---
    const int t0 = blockIdx.x;
    {
        const int e0 = t0 * 128;
        sdst_all[tid] = ei[NEDGES + e0 + tid];
        for (int i = tid; i < 640; i += 128) sea_all[i] = ea[(ull)e0 * 5 + i];
#pragma unroll
        for (int i = 0; i < 16; ++i) {
            int row = grow + 2 * i;
            int node = ei[NEDGES + e0 + row];
            cpasync16(sbase + OFF_A0H + gdoff + (unsigned)(row * 128) + ((((unsigned)row & 7u) << 4) & (unsigned)((cp & 7) ? 0xFFFFFFFF : 0xFFFFFFFF)) - ((unsigned)((cp & 7) * 16)) + ((unsigned)((cp & 7) * 16) ^ (((unsigned)row & 7u) << 4)) - ((((unsigned)row & 7u) << 4)),
                      (const unsigned char*)g_hs + (ull)node * 256 + cp * 16);
        }
        CP_COMMIT();
#pragma unroll
        for (int i = 0; i < 16; ++i) {
            int row = grow + 2 * i;
            int node = ei[e0 + row];
            cpasync16(sbase + OFF_A1H + ((cp < 8) ? 0u : 16384u) + (unsigned)(row * 128)
                          + ((unsigned)((cp & 7) * 16) ^ (((unsigned)row & 7u) << 4)),
                      (const unsigned char*)g_hs + (ull)node * 256 + cp * 16);
        }
        CP_COMMIT();
    }

    int it = 0;
    for (int t = t0; t < NTILES; t += gridDim.x, ++it) {
        const int p = it & 1;
        const int* sdst = sdst_all + p * 128;
        const float* sea = sea_all + p * 640;

        // next tile (clamped -> redundant copy, results unused)
        int tn = t + gridDim.x;
        if (tn >= NTILES) tn = t;
        const int e0n = tn * 128;

        // acc init with b1
        float acc[2][8][4];
#pragma unroll
        for (int nt = 0; nt < 8; ++nt) {
            float2 bv = *(const float2*)(bb1 + nt * 8 + 2 * tig);
#pragma unroll
            for (int mt = 0; mt < 2; ++mt) {
                acc[mt][nt][0] = bv.x; acc[mt][nt][1] = bv.y;
                acc[mt][nt][2] = bv.x; acc[mt][nt][3] = bv.y;
            }
        }

        // ===== wait buf0 (chunk0) + MMA =====
        CP_WAIT1();
        __syncthreads();
        {
            const unsigned bB = sbase + OFF_B1 + bLane;
#pragma unroll
            for (int kt = 0; kt < 4; ++kt) {
                const unsigned kx = (unsigned)(kt * 32);
                unsigned ah0[4], ah1[4], al0[4], al1[4];
                ldsm4(ah0, sbase + OFF_A0H + (aOff ^ kx));
                ldsm4(ah1, sbase + OFF_A0H + ((aOff + 2048u) ^ kx));
                ldsm4(al0, sbase + OFF_A0L + (aOff ^ kx));
                ldsm4(al1, sbase + OFF_A0L + ((aOff + 2048u) ^ kx));
                unsigned bf[4][4];
#pragma unroll
                for (int q = 0; q < 4; ++q) ldsm4(bf[q], bB + q * 2304u + kx);
#pragma unroll
                for (int q = 0; q < 4; ++q) {
                    mma16816(acc[0][2 * q],     ah0, bf[q][0], bf[q][1]);
                    mma16816(acc[0][2 * q + 1], ah0, bf[q][2], bf[q][3]);
                    mma16816(acc[1][2 * q],     ah1, bf[q][0], bf[q][1]);
                    mma16816(acc[1][2 * q + 1], ah1, bf[q][2], bf[q][3]);
                }
#pragma unroll
                for (int q = 0; q < 4; ++q) {
                    mma16816(acc[0][2 * q],     al0, bf[q][0], bf[q][1]);
                    mma16816(acc[0][2 * q + 1], al0, bf[q][2], bf[q][3]);
                    mma16816(acc[1][2 * q],     al1, bf[q][0], bf[q][1]);
                    mma16816(acc[1][2 * q + 1], al1, bf[q][2], bf[q][3]);
                }
            }
        }
        __syncthreads();   // all warps done reading buf0

        // stage next tables + issue chunk0(next) -> buf0
        sdst_all[(p ^ 1) * 128 + tid] = ei[NEDGES + e0n + tid];
        for (int i = tid; i < 640; i += 128) sea_all[(p ^ 1) * 640 + i] = ea[(ull)e0n * 5 + i];
#pragma unroll
        for (int i = 0; i < 16; ++i) {
            int row = grow + 2 * i;
            int node = ei[NEDGES + e0n + row];
            cpasync16(sbase + OFF_A0H + ((cp < 8) ? 0u : 16384u) + (unsigned)(row * 128)
                          + ((unsigned)((cp & 7) * 16) ^ (((unsigned)row & 7u) << 4)),
                      (const unsigned char*)g_hs + (ull)node * 256 + cp * 16);
        }
        CP_COMMIT();

        // ===== wait buf1 (chunk1) + MMA =====
        CP_WAIT1();
        __syncthreads();
        {
            const unsigned bB = sbase + OFF_B1 + 9216u + bLane;
#pragma unroll
            for (int kt = 0; kt < 4; ++kt) {
                const unsigned kx = (unsigned)(kt * 32);
                unsigned ah0[4], ah1[4], al0[4], al1[4];
                ldsm4(ah0, sbase + OFF_A1H + (aOff ^ kx));
                ldsm4(ah1, sbase + OFF_A1H + ((aOff + 2048u) ^ kx));
                ldsm4(al0, sbase + OFF_A1L + (aOff ^ kx));
                ldsm4(al1, sbase + OFF_A1L + ((aOff + 2048u) ^ kx));
                unsigned bf[4][4];
#pragma unroll
                for (int q = 0; q < 4; ++q) ldsm4(bf[q], bB + q * 2304u + kx);
#pragma unroll
                for (int q = 0; q < 4; ++q) {
                    mma16816(acc[0][2 * q],     ah0, bf[q][0], bf[q][1]);
                    mma16816(acc[0][2 * q + 1], ah0, bf[q][2], bf[q][3]);
                    mma16816(acc[1][2 * q],     ah1, bf[q][0], bf[q][1]);
                    mma16816(acc[1][2 * q + 1], ah1, bf[q][2], bf[q][3]);
                }
#pragma unroll
                for (int q = 0; q < 4; ++q) {
                    mma16816(acc[0][2 * q],     al0, bf[q][0], bf[q][1]);
                    mma16816(acc[0][2 * q + 1], al0, bf[q][2], bf[q][3]);
                    mma16816(acc[1][2 * q],     al1, bf[q][0], bf[q][1]);
                    mma16816(acc[1][2 * q + 1], al1, bf[q][2], bf[q][3]);
                }
            }
        }

        // ===== epilogue1 (registers): fp32 edge_attr tail + silu + fp16 split =====
        float eav[2][2][5];
#pragma unroll
        for (int mt = 0; mt < 2; ++mt)
#pragma unroll
            for (int h = 0; h < 2; ++h) {
                const float* er = sea + (warp * 32 + mt * 16 + h * 8 + gID) * 5;
#pragma unroll
                for (int j = 0; j < 5; ++j) eav[mt][h][j] = er[j];
            }
        unsigned uh[2][2][8], ulo[2][2][8];
#pragma unroll
        for (int nt = 0; nt < 8; ++nt) {
            float2 w[5];
#pragma unroll
            for (int j = 0; j < 5; ++j)
                w[j] = *(const float2*)(sm + OFF_T + (unsigned)((j * 64 + nt * 8 + tig * 2) * 4));
#pragma unroll
            for (int mt = 0; mt < 2; ++mt)
#pragma unroll
                for (int h = 0; h < 2; ++h) {
                    float y0 = acc[mt][nt][2 * h], y1 = acc[mt][nt][2 * h + 1];
#pragma unroll
                    for (int j = 0; j < 5; ++j) {
                        y0 = fmaf(eav[mt][h][j], w[j].x, y0);
                        y1 = fmaf(eav[mt][h][j], w[j].y, y1);
                    }
                    y0 = silu_f(y0); y1 = silu_f(y1);
                    __half2 hb = __float22half2_rn(make_float2(y0, y1));
                    float2 f = __half22float2(hb);
                    __half2 lb = __float22half2_rn(make_float2(y0 - f.x, y1 - f.y));
                    uh[mt][h][nt]  = *(unsigned*)&hb;
                    ulo[mt][h][nt] = *(unsigned*)&lb;
                }
        }

        // ===== GEMM2 (A from registers, B frags reused) =====
        float acc2[2][8][4];
#pragma unroll
        for (int nt = 0; nt < 8; ++nt) {
            float2 bv = *(const float2*)(sm + OFF_BB2 + (unsigned)((nt * 8 + tig * 2) * 4));
#pragma unroll
            for (int mt = 0; mt < 2; ++mt) {
                acc2[mt][nt][0] = bv.x; acc2[mt][nt][1] = bv.y;
                acc2[mt][nt][2] = bv.x; acc2[mt][nt][3] = bv.y;
            }
        }
        const unsigned b2B = sbase + OFF_B2 + bLane;
#pragma unroll
        for (int kt = 0; kt < 4; ++kt) {
            unsigned bf[4][4];
#pragma unroll
            for (int q = 0; q < 4; ++q) ldsm4(bf[q], b2B + q * 2304u + kt * 32u);
            unsigned ah0[4] = {uh[0][0][2 * kt], uh[0][1][2 * kt], uh[0][0][2 * kt + 1], uh[0][1][2 * kt + 1]};
            unsigned ah1[4] = {uh[1][0][2 * kt], uh[1][1][2 * kt], uh[1][0][2 * kt + 1], uh[1][1][2 * kt + 1]};
            unsigned al0[4] = {ulo[0][0][2 * kt], ulo[0][1][2 * kt], ulo[0][0][2 * kt + 1], ulo[0][1][2 * kt + 1]};
            unsigned al1[4] = {ulo[1][0][2 * kt], ulo[1][1][2 * kt], ulo[1][0][2 * kt + 1], ulo[1][1][2 * kt + 1]};
#pragma unroll
            for (int q = 0; q < 4; ++q) {
                mma16816(acc2[0][2 * q],     ah0, bf[q][0], bf[q][1]);
                mma16816(acc2[0][2 * q + 1], ah0, bf[q][2], bf[q][3]);
                mma16816(acc2[1][2 * q],     ah1, bf[q][0], bf[q][1]);
                mma16816(acc2[1][2 * q + 1], ah1, bf[q][2], bf[q][3]);
            }
#pragma unroll
            for (int q = 0; q < 4; ++q) {
                mma16816(acc2[0][2 * q],     al0, bf[q][0], bf[q][1]);
                mma16816(acc2[0][2 * q + 1], al0, bf[q][2], bf[q][3]);
                mma16816(acc2[1][2 * q],     al1, bf[q][0], bf[q][1]);
                mma16816(acc2[1][2 * q + 1], al1, bf[q][2], bf[q][3]);
            }
        }
        __syncthreads();   // all warps done reading buf1 (and tables written earlier are safe)

        // issue chunk1(next) -> buf1 (overlaps with epilogue2)
#pragma unroll
        for (int i = 0; i < 16; ++i) {
            int row = grow + 2 * i;
            int node = ei[e0n + row];
            cpasync16(sbase + OFF_A1H + ((cp < 8) ? 0u : 16384u) + (unsigned)(row * 128)
                          + ((unsigned)((cp & 7) * 16) ^ (((unsigned)row & 7u) << 4)),
                      (const unsigned char*)g_hs + (ull)node * 256 + cp * 16);
        }
        CP_COMMIT();

        // ===== epilogue2: LayerNorm (shuffles) + scatter (red.v4) =====
        float mArr[2][2], rsArr[2][2];
#pragma unroll
        for (int mt = 0; mt < 2; ++mt)
#pragma unroll
            for (int h = 0; h < 2; ++h) {
                float s = 0.f, ssum = 0.f;
#pragma unroll
                for (int nt = 0; nt < 8; ++nt) {
                    float v0 = acc2[mt][nt][2 * h], v1 = acc2[mt][nt][2 * h + 1];
                    s += v0 + v1; ssum += v0 * v0 + v1 * v1;
                }
                s    += __shfl_xor_sync(0xffffffffu, s, 1);
                ssum += __shfl_xor_sync(0xffffffffu, ssum, 1);
                s    += __shfl_xor_sync(0xffffffffu, s, 2);
                ssum += __shfl_xor_sync(0xffffffffu, ssum, 2);
                float m = s * (1.f / 64.f);
                mArr[mt][h]  = m;
                rsArr[mt][h] = rsqrtf(ssum * (1.f / 64.f) - m * m + 1e-5f);
            }
        const int cq = (tig & 1) * 2 + (tig >> 1);
        float4 gq[4], beq[4];
#pragma unroll
        for (int j = 0; j < 4; ++j) {
            gq[j]  = ((const float4*)(sm + OFF_G))[4 * j + cq];
            beq[j] = ((const float4*)(sm + OFF_BE))[4 * j + cq];
        }
        const unsigned colb = (unsigned)((tig & 1) * 8 + (tig >> 1) * 4);
#pragma unroll
        for (int mt = 0; mt < 2; ++mt)
#pragma unroll
            for (int h = 0; h < 2; ++h) {
                int row = warp * 32 + mt * 16 + h * 8 + gID;
                float* ag = g_agg + (ull)sdst[row] * 64 + colb;
                float m = mArr[mt][h], rs = rsArr[mt][h];
#pragma unroll
                for (int j = 0; j < 4; ++j) {
                    ull p0 = pack2(acc2[mt][2 * j][2 * h],     acc2[mt][2 * j][2 * h + 1]);
                    ull p1 = pack2(acc2[mt][2 * j + 1][2 * h], acc2[mt][2 * j + 1][2 * h + 1]);
                    ull sel = (tig & 1) ? p0 : p1;
                    ull rv = __shfl_xor_sync(0xffffffffu, sel, 1);
                    float q0, q1, q2, q3;
                    if (tig & 1) { unpack2(rv, q0, q1); unpack2(p1, q2, q3); }
                    else         { unpack2(p0, q0, q1); unpack2(rv, q2, q3); }
                    float o0 = (q0 - m) * rs * gq[j].x + beq[j].x;
                    float o1 = (q1 - m) * rs * gq[j].y + beq[j].y;
                    float o2 = (q2 - m) * rs * gq[j].z + beq[j].z;
                    float o3 = (q3 - m) * rs * gq[j].w + beq[j].w;
                    red_add4(ag + 16 * j, o0, o1, o2, o3);
                }
            }
    }
    CP_WAIT0();
}

// ---------------- node MLP (fp32 register-tiled; also writes fp16 g_hs) ----------------
#define FMA16(AA, AB, W0, W1, W2, W3, ACC)                               \
    do {                                                                 \
        ACC[0][0]=fma2(AA.x,W0,ACC[0][0]); ACC[0][1]=fma2(AA.x,W1,ACC[0][1]); \
        ACC[0][2]=fma2(AA.x,W2,ACC[0][2]); ACC[0][3]=fma2(AA.x,W3,ACC[0][3]); \
        ACC[1][0]=fma2(AA.y,W0,ACC[1][0]); ACC[1][1]=fma2(AA.y,W1,ACC[1][1]); \
        ACC[1][2]=fma2(AA.y,W2,ACC[1][2]); ACC[1][3]=fma2(AA.y,W3,ACC[1][3]); \
        ACC[2][0]=fma2(AB.x,W0,ACC[2][0]); ACC[2][1]=fma2(AB.x,W1,ACC[2][1]); \
        ACC[2][2]=fma2(AB.x,W2,ACC[2][2]); ACC[2][3]=fma2(AB.x,W3,ACC[2][3]); \
        ACC[3][0]=fma2(AB.y,W0,ACC[3][0]); ACC[3][1]=fma2(AB.y,W1,ACC[3][1]); \
        ACC[3][2]=fma2(AB.y,W2,ACC[3][2]); ACC[3][3]=fma2(AB.y,W3,ACC[3][3]); \
    } while (0)

__global__ void __launch_bounds__(256, 2) node2_kernel(
    const float* __restrict__ W1, const float* __restrict__ b1,
    const float* __restrict__ W2, const float* __restrict__ b2,
    const float* __restrict__ gam, const float* __restrict__ bet)
{
    extern __shared__ float smem[];
    float* sW1 = smem;
    float* sW2 = sW1 + 8192;
    float* sg  = sW2 + 4096;
    float* sbe = sg + 64;
    float* buf = sbe + 64;

    const int tid = threadIdx.x;
    for (int i = tid; i < 8192; i += 256) sW1[i] = W1[i];
    for (int i = tid; i < 4096; i += 256) sW2[i] = W2[i];
    if (tid < 64) { sg[tid] = gam[tid]; sbe[tid] = bet[tid]; }

    const int n0 = blockIdx.x * 128;
    const int tn = tid & 15, tm = tid >> 4;
    const int eg_ = tid & 127;
    const int kq  = (tid >> 7) * 4;

    ull acc[4][4];
    {
        float4 bv = *(const float4*)(b1 + tn * 4);
#pragma unroll
        for (int ep = 0; ep < 4; ++ep) {
            acc[ep][0] = dup2(bv.x); acc[ep][1] = dup2(bv.y);
            acc[ep][2] = dup2(bv.z); acc[ep][3] = dup2(bv.w);
        }
    }

    int ngi = n0 + eg_;
    if (ngi >= NNODES) ngi = 0;

#pragma unroll
    for (int ch = 0; ch < 2; ++ch) {
        const float* srcp = (ch == 0) ? g_h : g_agg;
        const float4* hp = (const float4*)(srcp + (ull)ngi * 64);
        __syncthreads();
#pragma unroll
        for (int r = 0; r < 8; ++r) {
            int k = r * 8 + kq;
            float4 v = hp[2 * r + (kq >> 2)];
            buf[(k + 0) * 128 + eg_] = v.x;
            buf[(k + 1) * 128 + eg_] = v.y;
            buf[(k + 2) * 128 + eg_] = v.z;
            buf[(k + 3) * 128 + eg_] = v.w;
        }
        __syncthreads();
        const float* wbase = sW1 + ch * 64 * 64;
#pragma unroll 2
        for (int k = 0; k < 64; ++k) {
            const ulonglong2* ar = (const ulonglong2*)(buf + k * 128 + tm * 8);
            ulonglong2 aA = ar[0], aB = ar[1];
            float4 wv = *(const float4*)(wbase + k * 64 + tn * 4);
            ull w0 = dup2(wv.x), w1 = dup2(wv.y), w2 = dup2(wv.z), w3 = dup2(wv.w);
            FMA16(aA, aB, w0, w1, w2, w3, acc);
        }
    }
    __syncthreads();

#pragma unroll
    for (int ep = 0; ep < 4; ++ep)
#pragma unroll
        for (int j = 0; j < 4; ++j) {
            float x0, x1;
            unpack2(acc[ep][j], x0, x1);
            *(ull*)(buf + (tn * 4 + j) * 132 + tm * 8 + 2 * ep) = pack2(silu_f(x0), silu_f(x1));
        }
    __syncthreads();

    ull acc2[4][4];
    {
        float4 bv = *(const float4*)(b2 + tn * 4);
#pragma unroll
        for (int ep = 0; ep < 4; ++ep) {
            acc2[ep][0] = dup2(bv.x); acc2[ep][1] = dup2(bv.y);
            acc2[ep][2] = dup2(bv.z); acc2[ep][3] = dup2(bv.w);
        }
    }
#pragma unroll 2
    for (int k = 0; k < 64; ++k) {
        const ulonglong2* ar = (const ulonglong2*)(buf + k * 132 + tm * 8);
        ulonglong2 aA = ar[0], aB = ar[1];
        float4 wv = *(const float4*)(sW2 + k * 64 + tn * 4);
        ull w0 = dup2(wv.x), w1 = dup2(wv.y), w2 = dup2(wv.z), w3 = dup2(wv.w);
        FMA16(aA, aB, w0, w1, w2, w3, acc2);
    }
    __syncthreads();

#pragma unroll
    for (int ep = 0; ep < 4; ++ep)
#pragma unroll
        for (int j = 0; j < 4; ++j) {
            float x0, x1;
            unpack2(acc2[ep][j], x0, x1);
            int e = tm * 8 + 2 * ep;
            buf[e * 66 + tn * 4 + j]       = x0;
            buf[(e + 1) * 66 + tn * 4 + j] = x1;
        }
    __syncthreads();

    if (tid < 128 && n0 + tid < NNODES) {
        const float* z = buf + tid * 66;
        float s = 0.f, ss = 0.f;
#pragma unroll 8
        for (int c = 0; c < 64; ++c) { float v = z[c]; s += v; ss += v * v; }
        float m  = s * (1.f / 64.f);
        float rs = rsqrtf(ss * (1.f / 64.f) - m * m + 1e-5f);
        float4* hp = (float4*)(g_h + (ull)(n0 + tid) * 64);
        __half* hs = g_hs + (ull)(n0 + tid) * 128;
#pragma unroll
        for (int q = 0; q < 16; ++q) {
            float4 hv = hp[q];
            hv.x += (z[4 * q + 0] - m) * rs * sg[4 * q + 0] + sbe[4 * q + 0];
            hv.y += (z[4 * q + 1] - m) * rs * sg[4 * q + 1] + sbe[4 * q + 1];
            hv.z += (z[4 * q + 2] - m) * rs * sg[4 * q + 2] + sbe[4 * q + 2];
            hv.w += (z[4 * q + 3] - m) * rs * sg[4 * q + 3] + sbe[4 * q + 3];
            hp[q] = hv;
            __half2 h01 = __float22half2_rn(make_float2(hv.x, hv.y));
            __half2 h23 = __float22half2_rn(make_float2(hv.z, hv.w));
            float2 f01 = __half22float2(h01);
            float2 f23 = __half22float2(h23);
            __half2 l01 = __float22half2_rn(make_float2(hv.x - f01.x, hv.y - f01.y));
            __half2 l23 = __float22half2_rn(make_float2(hv.z - f23.x, hv.w - f23.y));
            *(unsigned*)(hs + 4 * q)     = *(unsigned*)&h01;
            *(unsigned*)(hs + 4 * q + 2) = *(unsigned*)&h23;
            *(unsigned*)(hs + 64 + 4 * q)     = *(unsigned*)&l01;
            *(unsigned*)(hs + 64 + 4 * q + 2) = *(unsigned*)&l23;
        }
    }
}

// ---------------- local decoder ----------------
__global__ void __launch_bounds__(128) dec_local_kernel(
    const float* __restrict__ W1, const float* __restrict__ b1,
    const float* __restrict__ W2, const float* __restrict__ b2,
    float* __restrict__ out)
{
    __shared__ float sW1[64 * 64];
    __shared__ float sW2[64 * 6];
    __shared__ float sb1[64];
    __shared__ float sb2[8];
    __shared__ float sy[4][64];
    int tid = threadIdx.x;
    for (int i = tid; i < 64 * 64; i += 128) sW1[i] = W1[i];
    for (int i = tid; i < 64 * 6; i += 128) sW2[i] = W2[i];
    if (tid < 64) sb1[tid] = b1[tid];
    if (tid < 6)  sb2[tid] = b2[tid];
    __syncthreads();

    int lane = tid & 31, warp = tid >> 5;
    int j0 = lane, j1 = lane + 32;
    for (int n = blockIdx.x * 4 + warp; n < NNODES; n += gridDim.x * 4) {
        const float4* Hr = reinterpret_cast<const float4*>(g_h + n * HID);
        float a0 = sb1[j0], a1 = sb1[j1];
#pragma unroll 4
        for (int c = 0; c < 16; ++c) {
            float4 v = Hr[c];
            const float* w = sW1 + 4 * c * 64;
            a0 = fmaf(v.x, w[j0], a0);           a1 = fmaf(v.x, w[j1], a1);
            a0 = fmaf(v.y, w[64 + j0], a0);      a1 = fmaf(v.y, w[64 + j1], a1);
            a0 = fmaf(v.z, w[128 + j0], a0);     a1 = fmaf(v.z, w[128 + j1], a1);
            a0 = fmaf(v.w, w[192 + j0], a0);     a1 = fmaf(v.w, w[192 + j1], a1);
        }
        a0 = silu_f(a0); a1 = silu_f(a1);
        sy[warp][j0] = a0; sy[warp][j1] = a1;
        __syncwarp();
        if (lane < 6) {
            float o = sb2[lane];
#pragma unroll 8
            for (int k = 0; k < 64; ++k) o = fmaf(sy[warp][k], sW2[k * 6 + lane], o);
            out[n * 6 + lane] = o;
        }
        __syncwarp();
    }
}

// ---------------- pooling ----------------
__global__ void __launch_bounds__(256) pool_kernel(const int* __restrict__ batch)
{
    __shared__ float sacc[NGRAPH * HID];
    __shared__ int   scnt[NGRAPH];
    int tid = threadIdx.x;
    sacc[tid] = 0.f;
    if (tid < NGRAPH) scnt[tid] = 0;
    __syncthreads();
    int j = tid & 63;
    int r = tid >> 6;
    int base = blockIdx.x * 512;
    int end = min(base + 512, NNODES);
    for (int n = base + r; n < end; n += 4) {
        int b = batch[n];
        atomicAdd(&sacc[b * HID + j], g_h[n * HID + j]);
        if (j == 0) atomicAdd(&scnt[b], 1);
    }
    __syncthreads();
    atomicAdd(&g_pooled[tid], sacc[tid]);
    if (tid < NGRAPH) atomicAdd(&g_cnt[tid], scnt[tid]);
}

// ---------------- global decoder ----------------
__global__ void dec_global_kernel(
    const float* __restrict__ W1, const float* __restrict__ b1,
    const float* __restrict__ W2, const float* __restrict__ b2,
    float* __restrict__ out)
{
    __shared__ float sy[NGRAPH][32];
    int g = threadIdx.x >> 5;
    int lane = threadIdx.x & 31;
    float inv = 1.f / fmaxf((float)g_cnt[g], 1.f);
    float a = b1[lane];
#pragma unroll 8
    for (int k = 0; k < 64; ++k)
        a = fmaf(g_pooled[g * HID + k] * inv, W1[k * 32 + lane], a);
    a = silu_f(a);
    sy[g][lane] = a;
    __syncwarp();
    if (lane < 4) {
        float o = b2[lane];
#pragma unroll 8
        for (int k = 0; k < 32; ++k) o = fmaf(sy[g][k], W2[k * 4 + lane], o);
        out[g * 4 + lane] = o;
    }
}

// ---------------- launch ----------------
extern "C" void kernel_launch(void* const* d_in, const int* in_sizes, int n_in,
                              void* d_out, int out_size)
{
    (void)in_sizes; (void)n_in; (void)out_size;
    const float* x      = (const float*)d_in[0];
    const int*   ei     = (const int*)  d_in[1];
    const float* ea     = (const float*)d_in[2];
    const int*   batch  = (const int*)  d_in[3];
    const float* caseP  = (const float*)d_in[4];
    const float* bcP    = (const float*)d_in[5];
    const float* encW1  = (const float*)d_in[6];
    const float* encb1  = (const float*)d_in[7];
    const float* encW2  = (const float*)d_in[8];
    const float* encb2  = (const float*)d_in[9];
    const float* encg   = (const float*)d_in[10];
    const float* encbe  = (const float*)d_in[11];
    const float* eW1    = (const float*)d_in[12];
    const float* eb1    = (const float*)d_in[13];
    const float* eW2    = (const float*)d_in[14];
    const float* eb2    = (const float*)d_in[15];
    const float* egm    = (const float*)d_in[16];
    const float* ebe    = (const float*)d_in[17];
    const float* nW1    = (const float*)d_in[18];
    const float* nb1    = (const float*)d_in[19];
    const float* nW2    = (const float*)d_in[20];
    const float* nb2    = (const float*)d_in[21];
    const float* ngm    = (const float*)d_in[22];
    const float* nbe    = (const float*)d_in[23];
    const float* dlW1   = (const float*)d_in[24];
    const float* dlb1   = (const float*)d_in[25];
    const float* dlW2   = (const float*)d_in[26];
    const float* dlb2   = (const float*)d_in[27];
    const float* dgW1   = (const float*)d_in[28];
    const float* dgb1   = (const float*)d_in[29];
    const float* dgW2   = (const float*)d_in[30];
    const float* dgb2   = (const float*)d_in[31];
    float* out = (float*)d_out;

    const int NODE_SMEM = (8192 + 4096 + 128 + 8448) * 4;
    cudaFuncSetAttribute(edge10_kernel, cudaFuncAttributeMaxDynamicSharedMemorySize, EDGE_SMEM);
    cudaFuncSetAttribute(node2_kernel, cudaFuncAttributeMaxDynamicSharedMemorySize, NODE_SMEM);

    prep_weights<<<(NLAYERS * 12288 + 255) / 256, 256>>>(eW1, eW2);
    encoder_kernel<<<200, 128>>>(x, batch, caseP, bcP,
                                 encW1, encb1, encW2, encb2, encg, encbe);

    const int NODE_GRID = (NNODES + 127) / 128;

    for (int l = 0; l < NLAYERS; ++l) {
        zero_agg_kernel<<<512, 256>>>();
        edge10_kernel<<<296, 128, EDGE_SMEM>>>(
            ei, ea, l,
            eW1 + l * 133 * 64, eb1 + l * 64, eb2 + l * 64,
            egm + l * 64, ebe + l * 64);
        node2_kernel<<<NODE_GRID, 256, NODE_SMEM>>>(
            nW1 + l * 128 * 64, nb1 + l * 64,
            nW2 + l * 64 * 64,  nb2 + l * 64,
            ngm + l * 64,       nbe + l * 64);
    }

    zero_pool_kernel<<<1, 256>>>();
    dec_local_kernel<<<200, 128>>>(dlW1, dlb1, dlW2, dlb2, out);
    pool_kernel<<<(NNODES + 511) / 512, 256>>>(batch);
    dec_global_kernel<<<1, 128>>>(dgW1, dgb1, dgW2, dgb2, out + NNODES * 6);
}

// round 12
// speedup vs baseline: 1.5845x; 1.0507x over previous
#include <cuda_runtime.h>
#include <cuda_fp16.h>

typedef unsigned long long ull;

#define NNODES 50000
#define NEDGES 1600000
#define NGRAPH 4
#define HID    64
#define NLAYERS 5
#define NTILES (NEDGES / 128)   // 12500

// ---------------- device scratch ----------------
__device__ float g_h[NNODES * HID];
__device__ __align__(16) __half g_hs[NNODES * 128];   // per node: 64 fp16 hi, 64 fp16 lo
__device__ float g_agg[NNODES * HID];
__device__ float g_pooled[NGRAPH * HID];
__device__ int   g_cnt[NGRAPH];
// per-layer fp16 weights [n][k] stride-144: B1 (2 chunks x 9216) + B2 (9216) = 27648 B
__device__ __align__(16) unsigned char g_wB[NLAYERS * 27648];

// ---------------- SMEM layout (bytes) ----------------
#define OFF_A0H  0u        // chunk0: A hi 128x128B SW128 (16384)
#define OFF_A0L  16384u
#define OFF_A1H  32768u    // chunk1
#define OFF_A1L  49152u
#define OFF_B1   65536u    // 2 x 9216
#define OFF_B2   83968u    // 9216
#define OFF_T    93184u    // W1 tail rows 128..132 fp32 [5][64] (1280)
#define OFF_BB1  94464u
#define OFF_BB2  94720u
#define OFF_G    94976u
#define OFF_BE   95232u
#define OFF_SDST 95488u    // 2 x 128 ints (1024)
#define OFF_SEA  96512u    // 2 x 640 fp32 (5120)
#define EDGE_SMEM 101632

// ---------------- generic helpers ----------------
__device__ __forceinline__ float silu_f(float x) {
    float t;
    asm("tanh.approx.f32 %0, %1;" : "=f"(t) : "f"(x * 0.5f));
    return x * 0.5f * t + x * 0.5f;
}
__device__ __forceinline__ ull fma2(ull a, ull b, ull c) {
    ull d;
    asm("fma.rn.f32x2 %0, %1, %2, %3;" : "=l"(d) : "l"(a), "l"(b), "l"(c));
    return d;
}
__device__ __forceinline__ ull pack2(float lo, float hi) {
    ull r;
    asm("mov.b64 %0, {%1, %2};" : "=l"(r) : "f"(lo), "f"(hi));
    return r;
}
__device__ __forceinline__ ull dup2(float x) {
    ull r;
    asm("mov.b64 %0, {%1, %1};" : "=l"(r) : "f"(x));
    return r;
}
__device__ __forceinline__ void unpack2(ull v, float& lo, float& hi) {
    asm("mov.b64 {%0, %1}, %2;" : "=f"(lo), "=f"(hi) : "l"(v));
}
__device__ __forceinline__ void red_add4(float* p, float a, float b, float c, float d) {
    asm volatile("red.global.add.v4.f32 [%0], {%1, %2, %3, %4};"
                 :: "l"(p), "f"(a), "f"(b), "f"(c), "f"(d) : "memory");
}
__device__ __forceinline__ unsigned smem_u32(const void* p) {
    unsigned a;
    asm("{ .reg .u64 t; cvta.to.shared.u64 t, %1; cvt.u32.u64 %0, t; }" : "=r"(a) : "l"(p));
    return a;
}

// ---------------- cp.async helpers ----------------
__device__ __forceinline__ void cpasync16(unsigned dst, const void* src) {
    asm volatile("cp.async.cg.shared.global [%0], [%1], 16;" :: "r"(dst), "l"(src) : "memory");
}
#define CP_COMMIT() asm volatile("cp.async.commit_group;" ::: "memory")
#define CP_WAIT1()  asm volatile("cp.async.wait_group 1;" ::: "memory")
#define CP_WAIT0()  asm volatile("cp.async.wait_group 0;" ::: "memory")

// ---------------- mma.sync helpers (fp16 in, fp32 accum) ----------------
__device__ __forceinline__ void ldsm4(unsigned* r, unsigned addr) {
    asm volatile("ldmatrix.sync.aligned.m8n8.x4.shared.b16 {%0,%1,%2,%3}, [%4];"
                 : "=r"(r[0]), "=r"(r[1]), "=r"(r[2]), "=r"(r[3]) : "r"(addr));
}
__device__ __forceinline__ void mma16816(float* c, const unsigned* a, unsigned b0, unsigned b1) {
    asm volatile("mma.sync.aligned.m16n8k16.row.col.f32.f16.f16.f32 "
                 "{%0,%1,%2,%3}, {%4,%5,%6,%7}, {%8,%9}, {%0,%1,%2,%3};"
                 : "+f"(c[0]), "+f"(c[1]), "+f"(c[2]), "+f"(c[3])
                 : "r"(a[0]), "r"(a[1]), "r"(a[2]), "r"(a[3]), "r"(b0), "r"(b1));
}

// ---------------- zero kernels ----------------
__global__ void zero_agg_kernel() {
    int i = blockIdx.x * blockDim.x + threadIdx.x;
    for (; i < NNODES * HID; i += gridDim.x * blockDim.x) g_agg[i] = 0.f;
}
__global__ void zero_pool_kernel() {
    int t = threadIdx.x;
    if (t < NGRAPH * HID) g_pooled[t] = 0.f;
    if (t < NGRAPH) g_cnt[t] = 0;
}

// ---------------- weight prep: fp32 -> fp16, padded [n][k] ----------------
__global__ void prep_weights(const float* __restrict__ eW1, const float* __restrict__ eW2) {
    int idx = blockIdx.x * blockDim.x + threadIdx.x;
    if (idx >= NLAYERS * 12288) return;
    int l = idx / 12288, r = idx % 12288;
    unsigned char* base = g_wB + l * 27648;
    float w;
    unsigned off;
    if (r < 8192) {
        int c = r >> 12, rr = r & 4095, n = rr >> 6, kk = rr & 63;
        w = eW1[l * 133 * 64 + (c * 64 + kk) * 64 + n];
        off = (unsigned)(c * 9216 + n * 144 + kk * 2);
    } else {
        int rr = r - 8192, n = rr >> 6, kk = rr & 63;
        w = eW2[l * 4096 + kk * 64 + n];
        off = (unsigned)(18432 + n * 144 + kk * 2);
    }
    *(__half*)(base + off) = __float2half_rn(w);
}

// ---------------- encoder (also writes split-fp16 g_hs) ----------------
__global__ void __launch_bounds__(128) encoder_kernel(
    const float* __restrict__ x, const int* __restrict__ batch,
    const float* __restrict__ caseP, const float* __restrict__ bcP,
    const float* __restrict__ W1, const float* __restrict__ b1,
    const float* __restrict__ W2, const float* __restrict__ b2,
    const float* __restrict__ gam, const float* __restrict__ bet)
{
    __shared__ float sW1[16 * 64];
    __shared__ float sW2[64 * 64];
    __shared__ float sb1[64], sb2[64], sg[64], sbe[64];
    __shared__ float sy[4][64];
    int tid = threadIdx.x;
    for (int i = tid; i < 16 * 64; i += 128) sW1[i] = W1[i];
    for (int i = tid; i < 64 * 64; i += 128) sW2[i] = W2[i];
    if (tid < 64) { sb1[tid] = b1[tid]; sb2[tid] = b2[tid]; sg[tid] = gam[tid]; sbe[tid] = bet[tid]; }
    __syncthreads();

    int lane = tid & 31, warp = tid >> 5;
    int j0 = lane, j1 = lane + 32;
    for (int n = blockIdx.x * 4 + warp; n < NNODES; n += gridDim.x * 4) {
        float in[16];
        const float* xr = x + n * 8;
#pragma unroll
        for (int k = 0; k < 8; ++k) in[k] = xr[k];
        int b = batch[n];
#pragma unroll
        for (int k = 0; k < 4; ++k) in[8 + k]  = caseP[b * 4 + k];
#pragma unroll
        for (int k = 0; k < 4; ++k) in[12 + k] = bcP[b * 4 + k];

        float a0 = sb1[j0], a1 = sb1[j1];
#pragma unroll
        for (int k = 0; k < 16; ++k) {
            a0 = fmaf(in[k], sW1[k * 64 + j0], a0);
            a1 = fmaf(in[k], sW1[k * 64 + j1], a1);
        }
        a0 = silu_f(a0); a1 = silu_f(a1);
        sy[warp][j0] = a0; sy[warp][j1] = a1;
        __syncwarp();
        float z0 = sb2[j0], z1 = sb2[j1];
#pragma unroll 4
        for (int k = 0; k < 64; ++k) {
            float v = sy[warp][k];
            z0 = fmaf(v, sW2[k * 64 + j0], z0);
            z1 = fmaf(v, sW2[k * 64 + j1], z1);
        }
        float s = z0 + z1, ss = z0 * z0 + z1 * z1;
#pragma unroll
        for (int o = 16; o > 0; o >>= 1) {
            s  += __shfl_xor_sync(0xffffffffu, s, o);
            ss += __shfl_xor_sync(0xffffffffu, ss, o);
        }
        float m = s * (1.f / 64.f);
        float rs = rsqrtf(ss * (1.f / 64.f) - m * m + 1e-5f);
        float v0 = (z0 - m) * rs * sg[j0] + sbe[j0];
        float v1 = (z1 - m) * rs * sg[j1] + sbe[j1];
        g_h[n * HID + j0] = v0;
        g_h[n * HID + j1] = v1;
        __half h0 = __float2half_rn(v0);
        __half h1 = __float2half_rn(v1);
        g_hs[n * 128 + j0] = h0;
        g_hs[n * 128 + j1] = h1;
        g_hs[n * 128 + 64 + j0] = __float2half_rn(v0 - __half2float(h0));
        g_hs[n * 128 + 64 + j1] = __float2half_rn(v1 - __half2float(h1));
        __syncwarp();
    }
}

// ---------------- edge MLP v11: pipeline + single-pass GEMM2 ----------------
__global__ void __launch_bounds__(128, 2) edge11_kernel(
    const int* __restrict__ ei, const float* __restrict__ ea, int layer,
    const float* __restrict__ W1full, const float* __restrict__ b1,
    const float* __restrict__ b2,
    const float* __restrict__ gam, const float* __restrict__ bet)
{
    extern __shared__ unsigned char sm[];
    const unsigned sbase = smem_u32(sm);
    const int tid = threadIdx.x;
    const int lane = tid & 31, warp = tid >> 5;
    const int gID = lane >> 2, tig = lane & 3;
    const int lt = lane >> 3, lr = lane & 7;

    // --- one-time loads ---
    {
        const uint4* srcw = (const uint4*)(g_wB + layer * 27648);
        uint4* dstw = (uint4*)(sm + OFF_B1);
#pragma unroll 4
        for (int i = tid; i < 1728; i += 128) dstw[i] = srcw[i];
    }
    for (int i = tid; i < 320; i += 128) ((float*)(sm + OFF_T))[i] = W1full[128 * 64 + i];
    if (tid < 64) {
        ((float*)(sm + OFF_BB1))[tid] = b1[tid];
        ((float*)(sm + OFF_BB2))[tid] = b2[tid];
        ((float*)(sm + OFF_G))[tid]   = gam[tid];
        ((float*)(sm + OFF_BE))[tid]  = bet[tid];
    }

    // A ldsm addressing (SW128-swizzled, 128B rows)
    const unsigned aOff = (unsigned)((warp * 32 + (lt & 1) * 8 + lr) * 128
                                     + ((unsigned)((lt >> 1) << 4) ^ ((unsigned)lr << 4)));
    const unsigned bLane = (unsigned)(((lt >> 1) * 8 + lr) * 144 + ((lt & 1) << 4));
    const float* bb1 = (const float*)(sm + OFF_BB1);
    int* sdst_all = (int*)(sm + OFF_SDST);
    float* sea_all = (float*)(sm + OFF_SEA);

    // gather lane mapping: lanes 0-15 -> even rows, lanes 16-31 -> odd rows
    const int grow = warp * 32 + (lane >> 4);
    const int cp = lane & 15;                       // 16B chunk within 256B node row
    const unsigned gsel = (cp < 8) ? 0u : 16384u;   // hi vs lo buffer half
    const unsigned gcol = (unsigned)((cp & 7) * 16);

    // --- prologue: stage tables(t0) + launch both gathers of t0 ---
    const int t0 = blockIdx.x;
    {
        const int e0 = t0 * 128;
        sdst_all[tid] = ei[NEDGES + e0 + tid];
        for (int i = tid; i < 640; i += 128) sea_all[i] = ea[(ull)e0 * 5 + i];
#pragma unroll
        for (int i = 0; i < 16; ++i) {
            int row = grow + 2 * i;
            int node = ei[NEDGES + e0 + row];
            cpasync16(sbase + OFF_A0H + gsel + (unsigned)(row * 128)
                          + (gcol ^ (((unsigned)row & 7u) << 4)),
                      (const unsigned char*)g_hs + (ull)node * 256 + cp * 16);
        }
        CP_COMMIT();
#pragma unroll
        for (int i = 0; i < 16; ++i) {
            int row = grow + 2 * i;
            int node = ei[e0 + row];
            cpasync16(sbase + OFF_A1H + gsel + (unsigned)(row * 128)
                          + (gcol ^ (((unsigned)row & 7u) << 4)),
                      (const unsigned char*)g_hs + (ull)node * 256 + cp * 16);
        }
        CP_COMMIT();
    }

    int it = 0;
    for (int t = t0; t < NTILES; t += gridDim.x, ++it) {
        const int p = it & 1;
        const int* sdst = sdst_all + p * 128;
        const float* sea = sea_all + p * 640;

        // next tile (clamped -> redundant copy, results unused)
        int tn = t + gridDim.x;
        if (tn >= NTILES) tn = t;
        const int e0n = tn * 128;

        // acc init with b1
        float acc[2][8][4];
#pragma unroll
        for (int nt = 0; nt < 8; ++nt) {
            float2 bv = *(const float2*)(bb1 + nt * 8 + 2 * tig);
#pragma unroll
            for (int mt = 0; mt < 2; ++mt) {
                acc[mt][nt][0] = bv.x; acc[mt][nt][1] = bv.y;
                acc[mt][nt][2] = bv.x; acc[mt][nt][3] = bv.y;
            }
        }

        // ===== wait buf0 (chunk0) + MMA =====
        CP_WAIT1();
        __syncthreads();
        {
            const unsigned bB = sbase + OFF_B1 + bLane;
#pragma unroll
            for (int kt = 0; kt < 4; ++kt) {
                const unsigned kx = (unsigned)(kt * 32);
                unsigned ah0[4], ah1[4], al0[4], al1[4];
                ldsm4(ah0, sbase + OFF_A0H + (aOff ^ kx));
                ldsm4(ah1, sbase + OFF_A0H + ((aOff + 2048u) ^ kx));
                ldsm4(al0, sbase + OFF_A0L + (aOff ^ kx));
                ldsm4(al1, sbase + OFF_A0L + ((aOff + 2048u) ^ kx));
                unsigned bf[4][4];
#pragma unroll
                for (int q = 0; q < 4; ++q) ldsm4(bf[q], bB + q * 2304u + kx);
#pragma unroll
                for (int q = 0; q < 4; ++q) {
                    mma16816(acc[0][2 * q],     ah0, bf[q][0], bf[q][1]);
                    mma16816(acc[0][2 * q + 1], ah0, bf[q][2], bf[q][3]);
                    mma16816(acc[1][2 * q],     ah1, bf[q][0], bf[q][1]);
                    mma16816(acc[1][2 * q + 1], ah1, bf[q][2], bf[q][3]);
                }
#pragma unroll
                for (int q = 0; q < 4; ++q) {
                    mma16816(acc[0][2 * q],     al0, bf[q][0], bf[q][1]);
                    mma16816(acc[0][2 * q + 1], al0, bf[q][2], bf[q][3]);
                    mma16816(acc[1][2 * q],     al1, bf[q][0], bf[q][1]);
                    mma16816(acc[1][2 * q + 1], al1, bf[q][2], bf[q][3]);
                }
            }
        }
        __syncthreads();   // all warps done reading buf0

        // stage next tables + issue chunk0(next) -> buf0
        sdst_all[(p ^ 1) * 128 + tid] = ei[NEDGES + e0n + tid];
        for (int i = tid; i < 640; i += 128) sea_all[(p ^ 1) * 640 + i] = ea[(ull)e0n * 5 + i];
#pragma unroll
        for (int i = 0; i < 16; ++i) {
            int row = grow + 2 * i;
            int node = ei[NEDGES + e0n + row];
            cpasync16(sbase + OFF_A0H + gsel + (unsigned)(row * 128)
                          + (gcol ^ (((unsigned)row & 7u) << 4)),
                      (const unsigned char*)g_hs + (ull)node * 256 + cp * 16);
        }
        CP_COMMIT();

        // ===== wait buf1 (chunk1) + MMA =====
        CP_WAIT1();
        __syncthreads();
        {
            const unsigned bB = sbase + OFF_B1 + 9216u + bLane;
#pragma unroll
            for (int kt = 0; kt < 4; ++kt) {
                const unsigned kx = (unsigned)(kt * 32);
                unsigned ah0[4], ah1[4], al0[4], al1[4];
                ldsm4(ah0, sbase + OFF_A1H + (aOff ^ kx));
                ldsm4(ah1, sbase + OFF_A1H + ((aOff + 2048u) ^ kx));
                ldsm4(al0, sbase + OFF_A1L + (aOff ^ kx));
                ldsm4(al1, sbase + OFF_A1L + ((aOff + 2048u) ^ kx));
                unsigned bf[4][4];
#pragma unroll
                for (int q = 0; q < 4; ++q) ldsm4(bf[q], bB + q * 2304u + kx);
#pragma unroll
                for (int q = 0; q < 4; ++q) {
                    mma16816(acc[0][2 * q],     ah0, bf[q][0], bf[q][1]);
                    mma16816(acc[0][2 * q + 1], ah0, bf[q][2], bf[q][3]);
                    mma16816(acc[1][2 * q],     ah1, bf[q][0], bf[q][1]);
                    mma16816(acc[1][2 * q + 1], ah1, bf[q][2], bf[q][3]);
                }
#pragma unroll
                for (int q = 0; q < 4; ++q) {
                    mma16816(acc[0][2 * q],     al0, bf[q][0], bf[q][1]);
                    mma16816(acc[0][2 * q + 1], al0, bf[q][2], bf[q][3]);
                    mma16816(acc[1][2 * q],     al1, bf[q][0], bf[q][1]);
                    mma16816(acc[1][2 * q + 1], al1, bf[q][2], bf[q][3]);
                }
            }
        }

        // ===== epilogue1 (registers): fp32 edge_attr tail + silu -> fp16 (single) =====
        float eav[2][2][5];
#pragma unroll
        for (int mt = 0; mt < 2; ++mt)
#pragma unroll
            for (int h = 0; h < 2; ++h) {
                const float* er = sea + (warp * 32 + mt * 16 + h * 8 + gID) * 5;
#pragma unroll
                for (int j = 0; j < 5; ++j) eav[mt][h][j] = er[j];
            }
        unsigned uh[2][2][8];
#pragma unroll
        for (int nt = 0; nt < 8; ++nt) {
            float2 w[5];
#pragma unroll
            for (int j = 0; j < 5; ++j)
                w[j] = *(const float2*)(sm + OFF_T + (unsigned)((j * 64 + nt * 8 + tig * 2) * 4));
#pragma unroll
            for (int mt = 0; mt < 2; ++mt)
#pragma unroll
                for (int h = 0; h < 2; ++h) {
                    float y0 = acc[mt][nt][2 * h], y1 = acc[mt][nt][2 * h + 1];
#pragma unroll
                    for (int j = 0; j < 5; ++j) {
                        y0 = fmaf(eav[mt][h][j], w[j].x, y0);
                        y1 = fmaf(eav[mt][h][j], w[j].y, y1);
                    }
                    __half2 hb = __float22half2_rn(make_float2(silu_f(y0), silu_f(y1)));
                    uh[mt][h][nt] = *(unsigned*)&hb;
                }
        }

        // ===== GEMM2 (A from registers, single hi pass) =====
        float acc2[2][8][4];
#pragma unroll
        for (int nt = 0; nt < 8; ++nt) {
            float2 bv = *(const float2*)(sm + OFF_BB2 + (unsigned)((nt * 8 + tig * 2) * 4));
#pragma unroll
            for (int mt = 0; mt < 2; ++mt) {
                acc2[mt][nt][0] = bv.x; acc2[mt][nt][1] = bv.y;
                acc2[mt][nt][2] = bv.x; acc2[mt][nt][3] = bv.y;
            }
        }
        const unsigned b2B = sbase + OFF_B2 + bLane;
#pragma unroll
        for (int kt = 0; kt < 4; ++kt) {
            unsigned bf[4][4];
#pragma unroll
            for (int q = 0; q < 4; ++q) ldsm4(bf[q], b2B + q * 2304u + kt * 32u);
            unsigned ah0[4] = {uh[0][0][2 * kt], uh[0][1][2 * kt], uh[0][0][2 * kt + 1], uh[0][1][2 * kt + 1]};
            unsigned ah1[4] = {uh[1][0][2 * kt], uh[1][1][2 * kt], uh[1][0][2 * kt + 1], uh[1][1][2 * kt + 1]};
#pragma unroll
            for (int q = 0; q < 4; ++q) {
                mma16816(acc2[0][2 * q],     ah0, bf[q][0], bf[q][1]);
                mma16816(acc2[0][2 * q + 1], ah0, bf[q][2], bf[q][3]);
                mma16816(acc2[1][2 * q],     ah1, bf[q][0], bf[q][1]);
                mma16816(acc2[1][2 * q + 1], ah1, bf[q][2], bf[q][3]);
            }
        }
        __syncthreads();   // all warps done reading buf1

        // issue chunk1(next) -> buf1 (overlaps with epilogue2)
#pragma unroll
        for (int i = 0; i < 16; ++i) {
            int row = grow + 2 * i;
            int node = ei[e0n + row];
            cpasync16(sbase + OFF_A1H + gsel + (unsigned)(row * 128)
                          + (gcol ^ (((unsigned)row & 7u) << 4)),
                      (const unsigned char*)g_hs + (ull)node * 256 + cp * 16);
        }
        CP_COMMIT();

        // ===== epilogue2: LayerNorm (shuffles) + scatter (red.v4) =====
        float mArr[2][2], rsArr[2][2];
#pragma unroll
        for (int mt = 0; mt < 2; ++mt)
#pragma unroll
            for (int h = 0; h < 2; ++h) {
                float s = 0.f, ssum = 0.f;
#pragma unroll
                for (int nt = 0; nt < 8; ++nt) {
                    float v0 = acc2[mt][nt][2 * h], v1 = acc2[mt][nt][2 * h + 1];
                    s += v0 + v1; ssum += v0 * v0 + v1 * v1;
                }
                s    += __shfl_xor_sync(0xffffffffu, s, 1);
                ssum += __shfl_xor_sync(0xffffffffu, ssum, 1);
                s    += __shfl_xor_sync(0xffffffffu, s, 2);
                ssum += __shfl_xor_sync(0xffffffffu, ssum, 2);
                float m = s * (1.f / 64.f);
                mArr[mt][h]  = m;
                rsArr[mt][h] = rsqrtf(ssum * (1.f / 64.f) - m * m + 1e-5f);
            }
        const int cq = (tig & 1) * 2 + (tig >> 1);
        float4 gq[4], beq[4];
#pragma unroll
        for (int j = 0; j < 4; ++j) {
            gq[j]  = ((const float4*)(sm + OFF_G))[4 * j + cq];
            beq[j] = ((const float4*)(sm + OFF_BE))[4 * j + cq];
        }
        const unsigned colb = (unsigned)((tig & 1) * 8 + (tig >> 1) * 4);
#pragma unroll
        for (int mt = 0; mt < 2; ++mt)
#pragma unroll
            for (int h = 0; h < 2; ++h) {
                int row = warp * 32 + mt * 16 + h * 8 + gID;
                float* ag = g_agg + (ull)sdst[row] * 64 + colb;
                float m = mArr[mt][h], rs = rsArr[mt][h];
#pragma unroll
                for (int j = 0; j < 4; ++j) {
                    ull p0 = pack2(acc2[mt][2 * j][2 * h],     acc2[mt][2 * j][2 * h + 1]);
                    ull p1 = pack2(acc2[mt][2 * j + 1][2 * h], acc2[mt][2 * j + 1][2 * h + 1]);
                    ull sel = (tig & 1) ? p0 : p1;
                    ull rv = __shfl_xor_sync(0xffffffffu, sel, 1);
                    float q0, q1, q2, q3;
                    if (tig & 1) { unpack2(rv, q0, q1); unpack2(p1, q2, q3); }
                    else         { unpack2(p0, q0, q1); unpack2(rv, q2, q3); }
                    float o0 = (q0 - m) * rs * gq[j].x + beq[j].x;
                    float o1 = (q1 - m) * rs * gq[j].y + beq[j].y;
                    float o2 = (q2 - m) * rs * gq[j].z + beq[j].z;
                    float o3 = (q3 - m) * rs * gq[j].w + beq[j].w;
                    red_add4(ag + 16 * j, o0, o1, o2, o3);
                }
            }
    }
    CP_WAIT0();
}

// ---------------- node MLP (fp32 register-tiled; also writes fp16 g_hs) ----------------
#define FMA16(AA, AB, W0, W1, W2, W3, ACC)                               \
    do {                                                                 \
        ACC[0][0]=fma2(AA.x,W0,ACC[0][0]); ACC[0][1]=fma2(AA.x,W1,ACC[0][1]); \
        ACC[0][2]=fma2(AA.x,W2,ACC[0][2]); ACC[0][3]=fma2(AA.x,W3,ACC[0][3]); \
        ACC[1][0]=fma2(AA.y,W0,ACC[1][0]); ACC[1][1]=fma2(AA.y,W1,ACC[1][1]); \
        ACC[1][2]=fma2(AA.y,W2,ACC[1][2]); ACC[1][3]=fma2(AA.y,W3,ACC[1][3]); \
        ACC[2][0]=fma2(AB.x,W0,ACC[2][0]); ACC[2][1]=fma2(AB.x,W1,ACC[2][1]); \
        ACC[2][2]=fma2(AB.x,W2,ACC[2][2]); ACC[2][3]=fma2(AB.x,W3,ACC[2][3]); \
        ACC[3][0]=fma2(AB.y,W0,ACC[3][0]); ACC[3][1]=fma2(AB.y,W1,ACC[3][1]); \
        ACC[3][2]=fma2(AB.y,W2,ACC[3][2]); ACC[3][3]=fma2(AB.y,W3,ACC[3][3]); \
    } while (0)

__global__ void __launch_bounds__(256, 2) node2_kernel(
    const float* __restrict__ W1, const float* __restrict__ b1,
    const float* __restrict__ W2, const float* __restrict__ b2,
    const float* __restrict__ gam, const float* __restrict__ bet)
{
    extern __shared__ float smem[];
    float* sW1 = smem;
    float* sW2 = sW1 + 8192;
    float* sg  = sW2 + 4096;
    float* sbe = sg + 64;
    float* buf = sbe + 64;

    const int tid = threadIdx.x;
    for (int i = tid; i < 8192; i += 256) sW1[i] = W1[i];
    for (int i = tid; i < 4096; i += 256) sW2[i] = W2[i];
    if (tid < 64) { sg[tid] = gam[tid]; sbe[tid] = bet[tid]; }

    const int n0 = blockIdx.x * 128;
    const int tn = tid & 15, tm = tid >> 4;
    const int eg_ = tid & 127;
    const int kq  = (tid >> 7) * 4;

    ull acc[4][4];
    {
        float4 bv = *(const float4*)(b1 + tn * 4);
#pragma unroll
        for (int ep = 0; ep < 4; ++ep) {
            acc[ep][0] = dup2(bv.x); acc[ep][1] = dup2(bv.y);
            acc[ep][2] = dup2(bv.z); acc[ep][3] = dup2(bv.w);
        }
    }

    int ngi = n0 + eg_;
    if (ngi >= NNODES) ngi = 0;

#pragma unroll
    for (int ch = 0; ch < 2; ++ch) {
        const float* srcp = (ch == 0) ? g_h : g_agg;
        const float4* hp = (const float4*)(srcp + (ull)ngi * 64);
        __syncthreads();
#pragma unroll
        for (int r = 0; r < 8; ++r) {
            int k = r * 8 + kq;
            float4 v = hp[2 * r + (kq >> 2)];
            buf[(k + 0) * 128 + eg_] = v.x;
            buf[(k + 1) * 128 + eg_] = v.y;
            buf[(k + 2) * 128 + eg_] = v.z;
            buf[(k + 3) * 128 + eg_] = v.w;
        }
        __syncthreads();
        const float* wbase = sW1 + ch * 64 * 64;
#pragma unroll 2
        for (int k = 0; k < 64; ++k) {
            const ulonglong2* ar = (const ulonglong2*)(buf + k * 128 + tm * 8);
            ulonglong2 aA = ar[0], aB = ar[1];
            float4 wv = *(const float4*)(wbase + k * 64 + tn * 4);
            ull w0 = dup2(wv.x), w1 = dup2(wv.y), w2 = dup2(wv.z), w3 = dup2(wv.w);
            FMA16(aA, aB, w0, w1, w2, w3, acc);
        }
    }
    __syncthreads();

#pragma unroll
    for (int ep = 0; ep < 4; ++ep)
#pragma unroll
        for (int j = 0; j < 4; ++j) {
            float x0, x1;
            unpack2(acc[ep][j], x0, x1);
            *(ull*)(buf + (tn * 4 + j) * 132 + tm * 8 + 2 * ep) = pack2(silu_f(x0), silu_f(x1));
        }
    __syncthreads();

    ull acc2[4][4];
    {
        float4 bv = *(const float4*)(b2 + tn * 4);
#pragma unroll
        for (int ep = 0; ep < 4; ++ep) {
            acc2[ep][0] = dup2(bv.x); acc2[ep][1] = dup2(bv.y);
            acc2[ep][2] = dup2(bv.z); acc2[ep][3] = dup2(bv.w);
        }
    }
#pragma unroll 2
    for (int k = 0; k < 64; ++k) {
        const ulonglong2* ar = (const ulonglong2*)(buf + k * 132 + tm * 8);
        ulonglong2 aA = ar[0], aB = ar[1];
        float4 wv = *(const float4*)(sW2 + k * 64 + tn * 4);
        ull w0 = dup2(wv.x), w1 = dup2(wv.y), w2 = dup2(wv.z), w3 = dup2(wv.w);
        FMA16(aA, aB, w0, w1, w2, w3, acc2);
    }
    __syncthreads();

#pragma unroll
    for (int ep = 0; ep < 4; ++ep)
#pragma unroll
        for (int j = 0; j < 4; ++j) {
            float x0, x1;
            unpack2(acc2[ep][j], x0, x1);
            int e = tm * 8 + 2 * ep;
            buf[e * 66 + tn * 4 + j]       = x0;
            buf[(e + 1) * 66 + tn * 4 + j] = x1;
        }
    __syncthreads();

    if (tid < 128 && n0 + tid < NNODES) {
        const float* z = buf + tid * 66;
        float s = 0.f, ss = 0.f;
#pragma unroll 8
        for (int c = 0; c < 64; ++c) { float v = z[c]; s += v; ss += v * v; }
        float m  = s * (1.f / 64.f);
        float rs = rsqrtf(ss * (1.f / 64.f) - m * m + 1e-5f);
        float4* hp = (float4*)(g_h + (ull)(n0 + tid) * 64);
        __half* hs = g_hs + (ull)(n0 + tid) * 128;
#pragma unroll
        for (int q = 0; q < 16; ++q) {
            float4 hv = hp[q];
            hv.x += (z[4 * q + 0] - m) * rs * sg[4 * q + 0] + sbe[4 * q + 0];
            hv.y += (z[4 * q + 1] - m) * rs * sg[4 * q + 1] + sbe[4 * q + 1];
            hv.z += (z[4 * q + 2] - m) * rs * sg[4 * q + 2] + sbe[4 * q + 2];
            hv.w += (z[4 * q + 3] - m) * rs * sg[4 * q + 3] + sbe[4 * q + 3];
            hp[q] = hv;
            __half2 h01 = __float22half2_rn(make_float2(hv.x, hv.y));
            __half2 h23 = __float22half2_rn(make_float2(hv.z, hv.w));
            float2 f01 = __half22float2(h01);
            float2 f23 = __half22float2(h23);
            __half2 l01 = __float22half2_rn(make_float2(hv.x - f01.x, hv.y - f01.y));
            __half2 l23 = __float22half2_rn(make_float2(hv.z - f23.x, hv.w - f23.y));
            *(unsigned*)(hs + 4 * q)     = *(unsigned*)&h01;
            *(unsigned*)(hs + 4 * q + 2) = *(unsigned*)&h23;
            *(unsigned*)(hs + 64 + 4 * q)     = *(unsigned*)&l01;
            *(unsigned*)(hs + 64 + 4 * q + 2) = *(unsigned*)&l23;
        }
    }
}

// ---------------- local decoder ----------------
__global__ void __launch_bounds__(128) dec_local_kernel(
    const float* __restrict__ W1, const float* __restrict__ b1,
    const float* __restrict__ W2, const float* __restrict__ b2,
    float* __restrict__ out)
{
    __shared__ float sW1[64 * 64];
    __shared__ float sW2[64 * 6];
    __shared__ float sb1[64];
    __shared__ float sb2[8];
    __shared__ float sy[4][64];
    int tid = threadIdx.x;
    for (int i = tid; i < 64 * 64; i += 128) sW1[i] = W1[i];
    for (int i = tid; i < 64 * 6; i += 128) sW2[i] = W2[i];
    if (tid < 64) sb1[tid] = b1[tid];
    if (tid < 6)  sb2[tid] = b2[tid];
    __syncthreads();

    int lane = tid & 31, warp = tid >> 5;
    int j0 = lane, j1 = lane + 32;
    for (int n = blockIdx.x * 4 + warp; n < NNODES; n += gridDim.x * 4) {
        const float4* Hr = reinterpret_cast<const float4*>(g_h + n * HID);
        float a0 = sb1[j0], a1 = sb1[j1];
#pragma unroll 4
        for (int c = 0; c < 16; ++c) {
            float4 v = Hr[c];
            const float* w = sW1 + 4 * c * 64;
            a0 = fmaf(v.x, w[j0], a0);           a1 = fmaf(v.x, w[j1], a1);
            a0 = fmaf(v.y, w[64 + j0], a0);      a1 = fmaf(v.y, w[64 + j1], a1);
            a0 = fmaf(v.z, w[128 + j0], a0);     a1 = fmaf(v.z, w[128 + j1], a1);
            a0 = fmaf(v.w, w[192 + j0], a0);     a1 = fmaf(v.w, w[192 + j1], a1);
        }
        a0 = silu_f(a0); a1 = silu_f(a1);
        sy[warp][j0] = a0; sy[warp][j1] = a1;
        __syncwarp();
        if (lane < 6) {
            float o = sb2[lane];
#pragma unroll 8
            for (int k = 0; k < 64; ++k) o = fmaf(sy[warp][k], sW2[k * 6 + lane], o);
            out[n * 6 + lane] = o;
        }
        __syncwarp();
    }
}

// ---------------- pooling ----------------
__global__ void __launch_bounds__(256) pool_kernel(const int* __restrict__ batch)
{
    __shared__ float sacc[NGRAPH * HID];
    __shared__ int   scnt[NGRAPH];
    int tid = threadIdx.x;
    sacc[tid] = 0.f;
    if (tid < NGRAPH) scnt[tid] = 0;
    __syncthreads();
    int j = tid & 63;
    int r = tid >> 6;
    int base = blockIdx.x * 512;
    int end = min(base + 512, NNODES);
    for (int n = base + r; n < end; n += 4) {
        int b = batch[n];
        atomicAdd(&sacc[b * HID + j], g_h[n * HID + j]);
        if (j == 0) atomicAdd(&scnt[b], 1);
    }
    __syncthreads();
    atomicAdd(&g_pooled[tid], sacc[tid]);
    if (tid < NGRAPH) atomicAdd(&g_cnt[tid], scnt[tid]);
}

// ---------------- global decoder ----------------
__global__ void dec_global_kernel(
    const float* __restrict__ W1, const float* __restrict__ b1,
    const float* __restrict__ W2, const float* __restrict__ b2,
    float* __restrict__ out)
{
    __shared__ float sy[NGRAPH][32];
    int g = threadIdx.x >> 5;
    int lane = threadIdx.x & 31;
    float inv = 1.f / fmaxf((float)g_cnt[g], 1.f);
    float a = b1[lane];
#pragma unroll 8
    for (int k = 0; k < 64; ++k)
        a = fmaf(g_pooled[g * HID + k] * inv, W1[k * 32 + lane], a);
    a = silu_f(a);
    sy[g][lane] = a;
    __syncwarp();
    if (lane < 4) {
        float o = b2[lane];
#pragma unroll 8
        for (int k = 0; k < 32; ++k) o = fmaf(sy[g][k], W2[k * 4 + lane], o);
        out[g * 4 + lane] = o;
    }
}

// ---------------- launch ----------------
extern "C" void kernel_launch(void* const* d_in, const int* in_sizes, int n_in,
                              void* d_out, int out_size)
{
    (void)in_sizes; (void)n_in; (void)out_size;
    const float* x      = (const float*)d_in[0];
    const int*   ei     = (const int*)  d_in[1];
    const float* ea     = (const float*)d_in[2];
    const int*   batch  = (const int*)  d_in[3];
    const float* caseP  = (const float*)d_in[4];
    const float* bcP    = (const float*)d_in[5];
    const float* encW1  = (const float*)d_in[6];
    const float* encb1  = (const float*)d_in[7];
    const float* encW2  = (const float*)d_in[8];
    const float* encb2  = (const float*)d_in[9];
    const float* encg   = (const float*)d_in[10];
    const float* encbe  = (const float*)d_in[11];
    const float* eW1    = (const float*)d_in[12];
    const float* eb1    = (const float*)d_in[13];
    const float* eW2    = (const float*)d_in[14];
    const float* eb2    = (const float*)d_in[15];
    const float* egm    = (const float*)d_in[16];
    const float* ebe    = (const float*)d_in[17];
    const float* nW1    = (const float*)d_in[18];
    const float* nb1    = (const float*)d_in[19];
    const float* nW2    = (const float*)d_in[20];
    const float* nb2    = (const float*)d_in[21];
    const float* ngm    = (const float*)d_in[22];
    const float* nbe    = (const float*)d_in[23];
    const float* dlW1   = (const float*)d_in[24];
    const float* dlb1   = (const float*)d_in[25];
    const float* dlW2   = (const float*)d_in[26];
    const float* dlb2   = (const float*)d_in[27];
    const float* dgW1   = (const float*)d_in[28];
    const float* dgb1   = (const float*)d_in[29];
    const float* dgW2   = (const float*)d_in[30];
    const float* dgb2   = (const float*)d_in[31];
    float* out = (float*)d_out;

    const int NODE_SMEM = (8192 + 4096 + 128 + 8448) * 4;
    cudaFuncSetAttribute(edge11_kernel, cudaFuncAttributeMaxDynamicSharedMemorySize, EDGE_SMEM);
    cudaFuncSetAttribute(node2_kernel, cudaFuncAttributeMaxDynamicSharedMemorySize, NODE_SMEM);

    prep_weights<<<(NLAYERS * 12288 + 255) / 256, 256>>>(eW1, eW2);
    encoder_kernel<<<200, 128>>>(x, batch, caseP, bcP,
                                 encW1, encb1, encW2, encb2, encg, encbe);

    const int NODE_GRID = (NNODES + 127) / 128;

    for (int l = 0; l < NLAYERS; ++l) {
        zero_agg_kernel<<<512, 256>>>();
        edge11_kernel<<<296, 128, EDGE_SMEM>>>(
            ei, ea, l,
            eW1 + l * 133 * 64, eb1 + l * 64, eb2 + l * 64,
            egm + l * 64, ebe + l * 64);
        node2_kernel<<<NODE_GRID, 256, NODE_SMEM>>>(
            nW1 + l * 128 * 64, nb1 + l * 64,
            nW2 + l * 64 * 64,  nb2 + l * 64,
            ngm + l * 64,       nbe + l * 64);
    }

    zero_pool_kernel<<<1, 256>>>();
    dec_local_kernel<<<200, 128>>>(dlW1, dlb1, dlW2, dlb2, out);
    pool_kernel<<<(NNODES + 511) / 512, 256>>>(batch);
    dec_global_kernel<<<1, 128>>>(dgW1, dgb1, dgW2, dgb2, out + NNODES * 6);
}

// round 13
// speedup vs baseline: 1.9881x; 1.2547x over previous
#include <cuda_runtime.h>
#include <cuda_fp16.h>

typedef unsigned long long ull;

#define NNODES 50000
#define NEDGES 1600000
#define NGRAPH 4
#define HID    64
#define NLAYERS 5
#define NTILES (NEDGES / 128)   // 12500

// ---------------- device scratch ----------------
__device__ float g_h[NNODES * HID];
__device__ __align__(16) __half g_hs[NNODES * 64];    // per node: 64 fp16 (128 B)
__device__ float g_agg[NNODES * HID];
__device__ float g_pooled[NGRAPH * HID];
__device__ int   g_cnt[NGRAPH];
// per-layer fp16 weights [n][k] stride-144: B1 (2 chunks x 9216) + B2 (9216) = 27648 B
__device__ __align__(16) unsigned char g_wB[NLAYERS * 27648];

// ---------------- SMEM layout (bytes) ----------------
#define OFF_A0   0u        // chunk0: A 128x128B SW128 (16384)
#define OFF_A1   16384u    // chunk1
#define OFF_B1   32768u    // 2 x 9216
#define OFF_B2   51200u    // 9216
#define OFF_T    60416u    // W1 tail rows 128..132 fp32 [5][64] (1280)
#define OFF_BB1  61696u
#define OFF_BB2  61952u
#define OFF_G    62208u
#define OFF_BE   62464u
#define OFF_SDST 62720u    // 2 x 128 ints (1024)
#define OFF_SEA  63744u    // 2 x 640 fp32 (5120)
#define EDGE_SMEM 68864

// ---------------- generic helpers ----------------
__device__ __forceinline__ float silu_f(float x) {
    float t;
    asm("tanh.approx.f32 %0, %1;" : "=f"(t) : "f"(x * 0.5f));
    return x * 0.5f * t + x * 0.5f;
}
__device__ __forceinline__ ull fma2(ull a, ull b, ull c) {
    ull d;
    asm("fma.rn.f32x2 %0, %1, %2, %3;" : "=l"(d) : "l"(a), "l"(b), "l"(c));
    return d;
}
__device__ __forceinline__ ull pack2(float lo, float hi) {
    ull r;
    asm("mov.b64 %0, {%1, %2};" : "=l"(r) : "f"(lo), "f"(hi));
    return r;
}
__device__ __forceinline__ ull dup2(float x) {
    ull r;
    asm("mov.b64 %0, {%1, %1};" : "=l"(r) : "f"(x));
    return r;
}
__device__ __forceinline__ void unpack2(ull v, float& lo, float& hi) {
    asm("mov.b64 {%0, %1}, %2;" : "=f"(lo), "=f"(hi) : "l"(v));
}
__device__ __forceinline__ void red_add4(float* p, float a, float b, float c, float d) {
    asm volatile("red.global.add.v4.f32 [%0], {%1, %2, %3, %4};"
                 :: "l"(p), "f"(a), "f"(b), "f"(c), "f"(d) : "memory");
}
__device__ __forceinline__ unsigned smem_u32(const void* p) {
    unsigned a;
    asm("{ .reg .u64 t; cvta.to.shared.u64 t, %1; cvt.u32.u64 %0, t; }" : "=r"(a) : "l"(p));
    return a;
}

// ---------------- cp.async helpers ----------------
__device__ __forceinline__ void cpasync16(unsigned dst, const void* src) {
    asm volatile("cp.async.cg.shared.global [%0], [%1], 16;" :: "r"(dst), "l"(src) : "memory");
}
#define CP_COMMIT() asm volatile("cp.async.commit_group;" ::: "memory")
#define CP_WAIT1()  asm volatile("cp.async.wait_group 1;" ::: "memory")
#define CP_WAIT0()  asm volatile("cp.async.wait_group 0;" ::: "memory")

// ---------------- mma.sync helpers (fp16 in, fp32 accum) ----------------
__device__ __forceinline__ void ldsm4(unsigned* r, unsigned addr) {
    asm volatile("ldmatrix.sync.aligned.m8n8.x4.shared.b16 {%0,%1,%2,%3}, [%4];"
                 : "=r"(r[0]), "=r"(r[1]), "=r"(r[2]), "=r"(r[3]) : "r"(addr));
}
__device__ __forceinline__ void mma16816(float* c, const unsigned* a, unsigned b0, unsigned b1) {
    asm volatile("mma.sync.aligned.m16n8k16.row.col.f32.f16.f16.f32 "
                 "{%0,%1,%2,%3}, {%4,%5,%6,%7}, {%8,%9}, {%0,%1,%2,%3};"
                 : "+f"(c[0]), "+f"(c[1]), "+f"(c[2]), "+f"(c[3])
                 : "r"(a[0]), "r"(a[1]), "r"(a[2]), "r"(a[3]), "r"(b0), "r"(b1));
}

// ---------------- zero kernels ----------------
__global__ void zero_agg_kernel() {
    int i = blockIdx.x * blockDim.x + threadIdx.x;
    for (; i < NNODES * HID; i += gridDim.x * blockDim.x) g_agg[i] = 0.f;
}
__global__ void zero_pool_kernel() {
    int t = threadIdx.x;
    if (t < NGRAPH * HID) g_pooled[t] = 0.f;
    if (t < NGRAPH) g_cnt[t] = 0;
}

// ---------------- weight prep: fp32 -> fp16, padded [n][k] ----------------
__global__ void prep_weights(const float* __restrict__ eW1, const float* __restrict__ eW2) {
    int idx = blockIdx.x * blockDim.x + threadIdx.x;
    if (idx >= NLAYERS * 12288) return;
    int l = idx / 12288, r = idx % 12288;
    unsigned char* base = g_wB + l * 27648;
    float w;
    unsigned off;
    if (r < 8192) {
        int c = r >> 12, rr = r & 4095, n = rr >> 6, kk = rr & 63;
        w = eW1[l * 133 * 64 + (c * 64 + kk) * 64 + n];
        off = (unsigned)(c * 9216 + n * 144 + kk * 2);
    } else {
        int rr = r - 8192, n = rr >> 6, kk = rr & 63;
        w = eW2[l * 4096 + kk * 64 + n];
        off = (unsigned)(18432 + n * 144 + kk * 2);
    }
    *(__half*)(base + off) = __float2half_rn(w);
}

// ---------------- encoder (also writes fp16 g_hs) ----------------
__global__ void __launch_bounds__(128) encoder_kernel(
    const float* __restrict__ x, const int* __restrict__ batch,
    const float* __restrict__ caseP, const float* __restrict__ bcP,
    const float* __restrict__ W1, const float* __restrict__ b1,
    const float* __restrict__ W2, const float* __restrict__ b2,
    const float* __restrict__ gam, const float* __restrict__ bet)
{
    __shared__ float sW1[16 * 64];
    __shared__ float sW2[64 * 64];
    __shared__ float sb1[64], sb2[64], sg[64], sbe[64];
    __shared__ float sy[4][64];
    int tid = threadIdx.x;
    for (int i = tid; i < 16 * 64; i += 128) sW1[i] = W1[i];
    for (int i = tid; i < 64 * 64; i += 128) sW2[i] = W2[i];
    if (tid < 64) { sb1[tid] = b1[tid]; sb2[tid] = b2[tid]; sg[tid] = gam[tid]; sbe[tid] = bet[tid]; }
    __syncthreads();

    int lane = tid & 31, warp = tid >> 5;
    int j0 = lane, j1 = lane + 32;
    for (int n = blockIdx.x * 4 + warp; n < NNODES; n += gridDim.x * 4) {
        float in[16];
        const float* xr = x + n * 8;
#pragma unroll
        for (int k = 0; k < 8; ++k) in[k] = xr[k];
        int b = batch[n];
#pragma unroll
        for (int k = 0; k < 4; ++k) in[8 + k]  = caseP[b * 4 + k];
#pragma unroll
        for (int k = 0; k < 4; ++k) in[12 + k] = bcP[b * 4 + k];

        float a0 = sb1[j0], a1 = sb1[j1];
#pragma unroll
        for (int k = 0; k < 16; ++k) {
            a0 = fmaf(in[k], sW1[k * 64 + j0], a0);
            a1 = fmaf(in[k], sW1[k * 64 + j1], a1);
        }
        a0 = silu_f(a0); a1 = silu_f(a1);
        sy[warp][j0] = a0; sy[warp][j1] = a1;
        __syncwarp();
        float z0 = sb2[j0], z1 = sb2[j1];
#pragma unroll 4
        for (int k = 0; k < 64; ++k) {
            float v = sy[warp][k];
            z0 = fmaf(v, sW2[k * 64 + j0], z0);
            z1 = fmaf(v, sW2[k * 64 + j1], z1);
        }
        float s = z0 + z1, ss = z0 * z0 + z1 * z1;
#pragma unroll
        for (int o = 16; o > 0; o >>= 1) {
            s  += __shfl_xor_sync(0xffffffffu, s, o);
            ss += __shfl_xor_sync(0xffffffffu, ss, o);
        }
        float m = s * (1.f / 64.f);
        float rs = rsqrtf(ss * (1.f / 64.f) - m * m + 1e-5f);
        float v0 = (z0 - m) * rs * sg[j0] + sbe[j0];
        float v1 = (z1 - m) * rs * sg[j1] + sbe[j1];
        g_h[n * HID + j0] = v0;
        g_h[n * HID + j1] = v1;
        g_hs[n * 64 + j0] = __float2half_rn(v0);
        g_hs[n * 64 + j1] = __float2half_rn(v1);
        __syncwarp();
    }
}

// ---------------- edge MLP v12: pure fp16, 3 CTAs/SM, cp.async pipeline ----------------
__global__ void __launch_bounds__(128, 3) edge12_kernel(
    const int* __restrict__ ei, const float* __restrict__ ea, int layer,
    const float* __restrict__ W1full, const float* __restrict__ b1,
    const float* __restrict__ b2,
    const float* __restrict__ gam, const float* __restrict__ bet)
{
    extern __shared__ unsigned char sm[];
    const unsigned sbase = smem_u32(sm);
    const int tid = threadIdx.x;
    const int lane = tid & 31, warp = tid >> 5;
    const int gID = lane >> 2, tig = lane & 3;
    const int lt = lane >> 3, lr = lane & 7;

    // --- one-time loads ---
    {
        const uint4* srcw = (const uint4*)(g_wB + layer * 27648);
        uint4* dstw = (uint4*)(sm + OFF_B1);
#pragma unroll 4
        for (int i = tid; i < 1728; i += 128) dstw[i] = srcw[i];
    }
    for (int i = tid; i < 320; i += 128) ((float*)(sm + OFF_T))[i] = W1full[128 * 64 + i];
    if (tid < 64) {
        ((float*)(sm + OFF_BB1))[tid] = b1[tid];
        ((float*)(sm + OFF_BB2))[tid] = b2[tid];
        ((float*)(sm + OFF_G))[tid]   = gam[tid];
        ((float*)(sm + OFF_BE))[tid]  = bet[tid];
    }

    // A ldsm addressing (SW128-swizzled, 128B rows)
    const unsigned aOff = (unsigned)((warp * 32 + (lt & 1) * 8 + lr) * 128
                                     + ((unsigned)((lt >> 1) << 4) ^ ((unsigned)lr << 4)));
    const unsigned bLane = (unsigned)(((lt >> 1) * 8 + lr) * 144 + ((lt & 1) << 4));
    const float* bb1 = (const float*)(sm + OFF_BB1);
    int* sdst_all = (int*)(sm + OFF_SDST);
    float* sea_all = (float*)(sm + OFF_SEA);

    // gather lane mapping: 4 rows per warp-instr (8 lanes per 128B row)
    const int grow = warp * 32 + (lane >> 3);       // step 4
    const int cp = lane & 7;                        // 16B chunk within 128B node row
    const unsigned gcol = (unsigned)(cp * 16);

    // --- prologue: stage tables(t0) + launch both gathers of t0 ---
    const int t0 = blockIdx.x;
    {
        const int e0 = t0 * 128;
        sdst_all[tid] = ei[NEDGES + e0 + tid];
        for (int i = tid; i < 640; i += 128) sea_all[i] = ea[(ull)e0 * 5 + i];
#pragma unroll
        for (int i = 0; i < 8; ++i) {
            int row = grow + 4 * i;
            int node = ei[NEDGES + e0 + row];
            cpasync16(sbase + OFF_A0 + (unsigned)(row * 128)
                          + (gcol ^ (((unsigned)row & 7u) << 4)),
                      (const unsigned char*)g_hs + (ull)node * 128 + cp * 16);
        }
        CP_COMMIT();
#pragma unroll
        for (int i = 0; i < 8; ++i) {
            int row = grow + 4 * i;
            int node = ei[e0 + row];
            cpasync16(sbase + OFF_A1 + (unsigned)(row * 128)
                          + (gcol ^ (((unsigned)row & 7u) << 4)),
                      (const unsigned char*)g_hs + (ull)node * 128 + cp * 16);
        }
        CP_COMMIT();
    }

    int it = 0;
    for (int t = t0; t < NTILES; t += gridDim.x, ++it) {
        const int p = it & 1;
        const int* sdst = sdst_all + p * 128;
        const float* sea = sea_all + p * 640;

        // next tile (clamped -> redundant copy, results unused)
        int tn = t + gridDim.x;
        if (tn >= NTILES) tn = t;
        const int e0n = tn * 128;

        // acc init with b1
        float acc[2][8][4];
#pragma unroll
        for (int nt = 0; nt < 8; ++nt) {
            float2 bv = *(const float2*)(bb1 + nt * 8 + 2 * tig);
#pragma unroll
            for (int mt = 0; mt < 2; ++mt) {
                acc[mt][nt][0] = bv.x; acc[mt][nt][1] = bv.y;
                acc[mt][nt][2] = bv.x; acc[mt][nt][3] = bv.y;
            }
        }

        // ===== wait buf0 (chunk0) + MMA =====
        CP_WAIT1();
        __syncthreads();
        {
            const unsigned bB = sbase + OFF_B1 + bLane;
#pragma unroll
            for (int kt = 0; kt < 4; ++kt) {
                const unsigned kx = (unsigned)(kt * 32);
                unsigned a0[4], a1[4];
                ldsm4(a0, sbase + OFF_A0 + (aOff ^ kx));
                ldsm4(a1, sbase + OFF_A0 + ((aOff + 2048u) ^ kx));
                unsigned bf[4][4];
#pragma unroll
                for (int q = 0; q < 4; ++q) ldsm4(bf[q], bB + q * 2304u + kx);
#pragma unroll
                for (int q = 0; q < 4; ++q) {
                    mma16816(acc[0][2 * q],     a0, bf[q][0], bf[q][1]);
                    mma16816(acc[0][2 * q + 1], a0, bf[q][2], bf[q][3]);
                    mma16816(acc[1][2 * q],     a1, bf[q][0], bf[q][1]);
                    mma16816(acc[1][2 * q + 1], a1, bf[q][2], bf[q][3]);
                }
            }
        }
        __syncthreads();   // all warps done reading buf0

        // stage next tables + issue chunk0(next) -> buf0
        sdst_all[(p ^ 1) * 128 + tid] = ei[NEDGES + e0n + tid];
        for (int i = tid; i < 640; i += 128) sea_all[(p ^ 1) * 640 + i] = ea[(ull)e0n * 5 + i];
#pragma unroll
        for (int i = 0; i < 8; ++i) {
            int row = grow + 4 * i;
            int node = ei[NEDGES + e0n + row];
            cpasync16(sbase + OFF_A0 + (unsigned)(row * 128)
                          + (gcol ^ (((unsigned)row & 7u) << 4)),
                      (const unsigned char*)g_hs + (ull)node * 128 + cp * 16);
        }
        CP_COMMIT();

        // ===== wait buf1 (chunk1) + MMA =====
        CP_WAIT1();
        __syncthreads();
        {
            const unsigned bB = sbase + OFF_B1 + 9216u + bLane;
#pragma unroll
            for (int kt = 0; kt < 4; ++kt) {
                const unsigned kx = (unsigned)(kt * 32);
                unsigned a0[4], a1[4];
                ldsm4(a0, sbase + OFF_A1 + (aOff ^ kx));
                ldsm4(a1, sbase + OFF_A1 + ((aOff + 2048u) ^ kx));
                unsigned bf[4][4];
#pragma unroll
                for (int q = 0; q < 4; ++q) ldsm4(bf[q], bB + q * 2304u + kx);
#pragma unroll
                for (int q = 0; q < 4; ++q) {
                    mma16816(acc[0][2 * q],     a0, bf[q][0], bf[q][1]);
                    mma16816(acc[0][2 * q + 1], a0, bf[q][2], bf[q][3]);
                    mma16816(acc[1][2 * q],     a1, bf[q][0], bf[q][1]);
                    mma16816(acc[1][2 * q + 1], a1, bf[q][2], bf[q][3]);
                }
            }
        }

        // ===== epilogue1 (registers): fp32 edge_attr tail + silu -> fp16 =====
        float eav[2][2][5];
#pragma unroll
        for (int mt = 0; mt < 2; ++mt)
#pragma unroll
            for (int h = 0; h < 2; ++h) {
                const float* er = sea + (warp * 32 + mt * 16 + h * 8 + gID) * 5;
#pragma unroll
                for (int j = 0; j < 5; ++j) eav[mt][h][j] = er[j];
            }
        unsigned uh[2][2][8];
#pragma unroll
        for (int nt = 0; nt < 8; ++nt) {
            float2 w[5];
#pragma unroll
            for (int j = 0; j < 5; ++j)
                w[j] = *(const float2*)(sm + OFF_T + (unsigned)((j * 64 + nt * 8 + tig * 2) * 4));
#pragma unroll
            for (int mt = 0; mt < 2; ++mt)
#pragma unroll
                for (int h = 0; h < 2; ++h) {
                    float y0 = acc[mt][nt][2 * h], y1 = acc[mt][nt][2 * h + 1];
#pragma unroll
                    for (int j = 0; j < 5; ++j) {
                        y0 = fmaf(eav[mt][h][j], w[j].x, y0);
                        y1 = fmaf(eav[mt][h][j], w[j].y, y1);
                    }
                    __half2 hb = __float22half2_rn(make_float2(silu_f(y0), silu_f(y1)));
                    uh[mt][h][nt] = *(unsigned*)&hb;
                }
        }

        // ===== GEMM2 (A from registers, single pass) =====
        float acc2[2][8][4];
#pragma unroll
        for (int nt = 0; nt < 8; ++nt) {
            float2 bv = *(const float2*)(sm + OFF_BB2 + (unsigned)((nt * 8 + tig * 2) * 4));
#pragma unroll
            for (int mt = 0; mt < 2; ++mt) {
                acc2[mt][nt][0] = bv.x; acc2[mt][nt][1] = bv.y;
                acc2[mt][nt][2] = bv.x; acc2[mt][nt][3] = bv.y;
            }
        }
        const unsigned b2B = sbase + OFF_B2 + bLane;
#pragma unroll
        for (int kt = 0; kt < 4; ++kt) {
            unsigned bf[4][4];
#pragma unroll
            for (int q = 0; q < 4; ++q) ldsm4(bf[q], b2B + q * 2304u + kt * 32u);
            unsigned ah0[4] = {uh[0][0][2 * kt], uh[0][1][2 * kt], uh[0][0][2 * kt + 1], uh[0][1][2 * kt + 1]};
            unsigned ah1[4] = {uh[1][0][2 * kt], uh[1][1][2 * kt], uh[1][0][2 * kt + 1], uh[1][1][2 * kt + 1]};
#pragma unroll
            for (int q = 0; q < 4; ++q) {
                mma16816(acc2[0][2 * q],     ah0, bf[q][0], bf[q][1]);
                mma16816(acc2[0][2 * q + 1], ah0, bf[q][2], bf[q][3]);
                mma16816(acc2[1][2 * q],     ah1, bf[q][0], bf[q][1]);
                mma16816(acc2[1][2 * q + 1], ah1, bf[q][2], bf[q][3]);
            }
        }
        __syncthreads();   // all warps done reading buf1

        // issue chunk1(next) -> buf1 (overlaps with epilogue2)
#pragma unroll
        for (int i = 0; i < 8; ++i) {
            int row = grow + 4 * i;
            int node = ei[e0n + row];
            cpasync16(sbase + OFF_A1 + (unsigned)(row * 128)
                          + (gcol ^ (((unsigned)row & 7u) << 4)),
                      (const unsigned char*)g_hs + (ull)node * 128 + cp * 16);
        }
        CP_COMMIT();

        // ===== epilogue2: LayerNorm (shuffles) + scatter (red.v4) =====
        float mArr[2][2], rsArr[2][2];
#pragma unroll
        for (int mt = 0; mt < 2; ++mt)
#pragma unroll
            for (int h = 0; h < 2; ++h) {
                float s = 0.f, ssum = 0.f;
#pragma unroll
                for (int nt = 0; nt < 8; ++nt) {
                    float v0 = acc2[mt][nt][2 * h], v1 = acc2[mt][nt][2 * h + 1];
                    s += v0 + v1; ssum += v0 * v0 + v1 * v1;
                }
                s    += __shfl_xor_sync(0xffffffffu, s, 1);
                ssum += __shfl_xor_sync(0xffffffffu, ssum, 1);
                s    += __shfl_xor_sync(0xffffffffu, s, 2);
                ssum += __shfl_xor_sync(0xffffffffu, ssum, 2);
                float m = s * (1.f / 64.f);
                mArr[mt][h]  = m;
                rsArr[mt][h] = rsqrtf(ssum * (1.f / 64.f) - m * m + 1e-5f);
            }
        const int cq = (tig & 1) * 2 + (tig >> 1);
        float4 gq[4], beq[4];
#pragma unroll
        for (int j = 0; j < 4; ++j) {
            gq[j]  = ((const float4*)(sm + OFF_G))[4 * j + cq];
            beq[j] = ((const float4*)(sm + OFF_BE))[4 * j + cq];
        }
        const unsigned colb = (unsigned)((tig & 1) * 8 + (tig >> 1) * 4);
#pragma unroll
        for (int mt = 0; mt < 2; ++mt)
#pragma unroll
            for (int h = 0; h < 2; ++h) {
                int row = warp * 32 + mt * 16 + h * 8 + gID;
                float* ag = g_agg + (ull)sdst[row] * 64 + colb;
                float m = mArr[mt][h], rs = rsArr[mt][h];
#pragma unroll
                for (int j = 0; j < 4; ++j) {
                    ull p0 = pack2(acc2[mt][2 * j][2 * h],     acc2[mt][2 * j][2 * h + 1]);
                    ull p1 = pack2(acc2[mt][2 * j + 1][2 * h], acc2[mt][2 * j + 1][2 * h + 1]);
                    ull sel = (tig & 1) ? p0 : p1;
                    ull rv = __shfl_xor_sync(0xffffffffu, sel, 1);
                    float q0, q1, q2, q3;
                    if (tig & 1) { unpack2(rv, q0, q1); unpack2(p1, q2, q3); }
                    else         { unpack2(p0, q0, q1); unpack2(rv, q2, q3); }
                    float o0 = (q0 - m) * rs * gq[j].x + beq[j].x;
                    float o1 = (q1 - m) * rs * gq[j].y + beq[j].y;
                    float o2 = (q2 - m) * rs * gq[j].z + beq[j].z;
                    float o3 = (q3 - m) * rs * gq[j].w + beq[j].w;
                    red_add4(ag + 16 * j, o0, o1, o2, o3);
                }
            }
    }
    CP_WAIT0();
}

// ---------------- node MLP (fp32 register-tiled; also writes fp16 g_hs) ----------------
#define FMA16(AA, AB, W0, W1, W2, W3, ACC)                               \
    do {                                                                 \
        ACC[0][0]=fma2(AA.x,W0,ACC[0][0]); ACC[0][1]=fma2(AA.x,W1,ACC[0][1]); \
        ACC[0][2]=fma2(AA.x,W2,ACC[0][2]); ACC[0][3]=fma2(AA.x,W3,ACC[0][3]); \
        ACC[1][0]=fma2(AA.y,W0,ACC[1][0]); ACC[1][1]=fma2(AA.y,W1,ACC[1][1]); \
        ACC[1][2]=fma2(AA.y,W2,ACC[1][2]); ACC[1][3]=fma2(AA.y,W3,ACC[1][3]); \
        ACC[2][0]=fma2(AB.x,W0,ACC[2][0]); ACC[2][1]=fma2(AB.x,W1,ACC[2][1]); \
        ACC[2][2]=fma2(AB.x,W2,ACC[2][2]); ACC[2][3]=fma2(AB.x,W3,ACC[2][3]); \
        ACC[3][0]=fma2(AB.y,W0,ACC[3][0]); ACC[3][1]=fma2(AB.y,W1,ACC[3][1]); \
        ACC[3][2]=fma2(AB.y,W2,ACC[3][2]); ACC[3][3]=fma2(AB.y,W3,ACC[3][3]); \
    } while (0)

__global__ void __launch_bounds__(256, 2) node2_kernel(
    const float* __restrict__ W1, const float* __restrict__ b1,
    const float* __restrict__ W2, const float* __restrict__ b2,
    const float* __restrict__ gam, const float* __restrict__ bet)
{
    extern __shared__ float smem[];
    float* sW1 = smem;
    float* sW2 = sW1 + 8192;
    float* sg  = sW2 + 4096;
    float* sbe = sg + 64;
    float* buf = sbe + 64;

    const int tid = threadIdx.x;
    for (int i = tid; i < 8192; i += 256) sW1[i] = W1[i];
    for (int i = tid; i < 4096; i += 256) sW2[i] = W2[i];
    if (tid < 64) { sg[tid] = gam[tid]; sbe[tid] = bet[tid]; }

    const int n0 = blockIdx.x * 128;
    const int tn = tid & 15, tm = tid >> 4;
    const int eg_ = tid & 127;
    const int kq  = (tid >> 7) * 4;

    ull acc[4][4];
    {
        float4 bv = *(const float4*)(b1 + tn * 4);
#pragma unroll
        for (int ep = 0; ep < 4; ++ep) {
            acc[ep][0] = dup2(bv.x); acc[ep][1] = dup2(bv.y);
            acc[ep][2] = dup2(bv.z); acc[ep][3] = dup2(bv.w);
        }
    }

    int ngi = n0 + eg_;
    if (ngi >= NNODES) ngi = 0;

#pragma unroll
    for (int ch = 0; ch < 2; ++ch) {
        const float* srcp = (ch == 0) ? g_h : g_agg;
        const float4* hp = (const float4*)(srcp + (ull)ngi * 64);
        __syncthreads();
#pragma unroll
        for (int r = 0; r < 8; ++r) {
            int k = r * 8 + kq;
            float4 v = hp[2 * r + (kq >> 2)];
            buf[(k + 0) * 128 + eg_] = v.x;
            buf[(k + 1) * 128 + eg_] = v.y;
            buf[(k + 2) * 128 + eg_] = v.z;
            buf[(k + 3) * 128 + eg_] = v.w;
        }
        __syncthreads();
        const float* wbase = sW1 + ch * 64 * 64;
#pragma unroll 2
        for (int k = 0; k < 64; ++k) {
            const ulonglong2* ar = (const ulonglong2*)(buf + k * 128 + tm * 8);
            ulonglong2 aA = ar[0], aB = ar[1];
            float4 wv = *(const float4*)(wbase + k * 64 + tn * 4);
            ull w0 = dup2(wv.x), w1 = dup2(wv.y), w2 = dup2(wv.z), w3 = dup2(wv.w);
            FMA16(aA, aB, w0, w1, w2, w3, acc);
        }
    }
    __syncthreads();

#pragma unroll
    for (int ep = 0; ep < 4; ++ep)
#pragma unroll
        for (int j = 0; j < 4; ++j) {
            float x0, x1;
            unpack2(acc[ep][j], x0, x1);
            *(ull*)(buf + (tn * 4 + j) * 132 + tm * 8 + 2 * ep) = pack2(silu_f(x0), silu_f(x1));
        }
    __syncthreads();

    ull acc2[4][4];
    {
        float4 bv = *(const float4*)(b2 + tn * 4);
#pragma unroll
        for (int ep = 0; ep < 4; ++ep) {
            acc2[ep][0] = dup2(bv.x); acc2[ep][1] = dup2(bv.y);
            acc2[ep][2] = dup2(bv.z); acc2[ep][3] = dup2(bv.w);
        }
    }
#pragma unroll 2
    for (int k = 0; k < 64; ++k) {
        const ulonglong2* ar = (const ulonglong2*)(buf + k * 132 + tm * 8);
        ulonglong2 aA = ar[0], aB = ar[1];
        float4 wv = *(const float4*)(sW2 + k * 64 + tn * 4);
        ull w0 = dup2(wv.x), w1 = dup2(wv.y), w2 = dup2(wv.z), w3 = dup2(wv.w);
        FMA16(aA, aB, w0, w1, w2, w3, acc2);
    }
    __syncthreads();

#pragma unroll
    for (int ep = 0; ep < 4; ++ep)
#pragma unroll
        for (int j = 0; j < 4; ++j) {
            float x0, x1;
            unpack2(acc2[ep][j], x0, x1);
            int e = tm * 8 + 2 * ep;
            buf[e * 66 + tn * 4 + j]       = x0;
            buf[(e + 1) * 66 + tn * 4 + j] = x1;
        }
    __syncthreads();

    if (tid < 128 && n0 + tid < NNODES) {
        const float* z = buf + tid * 66;
        float s = 0.f, ss = 0.f;
#pragma unroll 8
        for (int c = 0; c < 64; ++c) { float v = z[c]; s += v; ss += v * v; }
        float m  = s * (1.f / 64.f);
        float rs = rsqrtf(ss * (1.f / 64.f) - m * m + 1e-5f);
        float4* hp = (float4*)(g_h + (ull)(n0 + tid) * 64);
        __half* hs = g_hs + (ull)(n0 + tid) * 64;
#pragma unroll
        for (int q = 0; q < 16; ++q) {
            float4 hv = hp[q];
            hv.x += (z[4 * q + 0] - m) * rs * sg[4 * q + 0] + sbe[4 * q + 0];
            hv.y += (z[4 * q + 1] - m) * rs * sg[4 * q + 1] + sbe[4 * q + 1];
            hv.z += (z[4 * q + 2] - m) * rs * sg[4 * q + 2] + sbe[4 * q + 2];
            hv.w += (z[4 * q + 3] - m) * rs * sg[4 * q + 3] + sbe[4 * q + 3];
            hp[q] = hv;
            __half2 h01 = __float22half2_rn(make_float2(hv.x, hv.y));
            __half2 h23 = __float22half2_rn(make_float2(hv.z, hv.w));
            *(unsigned*)(hs + 4 * q)     = *(unsigned*)&h01;
            *(unsigned*)(hs + 4 * q + 2) = *(unsigned*)&h23;
        }
    }
}

// ---------------- local decoder ----------------
__global__ void __launch_bounds__(128) dec_local_kernel(
    const float* __restrict__ W1, const float* __restrict__ b1,
    const float* __restrict__ W2, const float* __restrict__ b2,
    float* __restrict__ out)
{
    __shared__ float sW1[64 * 64];
    __shared__ float sW2[64 * 6];
    __shared__ float sb1[64];
    __shared__ float sb2[8];
    __shared__ float sy[4][64];
    int tid = threadIdx.x;
    for (int i = tid; i < 64 * 64; i += 128) sW1[i] = W1[i];
    for (int i = tid; i < 64 * 6; i += 128) sW2[i] = W2[i];
    if (tid < 64) sb1[tid] = b1[tid];
    if (tid < 6)  sb2[tid] = b2[tid];
    __syncthreads();

    int lane = tid & 31, warp = tid >> 5;
    int j0 = lane, j1 = lane + 32;
    for (int n = blockIdx.x * 4 + warp; n < NNODES; n += gridDim.x * 4) {
        const float4* Hr = reinterpret_cast<const float4*>(g_h + n * HID);
        float a0 = sb1[j0], a1 = sb1[j1];
#pragma unroll 4
        for (int c = 0; c < 16; ++c) {
            float4 v = Hr[c];
            const float* w = sW1 + 4 * c * 64;
            a0 = fmaf(v.x, w[j0], a0);           a1 = fmaf(v.x, w[j1], a1);
            a0 = fmaf(v.y, w[64 + j0], a0);      a1 = fmaf(v.y, w[64 + j1], a1);
            a0 = fmaf(v.z, w[128 + j0], a0);     a1 = fmaf(v.z, w[128 + j1], a1);
            a0 = fmaf(v.w, w[192 + j0], a0);     a1 = fmaf(v.w, w[192 + j1], a1);
        }
        a0 = silu_f(a0); a1 = silu_f(a1);
        sy[warp][j0] = a0; sy[warp][j1] = a1;
        __syncwarp();
        if (lane < 6) {
            float o = sb2[lane];
#pragma unroll 8
            for (int k = 0; k < 64; ++k) o = fmaf(sy[warp][k], sW2[k * 6 + lane], o);
            out[n * 6 + lane] = o;
        }
        __syncwarp();
    }
}

// ---------------- pooling ----------------
__global__ void __launch_bounds__(256) pool_kernel(const int* __restrict__ batch)
{
    __shared__ float sacc[NGRAPH * HID];
    __shared__ int   scnt[NGRAPH];
    int tid = threadIdx.x;
    sacc[tid] = 0.f;
    if (tid < NGRAPH) scnt[tid] = 0;
    __syncthreads();
    int j = tid & 63;
    int r = tid >> 6;
    int base = blockIdx.x * 512;
    int end = min(base + 512, NNODES);
    for (int n = base + r; n < end; n += 4) {
        int b = batch[n];
        atomicAdd(&sacc[b * HID + j], g_h[n * HID + j]);
        if (j == 0) atomicAdd(&scnt[b], 1);
    }
    __syncthreads();
    atomicAdd(&g_pooled[tid], sacc[tid]);
    if (tid < NGRAPH) atomicAdd(&g_cnt[tid], scnt[tid]);
}

// ---------------- global decoder ----------------
__global__ void dec_global_kernel(
    const float* __restrict__ W1, const float* __restrict__ b1,
    const float* __restrict__ W2, const float* __restrict__ b2,
    float* __restrict__ out)
{
    __shared__ float sy[NGRAPH][32];
    int g = threadIdx.x >> 5;
    int lane = threadIdx.x & 31;
    float inv = 1.f / fmaxf((float)g_cnt[g], 1.f);
    float a = b1[lane];
#pragma unroll 8
    for (int k = 0; k < 64; ++k)
        a = fmaf(g_pooled[g * HID + k] * inv, W1[k * 32 + lane], a);
    a = silu_f(a);
    sy[g][lane] = a;
    __syncwarp();
    if (lane < 4) {
        float o = b2[lane];
#pragma unroll 8
        for (int k = 0; k < 32; ++k) o = fmaf(sy[g][k], W2[k * 4 + lane], o);
        out[g * 4 + lane] = o;
    }
}

// ---------------- launch ----------------
extern "C" void kernel_launch(void* const* d_in, const int* in_sizes, int n_in,
                              void* d_out, int out_size)
{
    (void)in_sizes; (void)n_in; (void)out_size;
    const float* x      = (const float*)d_in[0];
    const int*   ei     = (const int*)  d_in[1];
    const float* ea     = (const float*)d_in[2];
    const int*   batch  = (const int*)  d_in[3];
    const float* caseP  = (const float*)d_in[4];
    const float* bcP    = (const float*)d_in[5];
    const float* encW1  = (const float*)d_in[6];
    const float* encb1  = (const float*)d_in[7];
    const float* encW2  = (const float*)d_in[8];
    const float* encb2  = (const float*)d_in[9];
    const float* encg   = (const float*)d_in[10];
    const float* encbe  = (const float*)d_in[11];
    const float* eW1    = (const float*)d_in[12];
    const float* eb1    = (const float*)d_in[13];
    const float* eW2    = (const float*)d_in[14];
    const float* eb2    = (const float*)d_in[15];
    const float* egm    = (const float*)d_in[16];
    const float* ebe    = (const float*)d_in[17];
    const float* nW1    = (const float*)d_in[18];
    const float* nb1    = (const float*)d_in[19];
    const float* nW2    = (const float*)d_in[20];
    const float* nb2    = (const float*)d_in[21];
    const float* ngm    = (const float*)d_in[22];
    const float* nbe    = (const float*)d_in[23];
    const float* dlW1   = (const float*)d_in[24];
    const float* dlb1   = (const float*)d_in[25];
    const float* dlW2   = (const float*)d_in[26];
    const float* dlb2   = (const float*)d_in[27];
    const float* dgW1   = (const float*)d_in[28];
    const float* dgb1   = (const float*)d_in[29];
    const float* dgW2   = (const float*)d_in[30];
    const float* dgb2   = (const float*)d_in[31];
    float* out = (float*)d_out;

    const int NODE_SMEM = (8192 + 4096 + 128 + 8448) * 4;
    cudaFuncSetAttribute(edge12_kernel, cudaFuncAttributeMaxDynamicSharedMemorySize, EDGE_SMEM);
    cudaFuncSetAttribute(node2_kernel, cudaFuncAttributeMaxDynamicSharedMemorySize, NODE_SMEM);

    prep_weights<<<(NLAYERS * 12288 + 255) / 256, 256>>>(eW1, eW2);
    encoder_kernel<<<200, 128>>>(x, batch, caseP, bcP,
                                 encW1, encb1, encW2, encb2, encg, encbe);

    const int NODE_GRID = (NNODES + 127) / 128;

    for (int l = 0; l < NLAYERS; ++l) {
        zero_agg_kernel<<<512, 256>>>();
        edge12_kernel<<<444, 128, EDGE_SMEM>>>(
            ei, ea, l,
            eW1 + l * 133 * 64, eb1 + l * 64, eb2 + l * 64,
            egm + l * 64, ebe + l * 64);
        node2_kernel<<<NODE_GRID, 256, NODE_SMEM>>>(
            nW1 + l * 128 * 64, nb1 + l * 64,
            nW2 + l * 64 * 64,  nb2 + l * 64,
            ngm + l * 64,       nbe + l * 64);
    }

    zero_pool_kernel<<<1, 256>>>();
    dec_local_kernel<<<200, 128>>>(dlW1, dlb1, dlW2, dlb2, out);
    pool_kernel<<<(NNODES + 511) / 512, 256>>>(batch);
    dec_global_kernel<<<1, 128>>>(dgW1, dgb1, dgW2, dgb2, out + NNODES * 6);
}

// round 14
// speedup vs baseline: 2.2785x; 1.1460x over previous
#include <cuda_runtime.h>
#include <cuda_fp16.h>

typedef unsigned long long ull;

#define NNODES 50000
#define NEDGES 1600000
#define NGRAPH 4
#define HID    64
#define NLAYERS 5
#define NTILES (NEDGES / 128)   // 12500
#define NTILE_N ((NNODES + 127) / 128)  // 391

// ---------------- device scratch ----------------
__device__ float g_h[NNODES * HID];
__device__ __align__(16) __half g_hs[NNODES * 64];    // per node: 64 fp16 (128 B)
__device__ float g_agg[NNODES * HID];
__device__ float g_pooled[NGRAPH * HID];
__device__ int   g_cnt[NGRAPH];
// per-layer fp16 weights [n][k] stride-144: B1 (2 chunks x 9216) + B2 (9216) = 27648 B
__device__ __align__(16) unsigned char g_wB[NLAYERS * 27648];  // edge
__device__ __align__(16) unsigned char g_wN[NLAYERS * 27648];  // node

// ---------------- SMEM layout: edge kernel (bytes) ----------------
#define OFF_A0   0u        // chunk0: A 128x128B SW128 (16384)
#define OFF_A1   16384u    // chunk1
#define OFF_B1   32768u    // 2 x 9216
#define OFF_B2   51200u    // 9216
#define OFF_T    60416u    // W1 tail rows 128..132 fp32 [5][64] (1280)
#define OFF_BB1  61696u
#define OFF_BB2  61952u
#define OFF_G    62208u
#define OFF_BE   62464u
#define OFF_SDST 62720u    // 2 x 128 ints (1024)
#define OFF_SEA  63744u    // 2 x 640 fp32 (5120)
#define EDGE_SMEM 68864

// ---------------- SMEM layout: node kernel (bytes) ----------------
#define NOFF_A   0u        // A 128x128B SW128 (16384)
#define NOFF_B1  16384u    // 2 x 9216
#define NOFF_B2  34816u    // 9216
#define NOFF_BB1 44032u
#define NOFF_BB2 44288u
#define NOFF_G   44544u
#define NOFF_BE  44800u
#define NODE3_SMEM 45056

// ---------------- generic helpers ----------------
__device__ __forceinline__ float silu_f(float x) {
    float t;
    asm("tanh.approx.f32 %0, %1;" : "=f"(t) : "f"(x * 0.5f));
    return x * 0.5f * t + x * 0.5f;
}
__device__ __forceinline__ ull pack2(float lo, float hi) {
    ull r;
    asm("mov.b64 %0, {%1, %2};" : "=l"(r) : "f"(lo), "f"(hi));
    return r;
}
__device__ __forceinline__ void unpack2(ull v, float& lo, float& hi) {
    asm("mov.b64 {%0, %1}, %2;" : "=f"(lo), "=f"(hi) : "l"(v));
}
__device__ __forceinline__ void red_add4(float* p, float a, float b, float c, float d) {
    asm volatile("red.global.add.v4.f32 [%0], {%1, %2, %3, %4};"
                 :: "l"(p), "f"(a), "f"(b), "f"(c), "f"(d) : "memory");
}
__device__ __forceinline__ unsigned smem_u32(const void* p) {
    unsigned a;
    asm("{ .reg .u64 t; cvta.to.shared.u64 t, %1; cvt.u32.u64 %0, t; }" : "=r"(a) : "l"(p));
    return a;
}

// ---------------- cp.async helpers ----------------
__device__ __forceinline__ void cpasync16(unsigned dst, const void* src) {
    asm volatile("cp.async.cg.shared.global [%0], [%1], 16;" :: "r"(dst), "l"(src) : "memory");
}
#define CP_COMMIT() asm volatile("cp.async.commit_group;" ::: "memory")
#define CP_WAIT1()  asm volatile("cp.async.wait_group 1;" ::: "memory")
#define CP_WAIT0()  asm volatile("cp.async.wait_group 0;" ::: "memory")

// ---------------- mma.sync helpers (fp16 in, fp32 accum) ----------------
__device__ __forceinline__ void ldsm4(unsigned* r, unsigned addr) {
    asm volatile("ldmatrix.sync.aligned.m8n8.x4.shared.b16 {%0,%1,%2,%3}, [%4];"
                 : "=r"(r[0]), "=r"(r[1]), "=r"(r[2]), "=r"(r[3]) : "r"(addr));
}
__device__ __forceinline__ void mma16816(float* c, const unsigned* a, unsigned b0, unsigned b1) {
    asm volatile("mma.sync.aligned.m16n8k16.row.col.f32.f16.f16.f32 "
                 "{%0,%1,%2,%3}, {%4,%5,%6,%7}, {%8,%9}, {%0,%1,%2,%3};"
                 : "+f"(c[0]), "+f"(c[1]), "+f"(c[2]), "+f"(c[3])
                 : "r"(a[0]), "r"(a[1]), "r"(a[2]), "r"(a[3]), "r"(b0), "r"(b1));
}

// ---------------- zero kernels ----------------
__global__ void zero_agg_kernel() {
    int i = blockIdx.x * blockDim.x + threadIdx.x;
    for (; i < NNODES * HID; i += gridDim.x * blockDim.x) g_agg[i] = 0.f;
}
__global__ void zero_pool_kernel() {
    int t = threadIdx.x;
    if (t < NGRAPH * HID) g_pooled[t] = 0.f;
    if (t < NGRAPH) g_cnt[t] = 0;
}

// ---------------- weight prep: fp32 -> fp16, padded [n][k] ----------------
__global__ void prep_weights(const float* __restrict__ eW1, const float* __restrict__ eW2,
                             const float* __restrict__ nW1, const float* __restrict__ nW2) {
    int idx = blockIdx.x * blockDim.x + threadIdx.x;
    if (idx >= NLAYERS * 24576) return;
    int l = idx / 24576, r = idx % 24576;
    int isNode = (r >= 12288);
    if (isNode) r -= 12288;
    unsigned char* base = (isNode ? g_wN : g_wB) + l * 27648;
    float w;
    unsigned off;
    if (r < 8192) {
        int c = r >> 12, rr = r & 4095, n = rr >> 6, kk = rr & 63;
        if (isNode) w = nW1[l * 128 * 64 + (c * 64 + kk) * 64 + n];
        else        w = eW1[l * 133 * 64 + (c * 64 + kk) * 64 + n];
        off = (unsigned)(c * 9216 + n * 144 + kk * 2);
    } else {
        int rr = r - 8192, n = rr >> 6, kk = rr & 63;
        if (isNode) w = nW2[l * 4096 + kk * 64 + n];
        else        w = eW2[l * 4096 + kk * 64 + n];
        off = (unsigned)(18432 + n * 144 + kk * 2);
    }
    *(__half*)(base + off) = __float2half_rn(w);
}

// ---------------- encoder (also writes fp16 g_hs) ----------------
__global__ void __launch_bounds__(128) encoder_kernel(
    const float* __restrict__ x, const int* __restrict__ batch,
    const float* __restrict__ caseP, const float* __restrict__ bcP,
    const float* __restrict__ W1, const float* __restrict__ b1,
    const float* __restrict__ W2, const float* __restrict__ b2,
    const float* __restrict__ gam, const float* __restrict__ bet)
{
    __shared__ float sW1[16 * 64];
    __shared__ float sW2[64 * 64];
    __shared__ float sb1[64], sb2[64], sg[64], sbe[64];
    __shared__ float sy[4][64];
    int tid = threadIdx.x;
    for (int i = tid; i < 16 * 64; i += 128) sW1[i] = W1[i];
    for (int i = tid; i < 64 * 64; i += 128) sW2[i] = W2[i];
    if (tid < 64) { sb1[tid] = b1[tid]; sb2[tid] = b2[tid]; sg[tid] = gam[tid]; sbe[tid] = bet[tid]; }
    __syncthreads();

    int lane = tid & 31, warp = tid >> 5;
    int j0 = lane, j1 = lane + 32;
    for (int n = blockIdx.x * 4 + warp; n < NNODES; n += gridDim.x * 4) {
        float in[16];
        const float* xr = x + n * 8;
#pragma unroll
        for (int k = 0; k < 8; ++k) in[k] = xr[k];
        int b = batch[n];
#pragma unroll
        for (int k = 0; k < 4; ++k) in[8 + k]  = caseP[b * 4 + k];
#pragma unroll
        for (int k = 0; k < 4; ++k) in[12 + k] = bcP[b * 4 + k];

        float a0 = sb1[j0], a1 = sb1[j1];
#pragma unroll
        for (int k = 0; k < 16; ++k) {
            a0 = fmaf(in[k], sW1[k * 64 + j0], a0);
            a1 = fmaf(in[k], sW1[k * 64 + j1], a1);
        }
        a0 = silu_f(a0); a1 = silu_f(a1);
        sy[warp][j0] = a0; sy[warp][j1] = a1;
        __syncwarp();
        float z0 = sb2[j0], z1 = sb2[j1];
#pragma unroll 4
        for (int k = 0; k < 64; ++k) {
            float v = sy[warp][k];
            z0 = fmaf(v, sW2[k * 64 + j0], z0);
            z1 = fmaf(v, sW2[k * 64 + j1], z1);
        }
        float s = z0 + z1, ss = z0 * z0 + z1 * z1;
#pragma unroll
        for (int o = 16; o > 0; o >>= 1) {
            s  += __shfl_xor_sync(0xffffffffu, s, o);
            ss += __shfl_xor_sync(0xffffffffu, ss, o);
        }
        float m = s * (1.f / 64.f);
        float rs = rsqrtf(ss * (1.f / 64.f) - m * m + 1e-5f);
        float v0 = (z0 - m) * rs * sg[j0] + sbe[j0];
        float v1 = (z1 - m) * rs * sg[j1] + sbe[j1];
        g_h[n * HID + j0] = v0;
        g_h[n * HID + j1] = v1;
        g_hs[n * 64 + j0] = __float2half_rn(v0);
        g_hs[n * 64 + j1] = __float2half_rn(v1);
        __syncwarp();
    }
}

// ---------------- edge MLP v12 (unchanged from R13) ----------------
__global__ void __launch_bounds__(128, 3) edge12_kernel(
    const int* __restrict__ ei, const float* __restrict__ ea, int layer,
    const float* __restrict__ W1full, const float* __restrict__ b1,
    const float* __restrict__ b2,
    const float* __restrict__ gam, const float* __restrict__ bet)
{
    extern __shared__ unsigned char sm[];
    const unsigned sbase = smem_u32(sm);
    const int tid = threadIdx.x;
    const int lane = tid & 31, warp = tid >> 5;
    const int gID = lane >> 2, tig = lane & 3;
    const int lt = lane >> 3, lr = lane & 7;

    {
        const uint4* srcw = (const uint4*)(g_wB + layer * 27648);
        uint4* dstw = (uint4*)(sm + OFF_B1);
#pragma unroll 4
        for (int i = tid; i < 1728; i += 128) dstw[i] = srcw[i];
    }
    for (int i = tid; i < 320; i += 128) ((float*)(sm + OFF_T))[i] = W1full[128 * 64 + i];
    if (tid < 64) {
        ((float*)(sm + OFF_BB1))[tid] = b1[tid];
        ((float*)(sm + OFF_BB2))[tid] = b2[tid];
        ((float*)(sm + OFF_G))[tid]   = gam[tid];
        ((float*)(sm + OFF_BE))[tid]  = bet[tid];
    }

    const unsigned aOff = (unsigned)((warp * 32 + (lt & 1) * 8 + lr) * 128
                                     + ((unsigned)((lt >> 1) << 4) ^ ((unsigned)lr << 4)));
    const unsigned bLane = (unsigned)(((lt >> 1) * 8 + lr) * 144 + ((lt & 1) << 4));
    const float* bb1 = (const float*)(sm + OFF_BB1);
    int* sdst_all = (int*)(sm + OFF_SDST);
    float* sea_all = (float*)(sm + OFF_SEA);

    const int grow = warp * 32 + (lane >> 3);
    const int cp = lane & 7;
    const unsigned gcol = (unsigned)(cp * 16);

    const int t0 = blockIdx.x;
    {
        const int e0 = t0 * 128;
        sdst_all[tid] = ei[NEDGES + e0 + tid];
        for (int i = tid; i < 640; i += 128) sea_all[i] = ea[(ull)e0 * 5 + i];
#pragma unroll
        for (int i = 0; i < 8; ++i) {
            int row = grow + 4 * i;
            int node = ei[NEDGES + e0 + row];
            cpasync16(sbase + OFF_A0 + (unsigned)(row * 128)
                          + (gcol ^ (((unsigned)row & 7u) << 4)),
                      (const unsigned char*)g_hs + (ull)node * 128 + cp * 16);
        }
        CP_COMMIT();
#pragma unroll
        for (int i = 0; i < 8; ++i) {
            int row = grow + 4 * i;
            int node = ei[e0 + row];
            cpasync16(sbase + OFF_A1 + (unsigned)(row * 128)
                          + (gcol ^ (((unsigned)row & 7u) << 4)),
                      (const unsigned char*)g_hs + (ull)node * 128 + cp * 16);
        }
        CP_COMMIT();
    }

    int it = 0;
    for (int t = t0; t < NTILES; t += gridDim.x, ++it) {
        const int p = it & 1;
        const int* sdst = sdst_all + p * 128;
        const float* sea = sea_all + p * 640;

        int tn = t + gridDim.x;
        if (tn >= NTILES) tn = t;
        const int e0n = tn * 128;

        float acc[2][8][4];
#pragma unroll
        for (int nt = 0; nt < 8; ++nt) {
            float2 bv = *(const float2*)(bb1 + nt * 8 + 2 * tig);
#pragma unroll
            for (int mt = 0; mt < 2; ++mt) {
                acc[mt][nt][0] = bv.x; acc[mt][nt][1] = bv.y;
                acc[mt][nt][2] = bv.x; acc[mt][nt][3] = bv.y;
            }
        }

        CP_WAIT1();
        __syncthreads();
        {
            const unsigned bB = sbase + OFF_B1 + bLane;
#pragma unroll
            for (int kt = 0; kt < 4; ++kt) {
                const unsigned kx = (unsigned)(kt * 32);
                unsigned a0[4], a1[4];
                ldsm4(a0, sbase + OFF_A0 + (aOff ^ kx));
                ldsm4(a1, sbase + OFF_A0 + ((aOff + 2048u) ^ kx));
                unsigned bf[4][4];
#pragma unroll
                for (int q = 0; q < 4; ++q) ldsm4(bf[q], bB + q * 2304u + kx);
#pragma unroll
                for (int q = 0; q < 4; ++q) {
                    mma16816(acc[0][2 * q],     a0, bf[q][0], bf[q][1]);
                    mma16816(acc[0][2 * q + 1], a0, bf[q][2], bf[q][3]);
                    mma16816(acc[1][2 * q],     a1, bf[q][0], bf[q][1]);
                    mma16816(acc[1][2 * q + 1], a1, bf[q][2], bf[q][3]);
                }
            }
        }
        __syncthreads();

        sdst_all[(p ^ 1) * 128 + tid] = ei[NEDGES + e0n + tid];
        for (int i = tid; i < 640; i += 128) sea_all[(p ^ 1) * 640 + i] = ea[(ull)e0n * 5 + i];
#pragma unroll
        for (int i = 0; i < 8; ++i) {
            int row = grow + 4 * i;
            int node = ei[NEDGES + e0n + row];
            cpasync16(sbase + OFF_A0 + (unsigned)(row * 128)
                          + (gcol ^ (((unsigned)row & 7u) << 4)),
                      (const unsigned char*)g_hs + (ull)node * 128 + cp * 16);
        }
        CP_COMMIT();

        CP_WAIT1();
        __syncthreads();
        {
            const unsigned bB = sbase + OFF_B1 + 9216u + bLane;
#pragma unroll
            for (int kt = 0; kt < 4; ++kt) {
                const unsigned kx = (unsigned)(kt * 32);
                unsigned a0[4], a1[4];
                ldsm4(a0, sbase + OFF_A1 + (aOff ^ kx));
                ldsm4(a1, sbase + OFF_A1 + ((aOff + 2048u) ^ kx));
                unsigned bf[4][4];
#pragma unroll
                for (int q = 0; q < 4; ++q) ldsm4(bf[q], bB + q * 2304u + kx);
#pragma unroll
                for (int q = 0; q < 4; ++q) {
                    mma16816(acc[0][2 * q],     a0, bf[q][0], bf[q][1]);
                    mma16816(acc[0][2 * q + 1], a0, bf[q][2], bf[q][3]);
                    mma16816(acc[1][2 * q],     a1, bf[q][0], bf[q][1]);
                    mma16816(acc[1][2 * q + 1], a1, bf[q][2], bf[q][3]);
                }
            }
        }

        float eav[2][2][5];
#pragma unroll
        for (int mt = 0; mt < 2; ++mt)
#pragma unroll
            for (int h = 0; h < 2; ++h) {
                const float* er = sea + (warp * 32 + mt * 16 + h * 8 + gID) * 5;
#pragma unroll
                for (int j = 0; j < 5; ++j) eav[mt][h][j] = er[j];
            }
        unsigned uh[2][2][8];
#pragma unroll
        for (int nt = 0; nt < 8; ++nt) {
            float2 w[5];
#pragma unroll
            for (int j = 0; j < 5; ++j)
                w[j] = *(const float2*)(sm + OFF_T + (unsigned)((j * 64 + nt * 8 + tig * 2) * 4));
#pragma unroll
            for (int mt = 0; mt < 2; ++mt)
#pragma unroll
                for (int h = 0; h < 2; ++h) {
                    float y0 = acc[mt][nt][2 * h], y1 = acc[mt][nt][2 * h + 1];
#pragma unroll
                    for (int j = 0; j < 5; ++j) {
                        y0 = fmaf(eav[mt][h][j], w[j].x, y0);
                        y1 = fmaf(eav[mt][h][j], w[j].y, y1);
                    }
                    __half2 hb = __float22half2_rn(make_float2(silu_f(y0), silu_f(y1)));
                    uh[mt][h][nt] = *(unsigned*)&hb;
                }
        }

        float acc2[2][8][4];
#pragma unroll
        for (int nt = 0; nt < 8; ++nt) {
            float2 bv = *(const float2*)(sm + OFF_BB2 + (unsigned)((nt * 8 + tig * 2) * 4));
#pragma unroll
            for (int mt = 0; mt < 2; ++mt) {
                acc2[mt][nt][0] = bv.x; acc2[mt][nt][1] = bv.y;
                acc2[mt][nt][2] = bv.x; acc2[mt][nt][3] = bv.y;
            }
        }
        const unsigned b2B = sbase + OFF_B2 + bLane;
#pragma unroll
        for (int kt = 0; kt < 4; ++kt) {
            unsigned bf[4][4];
#pragma unroll
            for (int q = 0; q < 4; ++q) ldsm4(bf[q], b2B + q * 2304u + kt * 32u);
            unsigned ah0[4] = {uh[0][0][2 * kt], uh[0][1][2 * kt], uh[0][0][2 * kt + 1], uh[0][1][2 * kt + 1]};
            unsigned ah1[4] = {uh[1][0][2 * kt], uh[1][1][2 * kt], uh[1][0][2 * kt + 1], uh[1][1][2 * kt + 1]};
#pragma unroll
            for (int q = 0; q < 4; ++q) {
                mma16816(acc2[0][2 * q],     ah0, bf[q][0], bf[q][1]);
                mma16816(acc2[0][2 * q + 1], ah0, bf[q][2], bf[q][3]);
                mma16816(acc2[1][2 * q],     ah1, bf[q][0], bf[q][1]);
                mma16816(acc2[1][2 * q + 1], ah1, bf[q][2], bf[q][3]);
            }
        }
        __syncthreads();

#pragma unroll
        for (int i = 0; i < 8; ++i) {
            int row = grow + 4 * i;
            int node = ei[e0n + row];
            cpasync16(sbase + OFF_A1 + (unsigned)(row * 128)
                          + (gcol ^ (((unsigned)row & 7u) << 4)),
                      (const unsigned char*)g_hs + (ull)node * 128 + cp * 16);
        }
        CP_COMMIT();

        float mArr[2][2], rsArr[2][2];
#pragma unroll
        for (int mt = 0; mt < 2; ++mt)
#pragma unroll
            for (int h = 0; h < 2; ++h) {
                float s = 0.f, ssum = 0.f;
#pragma unroll
                for (int nt = 0; nt < 8; ++nt) {
                    float v0 = acc2[mt][nt][2 * h], v1 = acc2[mt][nt][2 * h + 1];
                    s += v0 + v1; ssum += v0 * v0 + v1 * v1;
                }
                s    += __shfl_xor_sync(0xffffffffu, s, 1);
                ssum += __shfl_xor_sync(0xffffffffu, ssum, 1);
                s    += __shfl_xor_sync(0xffffffffu, s, 2);
                ssum += __shfl_xor_sync(0xffffffffu, ssum, 2);
                float m = s * (1.f / 64.f);
                mArr[mt][h]  = m;
                rsArr[mt][h] = rsqrtf(ssum * (1.f / 64.f) - m * m + 1e-5f);
            }
        const int cq = (tig & 1) * 2 + (tig >> 1);
        float4 gq[4], beq[4];
#pragma unroll
        for (int j = 0; j < 4; ++j) {
            gq[j]  = ((const float4*)(sm + OFF_G))[4 * j + cq];
            beq[j] = ((const float4*)(sm + OFF_BE))[4 * j + cq];
        }
        const unsigned colb = (unsigned)((tig & 1) * 8 + (tig >> 1) * 4);
#pragma unroll
        for (int mt = 0; mt < 2; ++mt)
#pragma unroll
            for (int h = 0; h < 2; ++h) {
                int row = warp * 32 + mt * 16 + h * 8 + gID;
                float* ag = g_agg + (ull)sdst[row] * 64 + colb;
                float m = mArr[mt][h], rs = rsArr[mt][h];
#pragma unroll
                for (int j = 0; j < 4; ++j) {
                    ull p0 = pack2(acc2[mt][2 * j][2 * h],     acc2[mt][2 * j][2 * h + 1]);
                    ull p1 = pack2(acc2[mt][2 * j + 1][2 * h], acc2[mt][2 * j + 1][2 * h + 1]);
                    ull sel = (tig & 1) ? p0 : p1;
                    ull rv = __shfl_xor_sync(0xffffffffu, sel, 1);
                    float q0, q1, q2, q3;
                    if (tig & 1) { unpack2(rv, q0, q1); unpack2(p1, q2, q3); }
                    else         { unpack2(p0, q0, q1); unpack2(rv, q2, q3); }
                    float o0 = (q0 - m) * rs * gq[j].x + beq[j].x;
                    float o1 = (q1 - m) * rs * gq[j].y + beq[j].y;
                    float o2 = (q2 - m) * rs * gq[j].z + beq[j].z;
                    float o3 = (q3 - m) * rs * gq[j].w + beq[j].w;
                    red_add4(ag + 16 * j, o0, o1, o2, o3);
                }
            }
    }
    CP_WAIT0();
}

// ---------------- node MLP v3: fp16 mma, sequential rows, residual ----------------
__global__ void __launch_bounds__(128, 3) node3_kernel(
    int layer,
    const float* __restrict__ b1, const float* __restrict__ b2,
    const float* __restrict__ gam, const float* __restrict__ bet)
{
    extern __shared__ unsigned char sm[];
    const unsigned sbase = smem_u32(sm);
    const int tid = threadIdx.x;
    const int lane = tid & 31, warp = tid >> 5;
    const int gID = lane >> 2, tig = lane & 3;
    const int lt = lane >> 3, lr = lane & 7;

    {
        const uint4* srcw = (const uint4*)(g_wN + layer * 27648);
        uint4* dstw = (uint4*)(sm + NOFF_B1);
#pragma unroll 4
        for (int i = tid; i < 1728; i += 128) dstw[i] = srcw[i];
    }
    if (tid < 64) {
        ((float*)(sm + NOFF_BB1))[tid] = b1[tid];
        ((float*)(sm + NOFF_BB2))[tid] = b2[tid];
        ((float*)(sm + NOFF_G))[tid]   = gam[tid];
        ((float*)(sm + NOFF_BE))[tid]  = bet[tid];
    }
    __syncthreads();

    const unsigned aOff = (unsigned)((warp * 32 + (lt & 1) * 8 + lr) * 128
                                     + ((unsigned)((lt >> 1) << 4) ^ ((unsigned)lr << 4)));
    const unsigned bLane = (unsigned)(((lt >> 1) * 8 + lr) * 144 + ((lt & 1) << 4));
    const float* bb1 = (const float*)(sm + NOFF_BB1);

    const int n0 = blockIdx.x * 128;

    // acc init with b1
    float acc[2][8][4];
#pragma unroll
    for (int nt = 0; nt < 8; ++nt) {
        float2 bv = *(const float2*)(bb1 + nt * 8 + 2 * tig);
#pragma unroll
        for (int mt = 0; mt < 2; ++mt) {
            acc[mt][nt][0] = bv.x; acc[mt][nt][1] = bv.y;
            acc[mt][nt][2] = bv.x; acc[mt][nt][3] = bv.y;
        }
    }

    // ---- stage chunk0: g_hs rows (fp16, 16B chunks, coalesced) ----
    for (int idx = tid; idx < 1024; idx += 128) {
        int row = idx >> 3, c = idx & 7;
        int node = n0 + row;
        if (node >= NNODES) node = NNODES - 1;
        uint4 v = *(const uint4*)((const unsigned char*)g_hs + (ull)node * 128 + c * 16);
        *(uint4*)(sm + NOFF_A + (unsigned)(row * 128)
                     + (((unsigned)c * 16u) ^ (((unsigned)row & 7u) << 4))) = v;
    }
    __syncthreads();
    {
        const unsigned bB = sbase + NOFF_B1 + bLane;
#pragma unroll
        for (int kt = 0; kt < 4; ++kt) {
            const unsigned kx = (unsigned)(kt * 32);
            unsigned a0[4], a1[4];
            ldsm4(a0, sbase + NOFF_A + (aOff ^ kx));
            ldsm4(a1, sbase + NOFF_A + ((aOff + 2048u) ^ kx));
            unsigned bf[4][4];
#pragma unroll
            for (int q = 0; q < 4; ++q) ldsm4(bf[q], bB + q * 2304u + kx);
#pragma unroll
            for (int q = 0; q < 4; ++q) {
                mma16816(acc[0][2 * q],     a0, bf[q][0], bf[q][1]);
                mma16816(acc[0][2 * q + 1], a0, bf[q][2], bf[q][3]);
                mma16816(acc[1][2 * q],     a1, bf[q][0], bf[q][1]);
                mma16816(acc[1][2 * q + 1], a1, bf[q][2], bf[q][3]);
            }
        }
    }
    __syncthreads();

    // ---- stage chunk1: g_agg rows fp32 -> fp16 (coalesced float4 loads) ----
    for (int idx = tid; idx < 2048; idx += 128) {
        int row = idx >> 4, c = idx & 15;
        int node = n0 + row;
        if (node >= NNODES) node = NNODES - 1;
        float4 v = *(const float4*)(g_agg + (ull)node * 64 + c * 4);
        __half2 h01 = __float22half2_rn(make_float2(v.x, v.y));
        __half2 h23 = __float22half2_rn(make_float2(v.z, v.w));
        ull pv = ((ull)*(unsigned*)&h23 << 32) | *(unsigned*)&h01;
        *(ull*)(sm + NOFF_A + (unsigned)(row * 128)
                   + ((((unsigned)(c >> 1)) * 16u) ^ (((unsigned)row & 7u) << 4))
                   + (unsigned)((c & 1) * 8)) = pv;
    }
    __syncthreads();
    {
        const unsigned bB = sbase + NOFF_B1 + 9216u + bLane;
#pragma unroll
        for (int kt = 0; kt < 4; ++kt) {
            const unsigned kx = (unsigned)(kt * 32);
            unsigned a0[4], a1[4];
            ldsm4(a0, sbase + NOFF_A + (aOff ^ kx));
            ldsm4(a1, sbase + NOFF_A + ((aOff + 2048u) ^ kx));
            unsigned bf[4][4];
#pragma unroll
            for (int q = 0; q < 4; ++q) ldsm4(bf[q], bB + q * 2304u + kx);
#pragma unroll
            for (int q = 0; q < 4; ++q) {
                mma16816(acc[0][2 * q],     a0, bf[q][0], bf[q][1]);
                mma16816(acc[0][2 * q + 1], a0, bf[q][2], bf[q][3]);
                mma16816(acc[1][2 * q],     a1, bf[q][0], bf[q][1]);
                mma16816(acc[1][2 * q + 1], a1, bf[q][2], bf[q][3]);
            }
        }
    }

    // ---- epilogue1: silu -> fp16 regs ----
    unsigned uh[2][2][8];
#pragma unroll
    for (int nt = 0; nt < 8; ++nt)
#pragma unroll
        for (int mt = 0; mt < 2; ++mt)
#pragma unroll
            for (int h = 0; h < 2; ++h) {
                __half2 hb = __float22half2_rn(make_float2(silu_f(acc[mt][nt][2 * h]),
                                                           silu_f(acc[mt][nt][2 * h + 1])));
                uh[mt][h][nt] = *(unsigned*)&hb;
            }

    // ---- GEMM2 ----
    float acc2[2][8][4];
#pragma unroll
    for (int nt = 0; nt < 8; ++nt) {
        float2 bv = *(const float2*)(sm + NOFF_BB2 + (unsigned)((nt * 8 + tig * 2) * 4));
#pragma unroll
        for (int mt = 0; mt < 2; ++mt) {
            acc2[mt][nt][0] = bv.x; acc2[mt][nt][1] = bv.y;
            acc2[mt][nt][2] = bv.x; acc2[mt][nt][3] = bv.y;
        }
    }
    const unsigned b2B = sbase + NOFF_B2 + bLane;
#pragma unroll
    for (int kt = 0; kt < 4; ++kt) {
        unsigned bf[4][4];
#pragma unroll
        for (int q = 0; q < 4; ++q) ldsm4(bf[q], b2B + q * 2304u + kt * 32u);
        unsigned ah0[4] = {uh[0][0][2 * kt], uh[0][1][2 * kt], uh[0][0][2 * kt + 1], uh[0][1][2 * kt + 1]};
        unsigned ah1[4] = {uh[1][0][2 * kt], uh[1][1][2 * kt], uh[1][0][2 * kt + 1], uh[1][1][2 * kt + 1]};
#pragma unroll
        for (int q = 0; q < 4; ++q) {
            mma16816(acc2[0][2 * q],     ah0, bf[q][0], bf[q][1]);
            mma16816(acc2[0][2 * q + 1], ah0, bf[q][2], bf[q][3]);
            mma16816(acc2[1][2 * q],     ah1, bf[q][0], bf[q][1]);
            mma16816(acc2[1][2 * q + 1], ah1, bf[q][2], bf[q][3]);
        }
    }

    // ---- epilogue2: LN + residual (disjoint RMW per thread) ----
    float mArr[2][2], rsArr[2][2];
#pragma unroll
    for (int mt = 0; mt < 2; ++mt)
#pragma unroll
        for (int h = 0; h < 2; ++h) {
            float s = 0.f, ssum = 0.f;
#pragma unroll
            for (int nt = 0; nt < 8; ++nt) {
                float v0 = acc2[mt][nt][2 * h], v1 = acc2[mt][nt][2 * h + 1];
                s += v0 + v1; ssum += v0 * v0 + v1 * v1;
            }
            s    += __shfl_xor_sync(0xffffffffu, s, 1);
            ssum += __shfl_xor_sync(0xffffffffu, ssum, 1);
            s    += __shfl_xor_sync(0xffffffffu, s, 2);
            ssum += __shfl_xor_sync(0xffffffffu, ssum, 2);
            float m = s * (1.f / 64.f);
            mArr[mt][h]  = m;
            rsArr[mt][h] = rsqrtf(ssum * (1.f / 64.f) - m * m + 1e-5f);
        }
    const int cq = (tig & 1) * 2 + (tig >> 1);
    float4 gq[4], beq[4];
#pragma unroll
    for (int j = 0; j < 4; ++j) {
        gq[j]  = ((const float4*)(sm + NOFF_G))[4 * j + cq];
        beq[j] = ((const float4*)(sm + NOFF_BE))[4 * j + cq];
    }
    const unsigned colb = (unsigned)((tig & 1) * 8 + (tig >> 1) * 4);
#pragma unroll
    for (int mt = 0; mt < 2; ++mt)
#pragma unroll
        for (int h = 0; h < 2; ++h) {
            int row = warp * 32 + mt * 16 + h * 8 + gID;
            int node = n0 + row;
            bool valid = (node < NNODES);
            float m = mArr[mt][h], rs = rsArr[mt][h];
#pragma unroll
            for (int j = 0; j < 4; ++j) {
                ull p0 = pack2(acc2[mt][2 * j][2 * h],     acc2[mt][2 * j][2 * h + 1]);
                ull p1 = pack2(acc2[mt][2 * j + 1][2 * h], acc2[mt][2 * j + 1][2 * h + 1]);
                ull sel = (tig & 1) ? p0 : p1;
                ull rv = __shfl_xor_sync(0xffffffffu, sel, 1);
                float q0, q1, q2, q3;
                if (tig & 1) { unpack2(rv, q0, q1); unpack2(p1, q2, q3); }
                else         { unpack2(p0, q0, q1); unpack2(rv, q2, q3); }
                if (valid) {
                    float* hp = g_h + (ull)node * 64 + colb + 16 * j;
                    float4 hv = *(float4*)hp;
                    hv.x += (q0 - m) * rs * gq[j].x + beq[j].x;
                    hv.y += (q1 - m) * rs * gq[j].y + beq[j].y;
                    hv.z += (q2 - m) * rs * gq[j].z + beq[j].z;
                    hv.w += (q3 - m) * rs * gq[j].w + beq[j].w;
                    *(float4*)hp = hv;
                    __half2 h01 = __float22half2_rn(make_float2(hv.x, hv.y));
                    __half2 h23 = __float22half2_rn(make_float2(hv.z, hv.w));
                    ull pv = ((ull)*(unsigned*)&h23 << 32) | *(unsigned*)&h01;
                    *(ull*)(g_hs + (ull)node * 64 + colb + 16 * j) = pv;
                }
            }
        }
}

// ---------------- local decoder ----------------
__global__ void __launch_bounds__(128) dec_local_kernel(
    const float* __restrict__ W1, const float* __restrict__ b1,
    const float* __restrict__ W2, const float* __restrict__ b2,
    float* __restrict__ out)
{
    __shared__ float sW1[64 * 64];
    __shared__ float sW2[64 * 6];
    __shared__ float sb1[64];
    __shared__ float sb2[8];
    __shared__ float sy[4][64];
    int tid = threadIdx.x;
    for (int i = tid; i < 64 * 64; i += 128) sW1[i] = W1[i];
    for (int i = tid; i < 64 * 6; i += 128) sW2[i] = W2[i];
    if (tid < 64) sb1[tid] = b1[tid];
    if (tid < 6)  sb2[tid] = b2[tid];
    __syncthreads();

    int lane = tid & 31, warp = tid >> 5;
    int j0 = lane, j1 = lane + 32;
    for (int n = blockIdx.x * 4 + warp; n < NNODES; n += gridDim.x * 4) {
        const float4* Hr = reinterpret_cast<const float4*>(g_h + n * HID);
        float a0 = sb1[j0], a1 = sb1[j1];
#pragma unroll 4
        for (int c = 0; c < 16; ++c) {
            float4 v = Hr[c];
            const float* w = sW1 + 4 * c * 64;
            a0 = fmaf(v.x, w[j0], a0);           a1 = fmaf(v.x, w[j1], a1);
            a0 = fmaf(v.y, w[64 + j0], a0);      a1 = fmaf(v.y, w[64 + j1], a1);
            a0 = fmaf(v.z, w[128 + j0], a0);     a1 = fmaf(v.z, w[128 + j1], a1);
            a0 = fmaf(v.w, w[192 + j0], a0);     a1 = fmaf(v.w, w[192 + j1], a1);
        }
        a0 = silu_f(a0); a1 = silu_f(a1);
        sy[warp][j0] = a0; sy[warp][j1] = a1;
        __syncwarp();
        if (lane < 6) {
            float o = sb2[lane];
#pragma unroll 8
            for (int k = 0; k < 64; ++k) o = fmaf(sy[warp][k], sW2[k * 6 + lane], o);
            out[n * 6 + lane] = o;
        }
        __syncwarp();
    }
}

// ---------------- pooling ----------------
__global__ void __launch_bounds__(256) pool_kernel(const int* __restrict__ batch)
{
    __shared__ float sacc[NGRAPH * HID];
    __shared__ int   scnt[NGRAPH];
    int tid = threadIdx.x;
    sacc[tid] = 0.f;
    if (tid < NGRAPH) scnt[tid] = 0;
    __syncthreads();
    int j = tid & 63;
    int r = tid >> 6;
    int base = blockIdx.x * 512;
    int end = min(base + 512, NNODES);
    for (int n = base + r; n < end; n += 4) {
        int b = batch[n];
        atomicAdd(&sacc[b * HID + j], g_h[n * HID + j]);
        if (j == 0) atomicAdd(&scnt[b], 1);
    }
    __syncthreads();
    atomicAdd(&g_pooled[tid], sacc[tid]);
    if (tid < NGRAPH) atomicAdd(&g_cnt[tid], scnt[tid]);
}

// ---------------- global decoder ----------------
__global__ void dec_global_kernel(
    const float* __restrict__ W1, const float* __restrict__ b1,
    const float* __restrict__ W2, const float* __restrict__ b2,
    float* __restrict__ out)
{
    __shared__ float sy[NGRAPH][32];
    int g = threadIdx.x >> 5;
    int lane = threadIdx.x & 31;
    float inv = 1.f / fmaxf((float)g_cnt[g], 1.f);
    float a = b1[lane];
#pragma unroll 8
    for (int k = 0; k < 64; ++k)
        a = fmaf(g_pooled[g * HID + k] * inv, W1[k * 32 + lane], a);
    a = silu_f(a);
    sy[g][lane] = a;
    __syncwarp();
    if (lane < 4) {
        float o = b2[lane];
#pragma unroll 8
        for (int k = 0; k < 32; ++k) o = fmaf(sy[g][k], W2[k * 4 + lane], o);
        out[g * 4 + lane] = o;
    }
}

// ---------------- launch ----------------
extern "C" void kernel_launch(void* const* d_in, const int* in_sizes, int n_in,
                              void* d_out, int out_size)
{
    (void)in_sizes; (void)n_in; (void)out_size;
    const float* x      = (const float*)d_in[0];
    const int*   ei     = (const int*)  d_in[1];
    const float* ea     = (const float*)d_in[2];
    const int*   batch  = (const int*)  d_in[3];
    const float* caseP  = (const float*)d_in[4];
    const float* bcP    = (const float*)d_in[5];
    const float* encW1  = (const float*)d_in[6];
    const float* encb1  = (const float*)d_in[7];
    const float* encW2  = (const float*)d_in[8];
    const float* encb2  = (const float*)d_in[9];
    const float* encg   = (const float*)d_in[10];
    const float* encbe  = (const float*)d_in[11];
    const float* eW1    = (const float*)d_in[12];
    const float* eb1    = (const float*)d_in[13];
    const float* eW2    = (const float*)d_in[14];
    const float* eb2    = (const float*)d_in[15];
    const float* egm    = (const float*)d_in[16];
    const float* ebe    = (const float*)d_in[17];
    const float* nW1    = (const float*)d_in[18];
    const float* nb1    = (const float*)d_in[19];
    const float* nW2    = (const float*)d_in[20];
    const float* nb2    = (const float*)d_in[21];
    const float* ngm    = (const float*)d_in[22];
    const float* nbe    = (const float*)d_in[23];
    const float* dlW1   = (const float*)d_in[24];
    const float* dlb1   = (const float*)d_in[25];
    const float* dlW2   = (const float*)d_in[26];
    const float* dlb2   = (const float*)d_in[27];
    const float* dgW1   = (const float*)d_in[28];
    const float* dgb1   = (const float*)d_in[29];
    const float* dgW2   = (const float*)d_in[30];
    const float* dgb2   = (const float*)d_in[31];
    float* out = (float*)d_out;

    cudaFuncSetAttribute(edge12_kernel, cudaFuncAttributeMaxDynamicSharedMemorySize, EDGE_SMEM);
    cudaFuncSetAttribute(node3_kernel, cudaFuncAttributeMaxDynamicSharedMemorySize, NODE3_SMEM);

    prep_weights<<<(NLAYERS * 24576 + 255) / 256, 256>>>(eW1, eW2, nW1, nW2);
    encoder_kernel<<<200, 128>>>(x, batch, caseP, bcP,
                                 encW1, encb1, encW2, encb2, encg, encbe);

    for (int l = 0; l < NLAYERS; ++l) {
        zero_agg_kernel<<<512, 256>>>();
        edge12_kernel<<<444, 128, EDGE_SMEM>>>(
            ei, ea, l,
            eW1 + l * 133 * 64, eb1 + l * 64, eb2 + l * 64,
            egm + l * 64, ebe + l * 64);
        node3_kernel<<<NTILE_N, 128, NODE3_SMEM>>>(
            l, nb1 + l * 64, nb2 + l * 64,
            ngm + l * 64, nbe + l * 64);
    }

    zero_pool_kernel<<<1, 256>>>();
    dec_local_kernel<<<200, 128>>>(dlW1, dlb1, dlW2, dlb2, out);
    pool_kernel<<<(NNODES + 511) / 512, 256>>>(batch);
    dec_global_kernel<<<1, 128>>>(dgW1, dgb1, dgW2, dgb2, out + NNODES * 6);
}